// round 1
// baseline (speedup 1.0000x reference)
#include <cuda_runtime.h>
#include <math.h>

// Problem constants
#define B_      2
#define S_      4096
#define E_      2048
#define NH_     16
#define HD_     128
#define NKV_    4
#define KVOUT_  1024
#define WINDOW_ 512
#define NMETA_  16

// Scratch (device globals — no allocation allowed)
__device__ float g_q [B_ * S_ * E_];                       // [b,s,h,hd] after Wq proj + RoPE
__device__ float g_kv[B_ * S_ * 2 * NKV_ * HD_];           // [b,s,2,kvh,hd]
__device__ float g_y [B_ * S_ * E_];                       // attention output [b,s,h,hd]

// ---------------------------------------------------------------------------
// Tiled fp32 GEMM: C[M,N] = A[M,K] @ W[K,N] + bias[N]
// 128x128 block tile, BK=16, 256 threads, 8x8 per-thread microtile.
// M,N multiples of 128; K multiple of 16.
// ---------------------------------------------------------------------------
__global__ __launch_bounds__(256) void gemm_bias_kernel(
    const float* __restrict__ A, const float* __restrict__ W,
    const float* __restrict__ bias, float* __restrict__ C,
    int M, int N, int K)
{
    __shared__ float As[16][128];   // [k][m]
    __shared__ float Ws[16][128];   // [k][n]

    const int tid = threadIdx.x;
    const int tx = tid & 15, ty = tid >> 4;
    const int m0 = blockIdx.y * 128;
    const int n0 = blockIdx.x * 128;

    float acc[8][8];
#pragma unroll
    for (int i = 0; i < 8; i++)
#pragma unroll
        for (int j = 0; j < 8; j++) acc[i][j] = 0.f;

    for (int k0 = 0; k0 < K; k0 += 16) {
#pragma unroll
        for (int u = 0; u < 2; u++) {
            int idx = tid + u * 256;
            // A tile: 128 rows x 16 cols -> transposed store
            int r  = idx >> 2;
            int c4 = (idx & 3) << 2;
            float4 av = *(const float4*)(A + (size_t)(m0 + r) * K + k0 + c4);
            As[c4 + 0][r] = av.x; As[c4 + 1][r] = av.y;
            As[c4 + 2][r] = av.z; As[c4 + 3][r] = av.w;
            // W tile: 16 rows x 128 cols -> direct store
            int rw = idx >> 5;
            int cw = (idx & 31) << 2;
            *(float4*)&Ws[rw][cw] = *(const float4*)(W + (size_t)(k0 + rw) * N + n0 + cw);
        }
        __syncthreads();
#pragma unroll
        for (int kk = 0; kk < 16; kk++) {
            float a[8], bb[8];
            *(float4*)&a[0]  = *(float4*)&As[kk][ty * 8];
            *(float4*)&a[4]  = *(float4*)&As[kk][ty * 8 + 4];
            *(float4*)&bb[0] = *(float4*)&Ws[kk][tx * 8];
            *(float4*)&bb[4] = *(float4*)&Ws[kk][tx * 8 + 4];
#pragma unroll
            for (int i = 0; i < 8; i++)
#pragma unroll
                for (int j = 0; j < 8; j++)
                    acc[i][j] += a[i] * bb[j];
        }
        __syncthreads();
    }

#pragma unroll
    for (int i = 0; i < 8; i++) {
        size_t row = (size_t)(m0 + ty * 8 + i);
#pragma unroll
        for (int j4 = 0; j4 < 2; j4++) {
            int nc = n0 + tx * 8 + j4 * 4;
            float4 v;
            v.x = acc[i][j4 * 4 + 0] + bias[nc + 0];
            v.y = acc[i][j4 * 4 + 1] + bias[nc + 1];
            v.z = acc[i][j4 * 4 + 2] + bias[nc + 2];
            v.w = acc[i][j4 * 4 + 3] + bias[nc + 3];
            *(float4*)(C + row * N + nc) = v;
        }
    }
}

// ---------------------------------------------------------------------------
// RoPE (interleaved pairs): out[2i] = x[2i]*c - x[2i+1]*s; out[2i+1] = x[2i+1]*c + x[2i]*s
// angle = pos * 10000^(-i/64)  (i = 0..63)
// ---------------------------------------------------------------------------
__device__ __forceinline__ void rope_pair(float* p, int pos, int i)
{
    double invd = exp(-(double)i * (9.210340371976184 / 64.0)); // ln(10000)/64
    float inv = (float)invd;
    float ang = (float)pos * inv;        // same fp32 multiply as reference
    float c = cosf(ang), sn = sinf(ang);
    float2 v = *(float2*)p;
    float2 r;
    r.x = v.x * c - v.y * sn;
    r.y = v.y * c + v.x * sn;
    *(float2*)p = r;
}

__global__ void rope_q_kernel(float* __restrict__ q)
{
    int idx = blockIdx.x * 256 + threadIdx.x;          // over B*S*NH*64 pairs
    if (idx >= B_ * S_ * NH_ * 64) return;
    int i = idx & 63;
    int s = (idx >> 10) & (S_ - 1);
    rope_pair(q + (size_t)idx * 2, s, i);
}

__global__ void rope_k_kernel(float* __restrict__ kv)
{
    int idx = blockIdx.x * 256 + threadIdx.x;          // over B*S*NKV*64 pairs
    if (idx >= B_ * S_ * NKV_ * 64) return;
    int i   = idx & 63;
    int row = idx >> 6;                                 // (b*S+s)*NKV + kvh
    int kvh = row & 3;
    int bs  = row >> 2;                                 // b*S + s
    int pos = bs & (S_ - 1);
    size_t off = ((size_t)bs * 8 + kvh) * 128 + 2 * i;  // pair=0 (K half)
    rope_pair(kv + off, pos, i);
}

// ---------------------------------------------------------------------------
// Attention: per block = (64 queries, one (b,h)). Flash-style online softmax.
// Key set for q-block starting at q0: meta [0,16) ∪ [ls, q0+64),
//   ls = max(16, chunk_start - 511); chunk_start = q0 & ~511.
// Mask: k<=q && (k >= q-511 || k < 16).
// smem: Q,K,V tiles 64x128 fp32 (xor-swizzled float4), P 64x65.
// ---------------------------------------------------------------------------
#define ATTN_SMEM_BYTES ((3 * 64 * 128 + 64 * 65) * 4)

__global__ __launch_bounds__(256) void attn_kernel(
    const float* __restrict__ qg, const float* __restrict__ kvg,
    float* __restrict__ yg)
{
    extern __shared__ float smf[];
    float4* Qs = (float4*)smf;          // 64*32 float4
    float4* Ks = Qs + 64 * 32;
    float4* Vs = Ks + 64 * 32;
    float*  Ps = (float*)(Vs + 64 * 32); // [64][65]

    const int tid = threadIdx.x;
    const int tx = tid & 15, ty = tid >> 4;
    const int bh = blockIdx.y;
    const int b = bh >> 4, h = bh & 15;
    const int kvh = h >> 2;              // repeat factor 4
    const int q0 = blockIdx.x << 6;
    const int qs = q0 & ~(WINDOW_ - 1);
    int ls = qs - WINDOW_ + 1; if (ls < NMETA_) ls = NMETA_;
    const int kend = q0 + 64;
    const float scale = 0.088388347648318447f; // 1/sqrt(128)

    // Load Q tile (swizzled float4 columns)
    {
        const float* qbase = qg + ((size_t)(b * S_ + q0) * NH_ + h) * HD_;
#pragma unroll
        for (int it = 0; it < 8; it++) {
            int fi = tid + it * 256;
            int r = fi >> 5, d4 = fi & 31;
            float4 v = *(const float4*)(qbase + (size_t)r * (NH_ * HD_) + d4 * 4);
            Qs[r * 32 + (d4 ^ ((r >> 2) & 7))] = v;
        }
    }

    float m_[4], l_[4], o_[4][8];
#pragma unroll
    for (int i = 0; i < 4; i++) {
        m_[i] = -1e30f; l_[i] = 0.f;
#pragma unroll
        for (int j = 0; j < 8; j++) o_[i][j] = 0.f;
    }

    const int nB = (kend - ls + 63) >> 6;
    for (int t = -1; t < nB; t++) {
        const int kbase = (t < 0) ? 0 : (ls + (t << 6));
        int kcnt = (t < 0) ? NMETA_ : (kend - kbase);
        if (kcnt > 64) kcnt = 64;

        __syncthreads();   // previous PV done (and Q visible on first iter path)
        // Load K,V tiles (zero-fill invalid rows)
#pragma unroll
        for (int it = 0; it < 8; it++) {
            int fi = tid + it * 256;
            int r = fi >> 5, d4 = fi & 31;
            float4 kvv, vvv;
            if (r < kcnt) {
                size_t base = ((size_t)(b * S_ + kbase + r) * 8 + kvh) * 128;
                kvv = *(const float4*)(kvg + base + d4 * 4);
                vvv = *(const float4*)(kvg + base + 512 + d4 * 4);
            } else {
                kvv = make_float4(0.f, 0.f, 0.f, 0.f);
                vvv = kvv;
            }
            int si = r * 32 + (d4 ^ ((r >> 2) & 7));
            Ks[si] = kvv;
            Vs[si] = vvv;
        }
        __syncthreads();

        // Scores: s[i][j] = Q[ty*4+i] . K[tx*4+j]
        float s[4][4];
#pragma unroll
        for (int i = 0; i < 4; i++)
#pragma unroll
            for (int j = 0; j < 4; j++) s[i][j] = 0.f;

#pragma unroll 8
        for (int d4 = 0; d4 < 32; d4++) {
            float4 qv[4], kv4[4];
#pragma unroll
            for (int i = 0; i < 4; i++)
                qv[i] = Qs[(ty * 4 + i) * 32 + (d4 ^ (ty & 7))];
#pragma unroll
            for (int j = 0; j < 4; j++)
                kv4[j] = Ks[(tx * 4 + j) * 32 + (d4 ^ (tx & 7))];
#pragma unroll
            for (int i = 0; i < 4; i++)
#pragma unroll
                for (int j = 0; j < 4; j++) {
                    s[i][j] += qv[i].x * kv4[j].x;
                    s[i][j] += qv[i].y * kv4[j].y;
                    s[i][j] += qv[i].z * kv4[j].z;
                    s[i][j] += qv[i].w * kv4[j].w;
                }
        }

        // Mask + online softmax update
#pragma unroll
        for (int i = 0; i < 4; i++) {
            const int qpos = q0 + ty * 4 + i;
#pragma unroll
            for (int j = 0; j < 4; j++) {
                int kk = tx * 4 + j;
                int kpos = kbase + kk;
                bool ok = (kk < kcnt) && (kpos <= qpos) &&
                          ((kpos >= qpos - (WINDOW_ - 1)) || (kpos < NMETA_));
                s[i][j] = ok ? s[i][j] * scale : -1e30f;
            }
        }

#pragma unroll
        for (int i = 0; i < 4; i++) {
            float tm = fmaxf(fmaxf(s[i][0], s[i][1]), fmaxf(s[i][2], s[i][3]));
#pragma unroll
            for (int off = 8; off >= 1; off >>= 1)
                tm = fmaxf(tm, __shfl_xor_sync(0xffffffffu, tm, off));
            float mn = fmaxf(m_[i], tm);
            float fac = __expf(m_[i] - mn);
            float rs = 0.f;
#pragma unroll
            for (int j = 0; j < 4; j++) {
                float p = __expf(s[i][j] - mn);
                s[i][j] = p;
                rs += p;
            }
#pragma unroll
            for (int off = 8; off >= 1; off >>= 1)
                rs += __shfl_xor_sync(0xffffffffu, rs, off);
            l_[i] = l_[i] * fac + rs;
            m_[i] = mn;
#pragma unroll
            for (int j = 0; j < 8; j++) o_[i][j] *= fac;
        }

        // Store P (probabilities)
#pragma unroll
        for (int i = 0; i < 4; i++)
#pragma unroll
            for (int j = 0; j < 4; j++)
                Ps[(ty * 4 + i) * 65 + tx * 4 + j] = s[i][j];
        __syncthreads();

        // O += P @ V   (rows ty*4+i, cols tx*8..tx*8+7)
#pragma unroll 4
        for (int kk = 0; kk < 64; kk++) {
            float4 v0 = Vs[kk * 32 + ((tx * 2)     ^ ((kk >> 2) & 7))];
            float4 v1 = Vs[kk * 32 + ((tx * 2 + 1) ^ ((kk >> 2) & 7))];
#pragma unroll
            for (int i = 0; i < 4; i++) {
                float p = Ps[(ty * 4 + i) * 65 + kk];
                o_[i][0] += p * v0.x; o_[i][1] += p * v0.y;
                o_[i][2] += p * v0.z; o_[i][3] += p * v0.w;
                o_[i][4] += p * v1.x; o_[i][5] += p * v1.y;
                o_[i][6] += p * v1.z; o_[i][7] += p * v1.w;
            }
        }
    }

    // Epilogue: normalize, write y[b, q, h, :]
#pragma unroll
    for (int i = 0; i < 4; i++) {
        float inv = 1.0f / l_[i];
        size_t base = ((size_t)(b * S_ + q0 + ty * 4 + i) * NH_ + h) * HD_ + tx * 8;
        float4 r0 = make_float4(o_[i][0] * inv, o_[i][1] * inv, o_[i][2] * inv, o_[i][3] * inv);
        float4 r1 = make_float4(o_[i][4] * inv, o_[i][5] * inv, o_[i][6] * inv, o_[i][7] * inv);
        *(float4*)(yg + base)     = r0;
        *(float4*)(yg + base + 4) = r1;
    }
}

// ---------------------------------------------------------------------------
// Launch
// ---------------------------------------------------------------------------
extern "C" void kernel_launch(void* const* d_in, const int* in_sizes, int n_in,
                              void* d_out, int out_size)
{
    const float* x   = (const float*)d_in[0];
    const float* Wq  = (const float*)d_in[1];
    const float* bq  = (const float*)d_in[2];
    const float* Wkv = (const float*)d_in[3];
    const float* bkv = (const float*)d_in[4];
    const float* Wo  = (const float*)d_in[5];
    const float* bo  = (const float*)d_in[6];
    float* out = (float*)d_out;

    float *q_, *kv_, *y_;
    cudaGetSymbolAddress((void**)&q_,  g_q);
    cudaGetSymbolAddress((void**)&kv_, g_kv);
    cudaGetSymbolAddress((void**)&y_,  g_y);

    const int M = B_ * S_;

    // 1) q = x @ Wq + bq
    gemm_bias_kernel<<<dim3(E_ / 128, M / 128), 256>>>(x, Wq, bq, q_, M, E_, E_);
    // 2) kv = x @ Wkv + bkv
    gemm_bias_kernel<<<dim3(KVOUT_ / 128, M / 128), 256>>>(x, Wkv, bkv, kv_, M, KVOUT_, E_);
    // 3) RoPE on q and k
    rope_q_kernel<<<(B_ * S_ * NH_ * 64) / 256, 256>>>(q_);
    rope_k_kernel<<<(B_ * S_ * NKV_ * 64) / 256, 256>>>(kv_);
    // 4) Sliding-window attention with meta sinks
    cudaFuncSetAttribute(attn_kernel, cudaFuncAttributeMaxDynamicSharedMemorySize,
                         ATTN_SMEM_BYTES);
    attn_kernel<<<dim3(S_ / 64, B_ * NH_), 256, ATTN_SMEM_BYTES>>>(q_, kv_, y_);
    // 5) out = y @ Wo + bo
    gemm_bias_kernel<<<dim3(E_ / 128, M / 128), 256>>>(y_, Wo, bo, out, M, E_, E_);
}

// round 3
// speedup vs baseline: 1.7638x; 1.7638x over previous
#include <cuda_runtime.h>
#include <cuda_bf16.h>
#include <math.h>

typedef unsigned int u32;

// Problem constants
#define B_      2
#define S_      4096
#define E_      2048
#define NH_     16
#define HD_     128
#define NKV_    4
#define KVOUT_  1024
#define WINDOW_ 512
#define NMETA_  16

// ---------------------------------------------------------------------------
// Scratch (device globals)
// ---------------------------------------------------------------------------
__device__ float g_q [B_ * S_ * E_];
__device__ float g_kv[B_ * S_ * 2 * NKV_ * HD_];
__device__ float g_y [B_ * S_ * E_];
__device__ __nv_bfloat16 g_xh[B_ * S_ * E_];
__device__ __nv_bfloat16 g_xl[B_ * S_ * E_];
__device__ __nv_bfloat16 g_yh[B_ * S_ * E_];
__device__ __nv_bfloat16 g_yl[B_ * S_ * E_];
__device__ __nv_bfloat16 g_wqt_h[E_ * E_];
__device__ __nv_bfloat16 g_wqt_l[E_ * E_];
__device__ __nv_bfloat16 g_wkvt_h[KVOUT_ * E_];
__device__ __nv_bfloat16 g_wkvt_l[KVOUT_ * E_];
__device__ __nv_bfloat16 g_wot_h[E_ * E_];
__device__ __nv_bfloat16 g_wot_l[E_ * E_];
__device__ float2 g_ropetab[S_ * 64];

// ---------------------------------------------------------------------------
// Prep kernels
// ---------------------------------------------------------------------------
__global__ void split_kernel(const float* __restrict__ in,
                             __nv_bfloat16* __restrict__ hi,
                             __nv_bfloat16* __restrict__ lo, int n4)
{
    int i = blockIdx.x * 256 + threadIdx.x;
    if (i >= n4) return;
    float4 v = ((const float4*)in)[i];
    __nv_bfloat16 h0 = __float2bfloat16(v.x), h1 = __float2bfloat16(v.y);
    __nv_bfloat16 h2 = __float2bfloat16(v.z), h3 = __float2bfloat16(v.w);
    __nv_bfloat162* H = (__nv_bfloat162*)hi;
    __nv_bfloat162* L = (__nv_bfloat162*)lo;
    H[i * 2]     = __nv_bfloat162(h0, h1);
    H[i * 2 + 1] = __nv_bfloat162(h2, h3);
    L[i * 2]     = __nv_bfloat162(__float2bfloat16(v.x - __bfloat162float(h0)),
                                  __float2bfloat16(v.y - __bfloat162float(h1)));
    L[i * 2 + 1] = __nv_bfloat162(__float2bfloat16(v.z - __bfloat162float(h2)),
                                  __float2bfloat16(v.w - __bfloat162float(h3)));
}

__global__ void transpose_split(const float* __restrict__ W,
                                __nv_bfloat16* __restrict__ Th,
                                __nv_bfloat16* __restrict__ Tl, int K, int N)
{
    __shared__ float t[32][33];
    int n0 = blockIdx.x * 32, k0 = blockIdx.y * 32;
    for (int i = threadIdx.y; i < 32; i += 8)
        t[i][threadIdx.x] = W[(size_t)(k0 + i) * N + n0 + threadIdx.x];
    __syncthreads();
    for (int i = threadIdx.y; i < 32; i += 8) {
        float v = t[threadIdx.x][i];
        size_t o = (size_t)(n0 + i) * K + k0 + threadIdx.x;
        __nv_bfloat16 h = __float2bfloat16(v);
        Th[o] = h;
        Tl[o] = __float2bfloat16(v - __bfloat162float(h));
    }
}

__global__ void rope_table_kernel(float2* tab)
{
    int idx = blockIdx.x * 256 + threadIdx.x;
    if (idx >= S_ * 64) return;
    int pos = idx >> 6, i = idx & 63;
    float inv = (float)exp(-(double)i * (9.210340371976184 / 64.0));
    float ang = (float)pos * inv;
    tab[idx] = make_float2(cosf(ang), sinf(ang));
}

// ---------------------------------------------------------------------------
// mma.sync bf16 GEMM (portable PTX; compiles to HMMA on sm_103)
// C[M,N] = (Ahi+Alo)[M,K] @ (Bhi+Blo)[N,K]^T + bias, fused RoPE.
// Block 128x128x32, 8 warps (2m x 4n), warp tile 64x32, cp.async 2-stage.
// rope_mode: 0 none, 1 all cols, 2 cols < 512
// ---------------------------------------------------------------------------
#define BKP       40                    // BK=32 + pad 8 (bf16 units)
#define TILE_ELEM (128 * BKP)           // per tile
#define STAGE_ELEM (4 * TILE_ELEM)      // Ah, Al, Bh, Bl
#define GT_SMEM   (2 * STAGE_ELEM * 2)  // bytes

#define CP_ASYNC16(dst, src) \
    asm volatile("cp.async.cg.shared.global [%0], [%1], 16;" :: "r"(dst), "l"(src))
#define CP_COMMIT() asm volatile("cp.async.commit_group;")
#define CP_WAIT1()  asm volatile("cp.async.wait_group 1;")
#define CP_WAIT0()  asm volatile("cp.async.wait_group 0;")

__device__ __forceinline__ u32 smem_u32(const void* p) {
    u32 a;
    asm("{ .reg .u64 t; cvta.to.shared.u64 t, %1; cvt.u32.u64 %0, t; }"
        : "=r"(a) : "l"(p));
    return a;
}

__device__ __forceinline__ void mma16816(float* d, const u32* a, const u32* b)
{
    asm volatile(
        "mma.sync.aligned.m16n8k16.row.col.f32.bf16.bf16.f32 "
        "{%0,%1,%2,%3}, {%4,%5,%6,%7}, {%8,%9}, {%0,%1,%2,%3};"
        : "+f"(d[0]), "+f"(d[1]), "+f"(d[2]), "+f"(d[3])
        : "r"(a[0]), "r"(a[1]), "r"(a[2]), "r"(a[3]), "r"(b[0]), "r"(b[1]));
}

__global__ __launch_bounds__(256, 1) void mma_gemm_kernel(
    const __nv_bfloat16* __restrict__ Ahi, const __nv_bfloat16* __restrict__ Alo,
    const __nv_bfloat16* __restrict__ Bhi, const __nv_bfloat16* __restrict__ Blo,
    const float* __restrict__ bias, float* __restrict__ C,
    const float2* __restrict__ tab, int M, int N, int K, int rope_mode)
{
    extern __shared__ __nv_bfloat16 sm[];
    const u32 sbase = smem_u32(sm);
    const int tid = threadIdx.x;
    const int wid = tid >> 5, lane = tid & 31;
    const int wm = wid & 1, wn = wid >> 1;     // 2 x 4 warp grid
    const int m0 = blockIdx.y * 128;
    const int n0 = blockIdx.x * 128;
    const int g  = lane >> 2;                   // row within 8-group
    const int c0 = (lane & 3) * 2;              // k pair / col pair

    // cp.async load of one stage (4 tiles: Ah, Al, Bh, Bl)
    auto load_stage = [&](int c, int stage) {
        const int k0 = c * 32;
        const u32 sb = sbase + stage * STAGE_ELEM * 2;
#pragma unroll
        for (int i = 0; i < 2; i++) {
            int idx = tid + i * 256;            // 0..511
            int row = idx >> 2, quad = idx & 3;
            u32 soff = (u32)(row * BKP + quad * 8) * 2;
            size_t ga = (size_t)(m0 + row) * K + k0 + quad * 8;
            size_t gb = (size_t)(n0 + row) * K + k0 + quad * 8;
            CP_ASYNC16(sb + soff,                    (const char*)(Ahi + ga));
            CP_ASYNC16(sb + TILE_ELEM * 2 + soff,    (const char*)(Alo + ga));
            CP_ASYNC16(sb + TILE_ELEM * 4 + soff,    (const char*)(Bhi + gb));
            CP_ASYNC16(sb + TILE_ELEM * 6 + soff,    (const char*)(Blo + gb));
        }
    };

    float acc[4][4][4];
#pragma unroll
    for (int i = 0; i < 4; i++)
#pragma unroll
        for (int j = 0; j < 4; j++)
#pragma unroll
            for (int e = 0; e < 4; e++) acc[i][j][e] = 0.f;

    const int nc = K >> 5;
    load_stage(0, 0);
    CP_COMMIT();

    for (int c = 0; c < nc; c++) {
        if (c + 1 < nc) {
            load_stage(c + 1, (c + 1) & 1);
            CP_COMMIT();
            CP_WAIT1();
        } else {
            CP_WAIT0();
        }
        __syncthreads();

        const __nv_bfloat16* st = sm + (c & 1) * STAGE_ELEM;
        const __nv_bfloat16* Ah = st;
        const __nv_bfloat16* Al = st + TILE_ELEM;
        const __nv_bfloat16* Bh = st + 2 * TILE_ELEM;
        const __nv_bfloat16* Bl = st + 3 * TILE_ELEM;

#pragma unroll
        for (int kh = 0; kh < 2; kh++) {
            const int kk = kh * 16 + c0;
            // B fragments: 4 n-frags x 2 regs (hi & lo)
            u32 bh[4][2], bl[4][2];
#pragma unroll
            for (int nf = 0; nf < 4; nf++) {
                int nrow = wn * 32 + nf * 8 + g;
                bh[nf][0] = *(const u32*)(Bh + nrow * BKP + kk);
                bh[nf][1] = *(const u32*)(Bh + nrow * BKP + kk + 8);
                bl[nf][0] = *(const u32*)(Bl + nrow * BKP + kk);
                bl[nf][1] = *(const u32*)(Bl + nrow * BKP + kk + 8);
            }
#pragma unroll
            for (int mf = 0; mf < 4; mf++) {
                int r0 = wm * 64 + mf * 16 + g;
                u32 ah[4], al[4];
                ah[0] = *(const u32*)(Ah + r0 * BKP + kk);
                ah[1] = *(const u32*)(Ah + (r0 + 8) * BKP + kk);
                ah[2] = *(const u32*)(Ah + r0 * BKP + kk + 8);
                ah[3] = *(const u32*)(Ah + (r0 + 8) * BKP + kk + 8);
                al[0] = *(const u32*)(Al + r0 * BKP + kk);
                al[1] = *(const u32*)(Al + (r0 + 8) * BKP + kk);
                al[2] = *(const u32*)(Al + r0 * BKP + kk + 8);
                al[3] = *(const u32*)(Al + (r0 + 8) * BKP + kk + 8);
#pragma unroll
                for (int nf = 0; nf < 4; nf++) {
                    mma16816(acc[mf][nf], ah, bh[nf]);
                    mma16816(acc[mf][nf], ah, bl[nf]);
                    mma16816(acc[mf][nf], al, bh[nf]);
                }
            }
        }
        __syncthreads();
    }

    // Epilogue: bias + fused RoPE + store
#pragma unroll
    for (int mf = 0; mf < 4; mf++) {
        int row0 = m0 + wm * 64 + mf * 16 + g;
        int pos0 = row0 & (S_ - 1);
        int pos1 = (row0 + 8) & (S_ - 1);
#pragma unroll
        for (int nf = 0; nf < 4; nf++) {
            int col = n0 + wn * 32 + nf * 8 + c0;
            float b0 = bias[col], b1 = bias[col + 1];
            float v0 = acc[mf][nf][0] + b0, v1 = acc[mf][nf][1] + b1;
            float v2 = acc[mf][nf][2] + b0, v3 = acc[mf][nf][3] + b1;
            bool do_rope = (rope_mode == 1) || (rope_mode == 2 && col < 512);
            if (do_rope) {
                int ti = (col & 127) >> 1;
                float2 cs0 = tab[pos0 * 64 + ti];
                float2 cs1 = tab[pos1 * 64 + ti];
                float t0 = v0, t1 = v1;
                v0 = t0 * cs0.x - t1 * cs0.y;
                v1 = t1 * cs0.x + t0 * cs0.y;
                float t2 = v2, t3 = v3;
                v2 = t2 * cs1.x - t3 * cs1.y;
                v3 = t3 * cs1.x + t2 * cs1.y;
            }
            *(float2*)(C + (size_t)row0 * N + col)       = make_float2(v0, v1);
            *(float2*)(C + (size_t)(row0 + 8) * N + col) = make_float2(v2, v3);
        }
    }
}

// ---------------------------------------------------------------------------
// Attention (SIMT flash-style, fp32) — unchanged from round 1 (passing)
// ---------------------------------------------------------------------------
#define ATTN_SMEM_BYTES ((3 * 64 * 128 + 64 * 65) * 4)

__global__ __launch_bounds__(256) void attn_kernel(
    const float* __restrict__ qg, const float* __restrict__ kvg,
    float* __restrict__ yg)
{
    extern __shared__ float smf[];
    float4* Qs = (float4*)smf;
    float4* Ks = Qs + 64 * 32;
    float4* Vs = Ks + 64 * 32;
    float*  Ps = (float*)(Vs + 64 * 32);

    const int tid = threadIdx.x;
    const int tx = tid & 15, ty = tid >> 4;
    const int bh = blockIdx.y;
    const int b = bh >> 4, h = bh & 15;
    const int kvh = h >> 2;
    const int q0 = blockIdx.x << 6;
    const int qs = q0 & ~(WINDOW_ - 1);
    int ls = qs - WINDOW_ + 1; if (ls < NMETA_) ls = NMETA_;
    const int kend = q0 + 64;
    const float scale = 0.088388347648318447f;

    {
        const float* qbase = qg + ((size_t)(b * S_ + q0) * NH_ + h) * HD_;
#pragma unroll
        for (int it = 0; it < 8; it++) {
            int fi = tid + it * 256;
            int r = fi >> 5, d4 = fi & 31;
            float4 v = *(const float4*)(qbase + (size_t)r * (NH_ * HD_) + d4 * 4);
            Qs[r * 32 + (d4 ^ ((r >> 2) & 7))] = v;
        }
    }

    float m_[4], l_[4], o_[4][8];
#pragma unroll
    for (int i = 0; i < 4; i++) {
        m_[i] = -1e30f; l_[i] = 0.f;
#pragma unroll
        for (int j = 0; j < 8; j++) o_[i][j] = 0.f;
    }

    const int nB = (kend - ls + 63) >> 6;
    for (int t = -1; t < nB; t++) {
        const int kbase = (t < 0) ? 0 : (ls + (t << 6));
        int kcnt = (t < 0) ? NMETA_ : (kend - kbase);
        if (kcnt > 64) kcnt = 64;

        __syncthreads();
#pragma unroll
        for (int it = 0; it < 8; it++) {
            int fi = tid + it * 256;
            int r = fi >> 5, d4 = fi & 31;
            float4 kvv, vvv;
            if (r < kcnt) {
                size_t base = ((size_t)(b * S_ + kbase + r) * 8 + kvh) * 128;
                kvv = *(const float4*)(kvg + base + d4 * 4);
                vvv = *(const float4*)(kvg + base + 512 + d4 * 4);
            } else {
                kvv = make_float4(0.f, 0.f, 0.f, 0.f);
                vvv = kvv;
            }
            int si = r * 32 + (d4 ^ ((r >> 2) & 7));
            Ks[si] = kvv;
            Vs[si] = vvv;
        }
        __syncthreads();

        float s[4][4];
#pragma unroll
        for (int i = 0; i < 4; i++)
#pragma unroll
            for (int j = 0; j < 4; j++) s[i][j] = 0.f;

#pragma unroll 8
        for (int d4 = 0; d4 < 32; d4++) {
            float4 qv[4], kv4[4];
#pragma unroll
            for (int i = 0; i < 4; i++)
                qv[i] = Qs[(ty * 4 + i) * 32 + (d4 ^ (ty & 7))];
#pragma unroll
            for (int j = 0; j < 4; j++)
                kv4[j] = Ks[(tx * 4 + j) * 32 + (d4 ^ (tx & 7))];
#pragma unroll
            for (int i = 0; i < 4; i++)
#pragma unroll
                for (int j = 0; j < 4; j++) {
                    s[i][j] += qv[i].x * kv4[j].x;
                    s[i][j] += qv[i].y * kv4[j].y;
                    s[i][j] += qv[i].z * kv4[j].z;
                    s[i][j] += qv[i].w * kv4[j].w;
                }
        }

#pragma unroll
        for (int i = 0; i < 4; i++) {
            const int qpos = q0 + ty * 4 + i;
#pragma unroll
            for (int j = 0; j < 4; j++) {
                int kk = tx * 4 + j;
                int kpos = kbase + kk;
                bool ok = (kk < kcnt) && (kpos <= qpos) &&
                          ((kpos >= qpos - (WINDOW_ - 1)) || (kpos < NMETA_));
                s[i][j] = ok ? s[i][j] * scale : -1e30f;
            }
        }

#pragma unroll
        for (int i = 0; i < 4; i++) {
            float tm = fmaxf(fmaxf(s[i][0], s[i][1]), fmaxf(s[i][2], s[i][3]));
#pragma unroll
            for (int off = 8; off >= 1; off >>= 1)
                tm = fmaxf(tm, __shfl_xor_sync(0xffffffffu, tm, off));
            float mn = fmaxf(m_[i], tm);
            float fac = __expf(m_[i] - mn);
            float rs = 0.f;
#pragma unroll
            for (int j = 0; j < 4; j++) {
                float p = __expf(s[i][j] - mn);
                s[i][j] = p;
                rs += p;
            }
#pragma unroll
            for (int off = 8; off >= 1; off >>= 1)
                rs += __shfl_xor_sync(0xffffffffu, rs, off);
            l_[i] = l_[i] * fac + rs;
            m_[i] = mn;
#pragma unroll
            for (int j = 0; j < 8; j++) o_[i][j] *= fac;
        }

#pragma unroll
        for (int i = 0; i < 4; i++)
#pragma unroll
            for (int j = 0; j < 4; j++)
                Ps[(ty * 4 + i) * 65 + tx * 4 + j] = s[i][j];
        __syncthreads();

#pragma unroll 4
        for (int kk = 0; kk < 64; kk++) {
            float4 v0 = Vs[kk * 32 + ((tx * 2)     ^ ((kk >> 2) & 7))];
            float4 v1 = Vs[kk * 32 + ((tx * 2 + 1) ^ ((kk >> 2) & 7))];
#pragma unroll
            for (int i = 0; i < 4; i++) {
                float p = Ps[(ty * 4 + i) * 65 + kk];
                o_[i][0] += p * v0.x; o_[i][1] += p * v0.y;
                o_[i][2] += p * v0.z; o_[i][3] += p * v0.w;
                o_[i][4] += p * v1.x; o_[i][5] += p * v1.y;
                o_[i][6] += p * v1.z; o_[i][7] += p * v1.w;
            }
        }
    }

#pragma unroll
    for (int i = 0; i < 4; i++) {
        float inv = 1.0f / l_[i];
        size_t base = ((size_t)(b * S_ + q0 + ty * 4 + i) * NH_ + h) * HD_ + tx * 8;
        float4 r0 = make_float4(o_[i][0] * inv, o_[i][1] * inv, o_[i][2] * inv, o_[i][3] * inv);
        float4 r1 = make_float4(o_[i][4] * inv, o_[i][5] * inv, o_[i][6] * inv, o_[i][7] * inv);
        *(float4*)(yg + base)     = r0;
        *(float4*)(yg + base + 4) = r1;
    }
}

// ---------------------------------------------------------------------------
// Launch
// ---------------------------------------------------------------------------
extern "C" void kernel_launch(void* const* d_in, const int* in_sizes, int n_in,
                              void* d_out, int out_size)
{
    const float* x   = (const float*)d_in[0];
    const float* Wq  = (const float*)d_in[1];
    const float* bq  = (const float*)d_in[2];
    const float* Wkv = (const float*)d_in[3];
    const float* bkv = (const float*)d_in[4];
    const float* Wo  = (const float*)d_in[5];
    const float* bo  = (const float*)d_in[6];
    float* out = (float*)d_out;

    float *q_, *kv_, *y_;
    __nv_bfloat16 *xh, *xl, *yh, *yl, *wqh, *wql, *wkh, *wkl, *woh, *wol;
    float2* tab;
    cudaGetSymbolAddress((void**)&q_,  g_q);
    cudaGetSymbolAddress((void**)&kv_, g_kv);
    cudaGetSymbolAddress((void**)&y_,  g_y);
    cudaGetSymbolAddress((void**)&xh,  g_xh);
    cudaGetSymbolAddress((void**)&xl,  g_xl);
    cudaGetSymbolAddress((void**)&yh,  g_yh);
    cudaGetSymbolAddress((void**)&yl,  g_yl);
    cudaGetSymbolAddress((void**)&wqh, g_wqt_h);
    cudaGetSymbolAddress((void**)&wql, g_wqt_l);
    cudaGetSymbolAddress((void**)&wkh, g_wkvt_h);
    cudaGetSymbolAddress((void**)&wkl, g_wkvt_l);
    cudaGetSymbolAddress((void**)&woh, g_wot_h);
    cudaGetSymbolAddress((void**)&wol, g_wot_l);
    cudaGetSymbolAddress((void**)&tab, g_ropetab);

    const int M = B_ * S_;
    const int n4 = (B_ * S_ * E_) / 4;

    split_kernel<<<n4 / 256, 256>>>(x, xh, xl, n4);
    transpose_split<<<dim3(E_ / 32, E_ / 32), dim3(32, 8)>>>(Wq, wqh, wql, E_, E_);
    transpose_split<<<dim3(KVOUT_ / 32, E_ / 32), dim3(32, 8)>>>(Wkv, wkh, wkl, E_, KVOUT_);
    transpose_split<<<dim3(E_ / 32, E_ / 32), dim3(32, 8)>>>(Wo, woh, wol, E_, E_);
    rope_table_kernel<<<(S_ * 64) / 256, 256>>>(tab);

    cudaFuncSetAttribute(mma_gemm_kernel, cudaFuncAttributeMaxDynamicSharedMemorySize,
                         GT_SMEM);

    // q = x @ Wq + bq  (+RoPE all cols)
    mma_gemm_kernel<<<dim3(E_ / 128, M / 128), 256, GT_SMEM>>>(
        xh, xl, wqh, wql, bq, q_, tab, M, E_, E_, 1);
    // kv = x @ Wkv + bkv  (+RoPE on K half, cols < 512)
    mma_gemm_kernel<<<dim3(KVOUT_ / 128, M / 128), 256, GT_SMEM>>>(
        xh, xl, wkh, wkl, bkv, kv_, tab, M, KVOUT_, E_, 2);

    cudaFuncSetAttribute(attn_kernel, cudaFuncAttributeMaxDynamicSharedMemorySize,
                         ATTN_SMEM_BYTES);
    attn_kernel<<<dim3(S_ / 64, B_ * NH_), 256, ATTN_SMEM_BYTES>>>(q_, kv_, y_);

    split_kernel<<<n4 / 256, 256>>>(y_, yh, yl, n4);
    mma_gemm_kernel<<<dim3(E_ / 128, M / 128), 256, GT_SMEM>>>(
        yh, yl, woh, wol, bo, out, tab, M, E_, E_, 0);
}

// round 4
// speedup vs baseline: 1.9992x; 1.1334x over previous
#include <cuda_runtime.h>
#include <cuda_bf16.h>
#include <math.h>

typedef unsigned int u32;

// Problem constants
#define B_      2
#define S_      4096
#define E_      2048
#define NH_     16
#define HD_     128
#define NKV_    4
#define KVOUT_  1024
#define WINDOW_ 512
#define NMETA_  16

// ---------------------------------------------------------------------------
// Scratch (device globals)
// ---------------------------------------------------------------------------
__device__ __nv_bfloat16 g_xh[B_ * S_ * E_];
__device__ __nv_bfloat16 g_xl[B_ * S_ * E_];
__device__ __nv_bfloat16 g_qh[B_ * S_ * E_];
__device__ __nv_bfloat16 g_ql[B_ * S_ * E_];
__device__ __nv_bfloat16 g_kvh[B_ * S_ * KVOUT_];
__device__ __nv_bfloat16 g_kvl[B_ * S_ * KVOUT_];
__device__ __nv_bfloat16 g_yh[B_ * S_ * E_];
__device__ __nv_bfloat16 g_yl[B_ * S_ * E_];
__device__ __nv_bfloat16 g_wqt_h[E_ * E_];
__device__ __nv_bfloat16 g_wqt_l[E_ * E_];
__device__ __nv_bfloat16 g_wkvt_h[KVOUT_ * E_];
__device__ __nv_bfloat16 g_wkvt_l[KVOUT_ * E_];
__device__ __nv_bfloat16 g_wot_h[E_ * E_];
__device__ __nv_bfloat16 g_wot_l[E_ * E_];
__device__ float2 g_ropetab[S_ * 64];

// ---------------------------------------------------------------------------
// Helpers
// ---------------------------------------------------------------------------
__device__ __forceinline__ u32 smem_u32(const void* p) {
    u32 a;
    asm("{ .reg .u64 t; cvta.to.shared.u64 t, %1; cvt.u32.u64 %0, t; }"
        : "=r"(a) : "l"(p));
    return a;
}

__device__ __forceinline__ void mma16816(float* d, const u32* a, const u32* b)
{
    asm volatile(
        "mma.sync.aligned.m16n8k16.row.col.f32.bf16.bf16.f32 "
        "{%0,%1,%2,%3}, {%4,%5,%6,%7}, {%8,%9}, {%0,%1,%2,%3};"
        : "+f"(d[0]), "+f"(d[1]), "+f"(d[2]), "+f"(d[3])
        : "r"(a[0]), "r"(a[1]), "r"(a[2]), "r"(a[3]), "r"(b[0]), "r"(b[1]));
}

// split two floats into packed bf16 hi + bf16 residual
__device__ __forceinline__ void split2(float x, float y, u32& hh, u32& ll)
{
    __nv_bfloat16 hx = __float2bfloat16(x), hy = __float2bfloat16(y);
    __nv_bfloat162 hv(hx, hy);
    __nv_bfloat162 lv(__float2bfloat16(x - __bfloat162float(hx)),
                      __float2bfloat16(y - __bfloat162float(hy)));
    hh = *(u32*)&hv; ll = *(u32*)&lv;
}

// ---------------------------------------------------------------------------
// Prep kernels
// ---------------------------------------------------------------------------
__global__ void split_kernel(const float* __restrict__ in,
                             __nv_bfloat16* __restrict__ hi,
                             __nv_bfloat16* __restrict__ lo, int n4)
{
    int i = blockIdx.x * 256 + threadIdx.x;
    if (i >= n4) return;
    float4 v = ((const float4*)in)[i];
    __nv_bfloat16 h0 = __float2bfloat16(v.x), h1 = __float2bfloat16(v.y);
    __nv_bfloat16 h2 = __float2bfloat16(v.z), h3 = __float2bfloat16(v.w);
    __nv_bfloat162* H = (__nv_bfloat162*)hi;
    __nv_bfloat162* L = (__nv_bfloat162*)lo;
    H[i * 2]     = __nv_bfloat162(h0, h1);
    H[i * 2 + 1] = __nv_bfloat162(h2, h3);
    L[i * 2]     = __nv_bfloat162(__float2bfloat16(v.x - __bfloat162float(h0)),
                                  __float2bfloat16(v.y - __bfloat162float(h1)));
    L[i * 2 + 1] = __nv_bfloat162(__float2bfloat16(v.z - __bfloat162float(h2)),
                                  __float2bfloat16(v.w - __bfloat162float(h3)));
}

__global__ void transpose_split(const float* __restrict__ W,
                                __nv_bfloat16* __restrict__ Th,
                                __nv_bfloat16* __restrict__ Tl, int K, int N)
{
    __shared__ float t[32][33];
    int n0 = blockIdx.x * 32, k0 = blockIdx.y * 32;
    for (int i = threadIdx.y; i < 32; i += 8)
        t[i][threadIdx.x] = W[(size_t)(k0 + i) * N + n0 + threadIdx.x];
    __syncthreads();
    for (int i = threadIdx.y; i < 32; i += 8) {
        float v = t[threadIdx.x][i];
        size_t o = (size_t)(n0 + i) * K + k0 + threadIdx.x;
        __nv_bfloat16 h = __float2bfloat16(v);
        Th[o] = h;
        Tl[o] = __float2bfloat16(v - __bfloat162float(h));
    }
}

__global__ void rope_table_kernel(float2* tab)
{
    int idx = blockIdx.x * 256 + threadIdx.x;
    if (idx >= S_ * 64) return;
    int pos = idx >> 6, i = idx & 63;
    float inv = (float)exp(-(double)i * (9.210340371976184 / 64.0));
    float ang = (float)pos * inv;
    tab[idx] = make_float2(cosf(ang), sinf(ang));
}

// ---------------------------------------------------------------------------
// mma.sync bf16 GEMM (proven R3 mainloop), epilogue: bias + RoPE + fp32 OR
// bf16 hi/lo output.
// rope_mode: 0 none, 1 all cols, 2 cols < 512
// ---------------------------------------------------------------------------
#define BKP       40
#define TILE_ELEM (128 * BKP)
#define STAGE_ELEM (4 * TILE_ELEM)
#define GT_SMEM   (2 * STAGE_ELEM * 2)

#define CP_ASYNC16(dst, src) \
    asm volatile("cp.async.cg.shared.global [%0], [%1], 16;" :: "r"(dst), "l"(src))
#define CP_COMMIT() asm volatile("cp.async.commit_group;")
#define CP_WAIT1()  asm volatile("cp.async.wait_group 1;")
#define CP_WAIT0()  asm volatile("cp.async.wait_group 0;")

__global__ __launch_bounds__(256, 1) void mma_gemm_kernel(
    const __nv_bfloat16* __restrict__ Ahi, const __nv_bfloat16* __restrict__ Alo,
    const __nv_bfloat16* __restrict__ Bhi, const __nv_bfloat16* __restrict__ Blo,
    const float* __restrict__ bias, float* __restrict__ Cf,
    __nv_bfloat16* __restrict__ Ch, __nv_bfloat16* __restrict__ Cl,
    const float2* __restrict__ tab, int M, int N, int K,
    int rope_mode, int bf16_out)
{
    extern __shared__ __nv_bfloat16 sm[];
    const u32 sbase = smem_u32(sm);
    const int tid = threadIdx.x;
    const int wid = tid >> 5, lane = tid & 31;
    const int wm = wid & 1, wn = wid >> 1;
    const int m0 = blockIdx.y * 128;
    const int n0 = blockIdx.x * 128;
    const int g  = lane >> 2;
    const int c0 = (lane & 3) * 2;

    auto load_stage = [&](int c, int stage) {
        const int k0 = c * 32;
        const u32 sb = sbase + stage * STAGE_ELEM * 2;
#pragma unroll
        for (int i = 0; i < 2; i++) {
            int idx = tid + i * 256;
            int row = idx >> 2, quad = idx & 3;
            u32 soff = (u32)(row * BKP + quad * 8) * 2;
            size_t ga = (size_t)(m0 + row) * K + k0 + quad * 8;
            size_t gb = (size_t)(n0 + row) * K + k0 + quad * 8;
            CP_ASYNC16(sb + soff,                 (const char*)(Ahi + ga));
            CP_ASYNC16(sb + TILE_ELEM * 2 + soff, (const char*)(Alo + ga));
            CP_ASYNC16(sb + TILE_ELEM * 4 + soff, (const char*)(Bhi + gb));
            CP_ASYNC16(sb + TILE_ELEM * 6 + soff, (const char*)(Blo + gb));
        }
    };

    float acc[4][4][4];
#pragma unroll
    for (int i = 0; i < 4; i++)
#pragma unroll
        for (int j = 0; j < 4; j++)
#pragma unroll
            for (int e = 0; e < 4; e++) acc[i][j][e] = 0.f;

    const int nc = K >> 5;
    load_stage(0, 0);
    CP_COMMIT();

    for (int c = 0; c < nc; c++) {
        if (c + 1 < nc) {
            load_stage(c + 1, (c + 1) & 1);
            CP_COMMIT();
            CP_WAIT1();
        } else {
            CP_WAIT0();
        }
        __syncthreads();

        const __nv_bfloat16* st = sm + (c & 1) * STAGE_ELEM;
        const __nv_bfloat16* Ah = st;
        const __nv_bfloat16* Al = st + TILE_ELEM;
        const __nv_bfloat16* Bh = st + 2 * TILE_ELEM;
        const __nv_bfloat16* Bl = st + 3 * TILE_ELEM;

#pragma unroll
        for (int kh = 0; kh < 2; kh++) {
            const int kk = kh * 16 + c0;
            u32 bh[4][2], bl[4][2];
#pragma unroll
            for (int nf = 0; nf < 4; nf++) {
                int nrow = wn * 32 + nf * 8 + g;
                bh[nf][0] = *(const u32*)(Bh + nrow * BKP + kk);
                bh[nf][1] = *(const u32*)(Bh + nrow * BKP + kk + 8);
                bl[nf][0] = *(const u32*)(Bl + nrow * BKP + kk);
                bl[nf][1] = *(const u32*)(Bl + nrow * BKP + kk + 8);
            }
#pragma unroll
            for (int mf = 0; mf < 4; mf++) {
                int r0 = wm * 64 + mf * 16 + g;
                u32 ah[4], al[4];
                ah[0] = *(const u32*)(Ah + r0 * BKP + kk);
                ah[1] = *(const u32*)(Ah + (r0 + 8) * BKP + kk);
                ah[2] = *(const u32*)(Ah + r0 * BKP + kk + 8);
                ah[3] = *(const u32*)(Ah + (r0 + 8) * BKP + kk + 8);
                al[0] = *(const u32*)(Al + r0 * BKP + kk);
                al[1] = *(const u32*)(Al + (r0 + 8) * BKP + kk);
                al[2] = *(const u32*)(Al + r0 * BKP + kk + 8);
                al[3] = *(const u32*)(Al + (r0 + 8) * BKP + kk + 8);
#pragma unroll
                for (int nf = 0; nf < 4; nf++) {
                    mma16816(acc[mf][nf], ah, bh[nf]);
                    mma16816(acc[mf][nf], ah, bl[nf]);
                    mma16816(acc[mf][nf], al, bh[nf]);
                }
            }
        }
        __syncthreads();
    }

    // Epilogue
#pragma unroll
    for (int mf = 0; mf < 4; mf++) {
        int row0 = m0 + wm * 64 + mf * 16 + g;
        int pos0 = row0 & (S_ - 1);
        int pos1 = (row0 + 8) & (S_ - 1);
#pragma unroll
        for (int nf = 0; nf < 4; nf++) {
            int col = n0 + wn * 32 + nf * 8 + c0;
            float b0 = bias[col], b1 = bias[col + 1];
            float v0 = acc[mf][nf][0] + b0, v1 = acc[mf][nf][1] + b1;
            float v2 = acc[mf][nf][2] + b0, v3 = acc[mf][nf][3] + b1;
            bool do_rope = (rope_mode == 1) || (rope_mode == 2 && col < 512);
            if (do_rope) {
                int ti = (col & 127) >> 1;
                float2 cs0 = tab[pos0 * 64 + ti];
                float2 cs1 = tab[pos1 * 64 + ti];
                float t0 = v0, t1 = v1;
                v0 = t0 * cs0.x - t1 * cs0.y;
                v1 = t1 * cs0.x + t0 * cs0.y;
                float t2 = v2, t3 = v3;
                v2 = t2 * cs1.x - t3 * cs1.y;
                v3 = t3 * cs1.x + t2 * cs1.y;
            }
            if (!bf16_out) {
                *(float2*)(Cf + (size_t)row0 * N + col)       = make_float2(v0, v1);
                *(float2*)(Cf + (size_t)(row0 + 8) * N + col) = make_float2(v2, v3);
            } else {
                u32 hh, ll;
                split2(v0, v1, hh, ll);
                *(u32*)(Ch + (size_t)row0 * N + col) = hh;
                *(u32*)(Cl + (size_t)row0 * N + col) = ll;
                split2(v2, v3, hh, ll);
                *(u32*)(Ch + (size_t)(row0 + 8) * N + col) = hh;
                *(u32*)(Cl + (size_t)(row0 + 8) * N + col) = ll;
            }
        }
    }
}

// ---------------------------------------------------------------------------
// Attention via mma.sync bf16, hi/lo 3-pass on QK and PV.
// Block = 64 queries x one (b,h), 4 warps; warp owns 16 query rows.
// smem (halves): Qh[64][136] Ql[64][136] Kh[64][136] Kl[64][136]
//                VTh[128][72] VTl[128][72]   (V stored transposed)
// ---------------------------------------------------------------------------
#define AT_BKP 136
#define AT_VP  72
#define Q_OFF   0
#define QL_OFF  (64 * AT_BKP)
#define KH_OFF  (2 * 64 * AT_BKP)
#define KL_OFF  (3 * 64 * AT_BKP)
#define VTH_OFF (4 * 64 * AT_BKP)
#define VTL_OFF (4 * 64 * AT_BKP + 128 * AT_VP)
#define ATT_SMEM ((4 * 64 * AT_BKP + 2 * 128 * AT_VP) * 2)

__global__ __launch_bounds__(128, 2) void attn_mma_kernel(
    const __nv_bfloat16* __restrict__ qh, const __nv_bfloat16* __restrict__ ql,
    const __nv_bfloat16* __restrict__ kvh, const __nv_bfloat16* __restrict__ kvl,
    __nv_bfloat16* __restrict__ yh, __nv_bfloat16* __restrict__ yl)
{
    extern __shared__ __nv_bfloat16 sm[];
    const int tid = threadIdx.x;
    const int w = tid >> 5, lane = tid & 31;
    const int g = lane >> 2, c0 = (lane & 3) * 2;
    const int bhp = blockIdx.y;
    const int b = bhp >> 4, h = bhp & 15;
    const int kv_h = h >> 2;
    const int q0 = blockIdx.x << 6;
    const int qs = q0 & ~(WINDOW_ - 1);
    int ls = qs - WINDOW_ + 1; if (ls < NMETA_) ls = NMETA_;
    const int kend = q0 + 64;
    const float scale = 0.088388347648318447f;

    // Load Q (hi/lo)
#pragma unroll
    for (int it = 0; it < 8; it++) {
        int fi = tid + it * 128;
        int r = fi >> 4, q8 = fi & 15;
        size_t ga = ((size_t)(b * S_ + q0 + r) * NH_ + h) * HD_ + q8 * 8;
        *(uint4*)&sm[Q_OFF  + r * AT_BKP + q8 * 8] = *(const uint4*)(qh + ga);
        *(uint4*)&sm[QL_OFF + r * AT_BKP + q8 * 8] = *(const uint4*)(ql + ga);
    }

    float m0 = -1e30f, m1 = -1e30f, l0 = 0.f, l1 = 0.f;
    float o[16][4];
#pragma unroll
    for (int i = 0; i < 16; i++)
#pragma unroll
        for (int e = 0; e < 4; e++) o[i][e] = 0.f;

    const int qp0 = q0 + w * 16 + g;
    const int qp1 = qp0 + 8;
    const int nB = (kend - ls + 63) >> 6;

    for (int t = -1; t < nB; t++) {
        const int kbase = (t < 0) ? 0 : (ls + (t << 6));
        int kcnt = (t < 0) ? NMETA_ : (kend - kbase);
        if (kcnt > 64) kcnt = 64;

        __syncthreads();
        // Load K (row-major) and V (transposed) tiles, hi/lo, zero-padded
#pragma unroll
        for (int it = 0; it < 8; it++) {
            int fi = tid + it * 128;
            int r = fi >> 4, q8 = fi & 15;
            uint4 kh4 = make_uint4(0, 0, 0, 0), kl4 = kh4, vh4 = kh4, vl4 = kh4;
            if (r < kcnt) {
                size_t base = (size_t)(b * S_ + kbase + r) * 1024 + kv_h * 128 + q8 * 8;
                kh4 = *(const uint4*)(kvh + base);
                kl4 = *(const uint4*)(kvl + base);
                vh4 = *(const uint4*)(kvh + base + 512);
                vl4 = *(const uint4*)(kvl + base + 512);
            }
            *(uint4*)&sm[KH_OFF + r * AT_BKP + q8 * 8] = kh4;
            *(uint4*)&sm[KL_OFF + r * AT_BKP + q8 * 8] = kl4;
            const __nv_bfloat16* pv = (const __nv_bfloat16*)&vh4;
            const __nv_bfloat16* pw = (const __nv_bfloat16*)&vl4;
#pragma unroll
            for (int j = 0; j < 8; j++) {
                sm[VTH_OFF + (q8 * 8 + j) * AT_VP + r] = pv[j];
                sm[VTL_OFF + (q8 * 8 + j) * AT_VP + r] = pw[j];
            }
        }
        __syncthreads();

        // --- QK^T: s[8 nfrags][4], 3-pass hi/lo ---
        float s[8][4];
#pragma unroll
        for (int nf = 0; nf < 8; nf++)
#pragma unroll
            for (int e = 0; e < 4; e++) s[nf][e] = 0.f;

        const int r0 = w * 16 + g;
#pragma unroll
        for (int ks = 0; ks < 8; ks++) {
            const int kk = ks * 16 + c0;
            u32 ah[4], al[4];
            ah[0] = *(const u32*)&sm[Q_OFF  + r0 * AT_BKP + kk];
            ah[1] = *(const u32*)&sm[Q_OFF  + (r0 + 8) * AT_BKP + kk];
            ah[2] = *(const u32*)&sm[Q_OFF  + r0 * AT_BKP + kk + 8];
            ah[3] = *(const u32*)&sm[Q_OFF  + (r0 + 8) * AT_BKP + kk + 8];
            al[0] = *(const u32*)&sm[QL_OFF + r0 * AT_BKP + kk];
            al[1] = *(const u32*)&sm[QL_OFF + (r0 + 8) * AT_BKP + kk];
            al[2] = *(const u32*)&sm[QL_OFF + r0 * AT_BKP + kk + 8];
            al[3] = *(const u32*)&sm[QL_OFF + (r0 + 8) * AT_BKP + kk + 8];
#pragma unroll
            for (int nf = 0; nf < 8; nf++) {
                int nr = nf * 8 + g;
                u32 bh2[2], bl2[2];
                bh2[0] = *(const u32*)&sm[KH_OFF + nr * AT_BKP + kk];
                bh2[1] = *(const u32*)&sm[KH_OFF + nr * AT_BKP + kk + 8];
                bl2[0] = *(const u32*)&sm[KL_OFF + nr * AT_BKP + kk];
                bl2[1] = *(const u32*)&sm[KL_OFF + nr * AT_BKP + kk + 8];
                mma16816(s[nf], ah, bh2);
                mma16816(s[nf], ah, bl2);
                mma16816(s[nf], al, bh2);
            }
        }

        // --- Mask + scale + online softmax ---
        float mx0 = -1e30f, mx1 = -1e30f;
#pragma unroll
        for (int nf = 0; nf < 8; nf++) {
#pragma unroll
            for (int e = 0; e < 4; e++) {
                int col = nf * 8 + c0 + (e & 1);
                int kpos = kbase + col;
                int qp = (e < 2) ? qp0 : qp1;
                bool ok = (col < kcnt) && (kpos <= qp) &&
                          ((kpos >= qp - (WINDOW_ - 1)) || (kpos < NMETA_));
                float v = ok ? s[nf][e] * scale : -1e30f;
                s[nf][e] = v;
                if (e < 2) mx0 = fmaxf(mx0, v); else mx1 = fmaxf(mx1, v);
            }
        }
        mx0 = fmaxf(mx0, __shfl_xor_sync(0xffffffffu, mx0, 1));
        mx0 = fmaxf(mx0, __shfl_xor_sync(0xffffffffu, mx0, 2));
        mx1 = fmaxf(mx1, __shfl_xor_sync(0xffffffffu, mx1, 1));
        mx1 = fmaxf(mx1, __shfl_xor_sync(0xffffffffu, mx1, 2));

        float mn0 = fmaxf(m0, mx0), mn1 = fmaxf(m1, mx1);
        float f0 = __expf(m0 - mn0), f1 = __expf(m1 - mn1);
        float rs0 = 0.f, rs1 = 0.f;
#pragma unroll
        for (int nf = 0; nf < 8; nf++) {
            float p0 = __expf(s[nf][0] - mn0);
            float p1 = __expf(s[nf][1] - mn0);
            float p2 = __expf(s[nf][2] - mn1);
            float p3 = __expf(s[nf][3] - mn1);
            s[nf][0] = p0; s[nf][1] = p1; s[nf][2] = p2; s[nf][3] = p3;
            rs0 += p0 + p1; rs1 += p2 + p3;
        }
        rs0 += __shfl_xor_sync(0xffffffffu, rs0, 1);
        rs0 += __shfl_xor_sync(0xffffffffu, rs0, 2);
        rs1 += __shfl_xor_sync(0xffffffffu, rs1, 1);
        rs1 += __shfl_xor_sync(0xffffffffu, rs1, 2);
        l0 = l0 * f0 + rs0; m0 = mn0;
        l1 = l1 * f1 + rs1; m1 = mn1;
#pragma unroll
        for (int nf = 0; nf < 16; nf++) {
            o[nf][0] *= f0; o[nf][1] *= f0;
            o[nf][2] *= f1; o[nf][3] *= f1;
        }

        // --- P @ V: A = P (registers, hi/lo split), B = VT smem ---
#pragma unroll
        for (int ks = 0; ks < 4; ks++) {
            u32 ph[4], pl[4];
            split2(s[2 * ks][0],     s[2 * ks][1],     ph[0], pl[0]);
            split2(s[2 * ks][2],     s[2 * ks][3],     ph[1], pl[1]);
            split2(s[2 * ks + 1][0], s[2 * ks + 1][1], ph[2], pl[2]);
            split2(s[2 * ks + 1][2], s[2 * ks + 1][3], ph[3], pl[3]);
            const int kk = ks * 16 + c0;
#pragma unroll
            for (int nf = 0; nf < 16; nf++) {
                int nr = nf * 8 + g;
                u32 bh2[2], bl2[2];
                bh2[0] = *(const u32*)&sm[VTH_OFF + nr * AT_VP + kk];
                bh2[1] = *(const u32*)&sm[VTH_OFF + nr * AT_VP + kk + 8];
                bl2[0] = *(const u32*)&sm[VTL_OFF + nr * AT_VP + kk];
                bl2[1] = *(const u32*)&sm[VTL_OFF + nr * AT_VP + kk + 8];
                mma16816(o[nf], ph, bh2);
                mma16816(o[nf], ph, bl2);
                mma16816(o[nf], pl, bh2);
            }
        }
    }

    // Epilogue: normalize, split to bf16 hi/lo, store y[b, q, h, :]
    float i0 = 1.0f / l0, i1 = 1.0f / l1;
    const int row0 = q0 + w * 16 + g;
#pragma unroll
    for (int nf = 0; nf < 16; nf++) {
        int col = nf * 8 + c0;
        size_t a0 = ((size_t)(b * S_ + row0) * NH_ + h) * HD_ + col;
        size_t a1 = ((size_t)(b * S_ + row0 + 8) * NH_ + h) * HD_ + col;
        u32 hh, ll;
        split2(o[nf][0] * i0, o[nf][1] * i0, hh, ll);
        *(u32*)(yh + a0) = hh;
        *(u32*)(yl + a0) = ll;
        split2(o[nf][2] * i1, o[nf][3] * i1, hh, ll);
        *(u32*)(yh + a1) = hh;
        *(u32*)(yl + a1) = ll;
    }
}

// ---------------------------------------------------------------------------
// Launch
// ---------------------------------------------------------------------------
extern "C" void kernel_launch(void* const* d_in, const int* in_sizes, int n_in,
                              void* d_out, int out_size)
{
    const float* x   = (const float*)d_in[0];
    const float* Wq  = (const float*)d_in[1];
    const float* bq  = (const float*)d_in[2];
    const float* Wkv = (const float*)d_in[3];
    const float* bkv = (const float*)d_in[4];
    const float* Wo  = (const float*)d_in[5];
    const float* bo  = (const float*)d_in[6];
    float* out = (float*)d_out;

    __nv_bfloat16 *xh, *xl, *qh, *ql, *kvh, *kvl, *yh, *yl;
    __nv_bfloat16 *wqh, *wql, *wkh, *wkl, *woh, *wol;
    float2* tab;
    cudaGetSymbolAddress((void**)&xh,  g_xh);
    cudaGetSymbolAddress((void**)&xl,  g_xl);
    cudaGetSymbolAddress((void**)&qh,  g_qh);
    cudaGetSymbolAddress((void**)&ql,  g_ql);
    cudaGetSymbolAddress((void**)&kvh, g_kvh);
    cudaGetSymbolAddress((void**)&kvl, g_kvl);
    cudaGetSymbolAddress((void**)&yh,  g_yh);
    cudaGetSymbolAddress((void**)&yl,  g_yl);
    cudaGetSymbolAddress((void**)&wqh, g_wqt_h);
    cudaGetSymbolAddress((void**)&wql, g_wqt_l);
    cudaGetSymbolAddress((void**)&wkh, g_wkvt_h);
    cudaGetSymbolAddress((void**)&wkl, g_wkvt_l);
    cudaGetSymbolAddress((void**)&woh, g_wot_h);
    cudaGetSymbolAddress((void**)&wol, g_wot_l);
    cudaGetSymbolAddress((void**)&tab, g_ropetab);

    const int M = B_ * S_;
    const int n4 = (B_ * S_ * E_) / 4;

    split_kernel<<<n4 / 256, 256>>>(x, xh, xl, n4);
    transpose_split<<<dim3(E_ / 32, E_ / 32), dim3(32, 8)>>>(Wq, wqh, wql, E_, E_);
    transpose_split<<<dim3(KVOUT_ / 32, E_ / 32), dim3(32, 8)>>>(Wkv, wkh, wkl, E_, KVOUT_);
    transpose_split<<<dim3(E_ / 32, E_ / 32), dim3(32, 8)>>>(Wo, woh, wol, E_, E_);
    rope_table_kernel<<<(S_ * 64) / 256, 256>>>(tab);

    cudaFuncSetAttribute(mma_gemm_kernel, cudaFuncAttributeMaxDynamicSharedMemorySize,
                         GT_SMEM);
    cudaFuncSetAttribute(attn_mma_kernel, cudaFuncAttributeMaxDynamicSharedMemorySize,
                         ATT_SMEM);

    // q = x @ Wq + bq  (+RoPE, bf16 hi/lo out)
    mma_gemm_kernel<<<dim3(E_ / 128, M / 128), 256, GT_SMEM>>>(
        xh, xl, wqh, wql, bq, nullptr, qh, ql, tab, M, E_, E_, 1, 1);
    // kv = x @ Wkv + bkv  (+RoPE on K half, bf16 hi/lo out)
    mma_gemm_kernel<<<dim3(KVOUT_ / 128, M / 128), 256, GT_SMEM>>>(
        xh, xl, wkh, wkl, bkv, nullptr, kvh, kvl, tab, M, KVOUT_, E_, 2, 1);

    // attention (tensor-core, bf16 hi/lo in & out)
    attn_mma_kernel<<<dim3(S_ / 64, B_ * NH_), 128, ATT_SMEM>>>(
        qh, ql, kvh, kvl, yh, yl);

    // out = y @ Wo + bo  (fp32 out)
    mma_gemm_kernel<<<dim3(E_ / 128, M / 128), 256, GT_SMEM>>>(
        yh, yl, woh, wol, bo, out, nullptr, nullptr, tab, M, E_, E_, 0, 0);
}

// round 5
// speedup vs baseline: 2.6763x; 1.3387x over previous
#include <cuda_runtime.h>
#include <cuda_bf16.h>
#include <math.h>

typedef unsigned int u32;

// Problem constants
#define B_      2
#define S_      4096
#define E_      2048
#define NH_     16
#define HD_     128
#define NKV_    4
#define KVOUT_  1024
#define WINDOW_ 512
#define NMETA_  16

// ---------------------------------------------------------------------------
// Scratch (device globals)
// ---------------------------------------------------------------------------
__device__ __nv_bfloat16 g_xh[B_ * S_ * E_];
__device__ __nv_bfloat16 g_xl[B_ * S_ * E_];
__device__ __nv_bfloat16 g_qh[B_ * S_ * E_];
__device__ __nv_bfloat16 g_ql[B_ * S_ * E_];
__device__ __nv_bfloat16 g_kvh[B_ * S_ * KVOUT_];
__device__ __nv_bfloat16 g_kvl[B_ * S_ * KVOUT_];
__device__ __nv_bfloat16 g_yh[B_ * S_ * E_];
__device__ __nv_bfloat16 g_yl[B_ * S_ * E_];
__device__ __nv_bfloat16 g_wqt_h[E_ * E_];
__device__ __nv_bfloat16 g_wqt_l[E_ * E_];
__device__ __nv_bfloat16 g_wkvt_h[KVOUT_ * E_];
__device__ __nv_bfloat16 g_wkvt_l[KVOUT_ * E_];
__device__ __nv_bfloat16 g_wot_h[E_ * E_];
__device__ __nv_bfloat16 g_wot_l[E_ * E_];
__device__ float2 g_ropetab[S_ * 64];

// ---------------------------------------------------------------------------
// Helpers
// ---------------------------------------------------------------------------
__device__ __forceinline__ u32 smem_u32(const void* p) {
    u32 a;
    asm("{ .reg .u64 t; cvta.to.shared.u64 t, %1; cvt.u32.u64 %0, t; }"
        : "=r"(a) : "l"(p));
    return a;
}

__device__ __forceinline__ void mma16816(float* d, const u32* a, const u32* b)
{
    asm volatile(
        "mma.sync.aligned.m16n8k16.row.col.f32.bf16.bf16.f32 "
        "{%0,%1,%2,%3}, {%4,%5,%6,%7}, {%8,%9}, {%0,%1,%2,%3};"
        : "+f"(d[0]), "+f"(d[1]), "+f"(d[2]), "+f"(d[3])
        : "r"(a[0]), "r"(a[1]), "r"(a[2]), "r"(a[3]), "r"(b[0]), "r"(b[1]));
}

__device__ __forceinline__ void ldsm_x4(u32* r, u32 addr)
{
    asm volatile("ldmatrix.sync.aligned.m8n8.x4.shared.b16 {%0,%1,%2,%3}, [%4];"
        : "=r"(r[0]), "=r"(r[1]), "=r"(r[2]), "=r"(r[3]) : "r"(addr));
}

__device__ __forceinline__ void ldsm_x4_t(u32* r, u32 addr)
{
    asm volatile("ldmatrix.sync.aligned.m8n8.x4.trans.shared.b16 {%0,%1,%2,%3}, [%4];"
        : "=r"(r[0]), "=r"(r[1]), "=r"(r[2]), "=r"(r[3]) : "r"(addr));
}

__device__ __forceinline__ void split2(float x, float y, u32& hh, u32& ll)
{
    __nv_bfloat16 hx = __float2bfloat16(x), hy = __float2bfloat16(y);
    __nv_bfloat162 hv(hx, hy);
    __nv_bfloat162 lv(__float2bfloat16(x - __bfloat162float(hx)),
                      __float2bfloat16(y - __bfloat162float(hy)));
    hh = *(u32*)&hv; ll = *(u32*)&lv;
}

// ---------------------------------------------------------------------------
// Prep kernels
// ---------------------------------------------------------------------------
__global__ void split_kernel(const float* __restrict__ in,
                             __nv_bfloat16* __restrict__ hi,
                             __nv_bfloat16* __restrict__ lo, int n4)
{
    int i = blockIdx.x * 256 + threadIdx.x;
    if (i >= n4) return;
    float4 v = ((const float4*)in)[i];
    __nv_bfloat16 h0 = __float2bfloat16(v.x), h1 = __float2bfloat16(v.y);
    __nv_bfloat16 h2 = __float2bfloat16(v.z), h3 = __float2bfloat16(v.w);
    __nv_bfloat162* H = (__nv_bfloat162*)hi;
    __nv_bfloat162* L = (__nv_bfloat162*)lo;
    H[i * 2]     = __nv_bfloat162(h0, h1);
    H[i * 2 + 1] = __nv_bfloat162(h2, h3);
    L[i * 2]     = __nv_bfloat162(__float2bfloat16(v.x - __bfloat162float(h0)),
                                  __float2bfloat16(v.y - __bfloat162float(h1)));
    L[i * 2 + 1] = __nv_bfloat162(__float2bfloat16(v.z - __bfloat162float(h2)),
                                  __float2bfloat16(v.w - __bfloat162float(h3)));
}

__global__ void transpose_split(const float* __restrict__ W,
                                __nv_bfloat16* __restrict__ Th,
                                __nv_bfloat16* __restrict__ Tl, int K, int N)
{
    __shared__ float t[32][33];
    int n0 = blockIdx.x * 32, k0 = blockIdx.y * 32;
    for (int i = threadIdx.y; i < 32; i += 8)
        t[i][threadIdx.x] = W[(size_t)(k0 + i) * N + n0 + threadIdx.x];
    __syncthreads();
    for (int i = threadIdx.y; i < 32; i += 8) {
        float v = t[threadIdx.x][i];
        size_t o = (size_t)(n0 + i) * K + k0 + threadIdx.x;
        __nv_bfloat16 h = __float2bfloat16(v);
        Th[o] = h;
        Tl[o] = __float2bfloat16(v - __bfloat162float(h));
    }
}

__global__ void rope_table_kernel(float2* tab)
{
    int idx = blockIdx.x * 256 + threadIdx.x;
    if (idx >= S_ * 64) return;
    int pos = idx >> 6, i = idx & 63;
    float inv = (float)exp(-(double)i * (9.210340371976184 / 64.0));
    float ang = (float)pos * inv;
    tab[idx] = make_float2(cosf(ang), sinf(ang));
}

// ---------------------------------------------------------------------------
// mma.sync bf16 GEMM, ldmatrix fragment loads.
// Block 128x128x32, 8 warps (2m x 4n), cp.async 2-stage.
// ---------------------------------------------------------------------------
#define BKP       40
#define TILE_ELEM (128 * BKP)
#define STAGE_ELEM (4 * TILE_ELEM)
#define GT_SMEM   (2 * STAGE_ELEM * 2)

#define CP_ASYNC16(dst, src) \
    asm volatile("cp.async.cg.shared.global [%0], [%1], 16;" :: "r"(dst), "l"(src))
#define CP_COMMIT() asm volatile("cp.async.commit_group;")
#define CP_WAIT1()  asm volatile("cp.async.wait_group 1;")
#define CP_WAIT0()  asm volatile("cp.async.wait_group 0;")

__global__ __launch_bounds__(256, 1) void mma_gemm_kernel(
    const __nv_bfloat16* __restrict__ Ahi, const __nv_bfloat16* __restrict__ Alo,
    const __nv_bfloat16* __restrict__ Bhi, const __nv_bfloat16* __restrict__ Blo,
    const float* __restrict__ bias, float* __restrict__ Cf,
    __nv_bfloat16* __restrict__ Ch, __nv_bfloat16* __restrict__ Cl,
    const float2* __restrict__ tab, int M, int N, int K,
    int rope_mode, int bf16_out)
{
    extern __shared__ __nv_bfloat16 sm[];
    const u32 sbase = smem_u32(sm);
    const int tid = threadIdx.x;
    const int wid = tid >> 5, lane = tid & 31;
    const int wm = wid & 1, wn = wid >> 1;
    const int m0 = blockIdx.y * 128;
    const int n0 = blockIdx.x * 128;
    const int g  = lane >> 2;
    const int c0 = (lane & 3) * 2;
    const int lrow = lane & 7, grp = lane >> 3;

    auto load_stage = [&](int c, int stage) {
        const int k0 = c * 32;
        const u32 sb = sbase + stage * STAGE_ELEM * 2;
#pragma unroll
        for (int i = 0; i < 2; i++) {
            int idx = tid + i * 256;
            int row = idx >> 2, quad = idx & 3;
            u32 soff = (u32)(row * BKP + quad * 8) * 2;
            size_t ga = (size_t)(m0 + row) * K + k0 + quad * 8;
            size_t gb = (size_t)(n0 + row) * K + k0 + quad * 8;
            CP_ASYNC16(sb + soff,                 (const char*)(Ahi + ga));
            CP_ASYNC16(sb + TILE_ELEM * 2 + soff, (const char*)(Alo + ga));
            CP_ASYNC16(sb + TILE_ELEM * 4 + soff, (const char*)(Bhi + gb));
            CP_ASYNC16(sb + TILE_ELEM * 6 + soff, (const char*)(Blo + gb));
        }
    };

    float acc[4][4][4];
#pragma unroll
    for (int i = 0; i < 4; i++)
#pragma unroll
        for (int j = 0; j < 4; j++)
#pragma unroll
            for (int e = 0; e < 4; e++) acc[i][j][e] = 0.f;

    const int nc = K >> 5;
    load_stage(0, 0);
    CP_COMMIT();

    for (int c = 0; c < nc; c++) {
        if (c + 1 < nc) {
            load_stage(c + 1, (c + 1) & 1);
            CP_COMMIT();
            CP_WAIT1();
        } else {
            CP_WAIT0();
        }
        __syncthreads();

        const u32 st  = sbase + (c & 1) * STAGE_ELEM * 2;
        const u32 sAh = st;
        const u32 sAl = st + TILE_ELEM * 2;
        const u32 sBh = st + TILE_ELEM * 4;
        const u32 sBl = st + TILE_ELEM * 6;

#pragma unroll
        for (int kh = 0; kh < 2; kh++) {
            const int kk = kh * 16;
            u32 bh[4][2], bl[4][2];
#pragma unroll
            for (int nfp = 0; nfp < 2; nfp++) {
                u32 off = (u32)((wn * 32 + nfp * 16 + (grp >> 1) * 8 + lrow) * BKP
                                + kk + (grp & 1) * 8) * 2;
                ldsm_x4(&bh[nfp * 2][0], sBh + off);
                ldsm_x4(&bl[nfp * 2][0], sBl + off);
            }
#pragma unroll
            for (int mf = 0; mf < 4; mf++) {
                u32 offa = (u32)((wm * 64 + mf * 16 + (grp & 1) * 8 + lrow) * BKP
                                 + kk + (grp >> 1) * 8) * 2;
                u32 ah[4], al[4];
                ldsm_x4(ah, sAh + offa);
                ldsm_x4(al, sAl + offa);
#pragma unroll
                for (int nf = 0; nf < 4; nf++) {
                    mma16816(acc[mf][nf], ah, bh[nf]);
                    mma16816(acc[mf][nf], ah, bl[nf]);
                    mma16816(acc[mf][nf], al, bh[nf]);
                }
            }
        }
        __syncthreads();
    }

    // Epilogue
#pragma unroll
    for (int mf = 0; mf < 4; mf++) {
        int row0 = m0 + wm * 64 + mf * 16 + g;
        int pos0 = row0 & (S_ - 1);
        int pos1 = (row0 + 8) & (S_ - 1);
#pragma unroll
        for (int nf = 0; nf < 4; nf++) {
            int col = n0 + wn * 32 + nf * 8 + c0;
            float b0 = bias[col], b1 = bias[col + 1];
            float v0 = acc[mf][nf][0] + b0, v1 = acc[mf][nf][1] + b1;
            float v2 = acc[mf][nf][2] + b0, v3 = acc[mf][nf][3] + b1;
            bool do_rope = (rope_mode == 1) || (rope_mode == 2 && col < 512);
            if (do_rope) {
                int ti = (col & 127) >> 1;
                float2 cs0 = tab[pos0 * 64 + ti];
                float2 cs1 = tab[pos1 * 64 + ti];
                float t0 = v0, t1 = v1;
                v0 = t0 * cs0.x - t1 * cs0.y;
                v1 = t1 * cs0.x + t0 * cs0.y;
                float t2 = v2, t3 = v3;
                v2 = t2 * cs1.x - t3 * cs1.y;
                v3 = t3 * cs1.x + t2 * cs1.y;
            }
            if (!bf16_out) {
                *(float2*)(Cf + (size_t)row0 * N + col)       = make_float2(v0, v1);
                *(float2*)(Cf + (size_t)(row0 + 8) * N + col) = make_float2(v2, v3);
            } else {
                u32 hh, ll;
                split2(v0, v1, hh, ll);
                *(u32*)(Ch + (size_t)row0 * N + col) = hh;
                *(u32*)(Cl + (size_t)row0 * N + col) = ll;
                split2(v2, v3, hh, ll);
                *(u32*)(Ch + (size_t)(row0 + 8) * N + col) = hh;
                *(u32*)(Cl + (size_t)(row0 + 8) * N + col) = ll;
            }
        }
    }
}

// ---------------------------------------------------------------------------
// Attention: mma.sync bf16, hi/lo 3-pass. Q fragments register-resident,
// K row-major (ldmatrix), V row-major (ldmatrix.trans).
// Block = 64 queries x one (b,h), 4 warps.
// smem: KH[64][136] KL VH VL  (Q staged through KH/KL before loop)
// ---------------------------------------------------------------------------
#define AT_BKP 136
#define KH_OFF 0
#define KL_OFF (64 * AT_BKP)
#define VH_OFF (2 * 64 * AT_BKP)
#define VL_OFF (3 * 64 * AT_BKP)
#define ATT_SMEM (4 * 64 * AT_BKP * 2)

__global__ __launch_bounds__(128, 2) void attn_mma_kernel(
    const __nv_bfloat16* __restrict__ qh, const __nv_bfloat16* __restrict__ ql,
    const __nv_bfloat16* __restrict__ kvh, const __nv_bfloat16* __restrict__ kvl,
    __nv_bfloat16* __restrict__ yh, __nv_bfloat16* __restrict__ yl)
{
    extern __shared__ __nv_bfloat16 sm[];
    const u32 smb = smem_u32(sm);
    const int tid = threadIdx.x;
    const int w = tid >> 5, lane = tid & 31;
    const int g = lane >> 2, c0 = (lane & 3) * 2;
    const int lrow = lane & 7, grp = lane >> 3;
    const int bhp = blockIdx.y;
    const int b = bhp >> 4, h = bhp & 15;
    const int kv_h = h >> 2;
    const int q0 = blockIdx.x << 6;
    const int qs = q0 & ~(WINDOW_ - 1);
    int ls = qs - WINDOW_ + 1; if (ls < NMETA_) ls = NMETA_;
    const int kend = q0 + 64;
    const float scale = 0.088388347648318447f;

    // Stage Q (hi/lo) into KH/KL regions, extract fragments to registers
#pragma unroll
    for (int it = 0; it < 8; it++) {
        int fi = tid + it * 128;
        int r = fi >> 4, q8 = fi & 15;
        size_t ga = ((size_t)(b * S_ + q0 + r) * NH_ + h) * HD_ + q8 * 8;
        *(uint4*)&sm[KH_OFF + r * AT_BKP + q8 * 8] = *(const uint4*)(qh + ga);
        *(uint4*)&sm[KL_OFF + r * AT_BKP + q8 * 8] = *(const uint4*)(ql + ga);
    }
    __syncthreads();

    u32 qfh[8][4], qfl[8][4];
#pragma unroll
    for (int ks = 0; ks < 8; ks++) {
        u32 off = (u32)((w * 16 + (grp & 1) * 8 + lrow) * AT_BKP
                        + ks * 16 + (grp >> 1) * 8) * 2;
        ldsm_x4(qfh[ks], smb + KH_OFF * 2 + off);
        ldsm_x4(qfl[ks], smb + KL_OFF * 2 + off);
    }

    float m0 = -1e30f, m1 = -1e30f, l0 = 0.f, l1 = 0.f;
    float o[16][4];
#pragma unroll
    for (int i = 0; i < 16; i++)
#pragma unroll
        for (int e = 0; e < 4; e++) o[i][e] = 0.f;

    const int qp0 = q0 + w * 16 + g;
    const int qp1 = qp0 + 8;
    const int nB = (kend - ls + 63) >> 6;

    for (int t = -1; t < nB; t++) {
        const int kbase = (t < 0) ? 0 : (ls + (t << 6));
        int kcnt = (t < 0) ? NMETA_ : (kend - kbase);
        if (kcnt > 64) kcnt = 64;

        __syncthreads();  // prior tile fully consumed (and Q ldmatrix done on 1st iter)
        // Load K and V tiles (row-major, hi/lo, zero-padded)
#pragma unroll
        for (int it = 0; it < 8; it++) {
            int fi = tid + it * 128;
            int r = fi >> 4, q8 = fi & 15;
            uint4 kh4 = make_uint4(0, 0, 0, 0), kl4 = kh4, vh4 = kh4, vl4 = kh4;
            if (r < kcnt) {
                size_t base = (size_t)(b * S_ + kbase + r) * 1024 + kv_h * 128 + q8 * 8;
                kh4 = *(const uint4*)(kvh + base);
                kl4 = *(const uint4*)(kvl + base);
                vh4 = *(const uint4*)(kvh + base + 512);
                vl4 = *(const uint4*)(kvl + base + 512);
            }
            int so = r * AT_BKP + q8 * 8;
            *(uint4*)&sm[KH_OFF + so] = kh4;
            *(uint4*)&sm[KL_OFF + so] = kl4;
            *(uint4*)&sm[VH_OFF + so] = vh4;
            *(uint4*)&sm[VL_OFF + so] = vl4;
        }
        __syncthreads();

        // --- QK^T: 3-pass hi/lo ---
        float s[8][4];
#pragma unroll
        for (int nf = 0; nf < 8; nf++)
#pragma unroll
            for (int e = 0; e < 4; e++) s[nf][e] = 0.f;

#pragma unroll
        for (int ks = 0; ks < 8; ks++) {
            const int kk = ks * 16;
#pragma unroll
            for (int nfp = 0; nfp < 4; nfp++) {
                u32 off = (u32)((nfp * 16 + (grp >> 1) * 8 + lrow) * AT_BKP
                                + kk + (grp & 1) * 8) * 2;
                u32 kh2[4], kl2[4];
                ldsm_x4(kh2, smb + KH_OFF * 2 + off);
                ldsm_x4(kl2, smb + KL_OFF * 2 + off);
                mma16816(s[2 * nfp],     qfh[ks], &kh2[0]);
                mma16816(s[2 * nfp],     qfh[ks], &kl2[0]);
                mma16816(s[2 * nfp],     qfl[ks], &kh2[0]);
                mma16816(s[2 * nfp + 1], qfh[ks], &kh2[2]);
                mma16816(s[2 * nfp + 1], qfh[ks], &kl2[2]);
                mma16816(s[2 * nfp + 1], qfl[ks], &kh2[2]);
            }
        }

        // --- Mask + scale + online softmax ---
        float mx0 = -1e30f, mx1 = -1e30f;
#pragma unroll
        for (int nf = 0; nf < 8; nf++) {
#pragma unroll
            for (int e = 0; e < 4; e++) {
                int col = nf * 8 + c0 + (e & 1);
                int kpos = kbase + col;
                int qp = (e < 2) ? qp0 : qp1;
                bool ok = (col < kcnt) && (kpos <= qp) &&
                          ((kpos >= qp - (WINDOW_ - 1)) || (kpos < NMETA_));
                float v = ok ? s[nf][e] * scale : -1e30f;
                s[nf][e] = v;
                if (e < 2) mx0 = fmaxf(mx0, v); else mx1 = fmaxf(mx1, v);
            }
        }
        mx0 = fmaxf(mx0, __shfl_xor_sync(0xffffffffu, mx0, 1));
        mx0 = fmaxf(mx0, __shfl_xor_sync(0xffffffffu, mx0, 2));
        mx1 = fmaxf(mx1, __shfl_xor_sync(0xffffffffu, mx1, 1));
        mx1 = fmaxf(mx1, __shfl_xor_sync(0xffffffffu, mx1, 2));

        float mn0 = fmaxf(m0, mx0), mn1 = fmaxf(m1, mx1);
        float f0 = __expf(m0 - mn0), f1 = __expf(m1 - mn1);
        float rs0 = 0.f, rs1 = 0.f;
#pragma unroll
        for (int nf = 0; nf < 8; nf++) {
            float p0 = __expf(s[nf][0] - mn0);
            float p1 = __expf(s[nf][1] - mn0);
            float p2 = __expf(s[nf][2] - mn1);
            float p3 = __expf(s[nf][3] - mn1);
            s[nf][0] = p0; s[nf][1] = p1; s[nf][2] = p2; s[nf][3] = p3;
            rs0 += p0 + p1; rs1 += p2 + p3;
        }
        rs0 += __shfl_xor_sync(0xffffffffu, rs0, 1);
        rs0 += __shfl_xor_sync(0xffffffffu, rs0, 2);
        rs1 += __shfl_xor_sync(0xffffffffu, rs1, 1);
        rs1 += __shfl_xor_sync(0xffffffffu, rs1, 2);
        l0 = l0 * f0 + rs0; m0 = mn0;
        l1 = l1 * f1 + rs1; m1 = mn1;
#pragma unroll
        for (int nf = 0; nf < 16; nf++) {
            o[nf][0] *= f0; o[nf][1] *= f0;
            o[nf][2] *= f1; o[nf][3] *= f1;
        }

        // --- P @ V: A = P (registers hi/lo), B = V via ldmatrix.trans ---
#pragma unroll
        for (int ks = 0; ks < 4; ks++) {
            u32 ph[4], pl[4];
            split2(s[2 * ks][0],     s[2 * ks][1],     ph[0], pl[0]);
            split2(s[2 * ks][2],     s[2 * ks][3],     ph[1], pl[1]);
            split2(s[2 * ks + 1][0], s[2 * ks + 1][1], ph[2], pl[2]);
            split2(s[2 * ks + 1][2], s[2 * ks + 1][3], ph[3], pl[3]);
            const int kk = ks * 16;
#pragma unroll
            for (int nfp = 0; nfp < 8; nfp++) {
                u32 off = (u32)((kk + (grp & 1) * 8 + lrow) * AT_BKP
                                + nfp * 16 + (grp >> 1) * 8) * 2;
                u32 vh2[4], vl2[4];
                ldsm_x4_t(vh2, smb + VH_OFF * 2 + off);
                ldsm_x4_t(vl2, smb + VL_OFF * 2 + off);
                mma16816(o[2 * nfp],     ph, &vh2[0]);
                mma16816(o[2 * nfp],     ph, &vl2[0]);
                mma16816(o[2 * nfp],     pl, &vh2[0]);
                mma16816(o[2 * nfp + 1], ph, &vh2[2]);
                mma16816(o[2 * nfp + 1], ph, &vl2[2]);
                mma16816(o[2 * nfp + 1], pl, &vh2[2]);
            }
        }
    }

    // Epilogue: normalize, split to bf16 hi/lo, store y[b, q, h, :]
    float i0 = 1.0f / l0, i1 = 1.0f / l1;
    const int row0 = q0 + w * 16 + g;
#pragma unroll
    for (int nf = 0; nf < 16; nf++) {
        int col = nf * 8 + c0;
        size_t a0 = ((size_t)(b * S_ + row0) * NH_ + h) * HD_ + col;
        size_t a1 = ((size_t)(b * S_ + row0 + 8) * NH_ + h) * HD_ + col;
        u32 hh, ll;
        split2(o[nf][0] * i0, o[nf][1] * i0, hh, ll);
        *(u32*)(yh + a0) = hh;
        *(u32*)(yl + a0) = ll;
        split2(o[nf][2] * i1, o[nf][3] * i1, hh, ll);
        *(u32*)(yh + a1) = hh;
        *(u32*)(yl + a1) = ll;
    }
}

// ---------------------------------------------------------------------------
// Launch
// ---------------------------------------------------------------------------
extern "C" void kernel_launch(void* const* d_in, const int* in_sizes, int n_in,
                              void* d_out, int out_size)
{
    const float* x   = (const float*)d_in[0];
    const float* Wq  = (const float*)d_in[1];
    const float* bq  = (const float*)d_in[2];
    const float* Wkv = (const float*)d_in[3];
    const float* bkv = (const float*)d_in[4];
    const float* Wo  = (const float*)d_in[5];
    const float* bo  = (const float*)d_in[6];
    float* out = (float*)d_out;

    __nv_bfloat16 *xh, *xl, *qh, *ql, *kvh, *kvl, *yh, *yl;
    __nv_bfloat16 *wqh, *wql, *wkh, *wkl, *woh, *wol;
    float2* tab;
    cudaGetSymbolAddress((void**)&xh,  g_xh);
    cudaGetSymbolAddress((void**)&xl,  g_xl);
    cudaGetSymbolAddress((void**)&qh,  g_qh);
    cudaGetSymbolAddress((void**)&ql,  g_ql);
    cudaGetSymbolAddress((void**)&kvh, g_kvh);
    cudaGetSymbolAddress((void**)&kvl, g_kvl);
    cudaGetSymbolAddress((void**)&yh,  g_yh);
    cudaGetSymbolAddress((void**)&yl,  g_yl);
    cudaGetSymbolAddress((void**)&wqh, g_wqt_h);
    cudaGetSymbolAddress((void**)&wql, g_wqt_l);
    cudaGetSymbolAddress((void**)&wkh, g_wkvt_h);
    cudaGetSymbolAddress((void**)&wkl, g_wkvt_l);
    cudaGetSymbolAddress((void**)&woh, g_wot_h);
    cudaGetSymbolAddress((void**)&wol, g_wot_l);
    cudaGetSymbolAddress((void**)&tab, g_ropetab);

    const int M = B_ * S_;
    const int n4 = (B_ * S_ * E_) / 4;

    split_kernel<<<n4 / 256, 256>>>(x, xh, xl, n4);
    transpose_split<<<dim3(E_ / 32, E_ / 32), dim3(32, 8)>>>(Wq, wqh, wql, E_, E_);
    transpose_split<<<dim3(KVOUT_ / 32, E_ / 32), dim3(32, 8)>>>(Wkv, wkh, wkl, E_, KVOUT_);
    transpose_split<<<dim3(E_ / 32, E_ / 32), dim3(32, 8)>>>(Wo, woh, wol, E_, E_);
    rope_table_kernel<<<(S_ * 64) / 256, 256>>>(tab);

    cudaFuncSetAttribute(mma_gemm_kernel, cudaFuncAttributeMaxDynamicSharedMemorySize,
                         GT_SMEM);
    cudaFuncSetAttribute(attn_mma_kernel, cudaFuncAttributeMaxDynamicSharedMemorySize,
                         ATT_SMEM);

    // q = x @ Wq + bq  (+RoPE, bf16 hi/lo out)
    mma_gemm_kernel<<<dim3(E_ / 128, M / 128), 256, GT_SMEM>>>(
        xh, xl, wqh, wql, bq, nullptr, qh, ql, tab, M, E_, E_, 1, 1);
    // kv = x @ Wkv + bkv  (+RoPE on K half, bf16 hi/lo out)
    mma_gemm_kernel<<<dim3(KVOUT_ / 128, M / 128), 256, GT_SMEM>>>(
        xh, xl, wkh, wkl, bkv, nullptr, kvh, kvl, tab, M, KVOUT_, E_, 2, 1);

    // attention (tensor-core, bf16 hi/lo in & out)
    attn_mma_kernel<<<dim3(S_ / 64, B_ * NH_), 128, ATT_SMEM>>>(
        qh, ql, kvh, kvl, yh, yl);

    // out = y @ Wo + bo  (fp32 out)
    mma_gemm_kernel<<<dim3(E_ / 128, M / 128), 256, GT_SMEM>>>(
        yh, yl, woh, wol, bo, out, nullptr, nullptr, tab, M, E_, E_, 0, 0);
}

// round 6
// speedup vs baseline: 3.2571x; 1.2170x over previous
#include <cuda_runtime.h>
#include <cuda_bf16.h>
#include <math.h>

typedef unsigned int u32;

// Problem constants
#define B_      2
#define S_      4096
#define E_      2048
#define NH_     16
#define HD_     128
#define NKV_    4
#define KVOUT_  1024
#define WINDOW_ 512
#define NMETA_  16

// ---------------------------------------------------------------------------
// Scratch (device globals)
// ---------------------------------------------------------------------------
__device__ __nv_bfloat16 g_xh[B_ * S_ * E_];
__device__ __nv_bfloat16 g_xl[B_ * S_ * E_];
__device__ __nv_bfloat16 g_qh[B_ * S_ * E_];
__device__ __nv_bfloat16 g_ql[B_ * S_ * E_];
__device__ __nv_bfloat16 g_kvh[B_ * S_ * KVOUT_];
__device__ __nv_bfloat16 g_kvl[B_ * S_ * KVOUT_];
__device__ __nv_bfloat16 g_yh[B_ * S_ * E_];
__device__ __nv_bfloat16 g_yl[B_ * S_ * E_];
__device__ __nv_bfloat16 g_wqt_h[E_ * E_];
__device__ __nv_bfloat16 g_wqt_l[E_ * E_];
__device__ __nv_bfloat16 g_wkvt_h[KVOUT_ * E_];
__device__ __nv_bfloat16 g_wkvt_l[KVOUT_ * E_];
__device__ __nv_bfloat16 g_wot_h[E_ * E_];
__device__ __nv_bfloat16 g_wot_l[E_ * E_];
__device__ float2 g_ropetab[S_ * 64];

// ---------------------------------------------------------------------------
// Helpers
// ---------------------------------------------------------------------------
__device__ __forceinline__ u32 smem_u32(const void* p) {
    u32 a;
    asm("{ .reg .u64 t; cvta.to.shared.u64 t, %1; cvt.u32.u64 %0, t; }"
        : "=r"(a) : "l"(p));
    return a;
}

__device__ __forceinline__ void mma16816(float* d, const u32* a, const u32* b)
{
    asm volatile(
        "mma.sync.aligned.m16n8k16.row.col.f32.bf16.bf16.f32 "
        "{%0,%1,%2,%3}, {%4,%5,%6,%7}, {%8,%9}, {%0,%1,%2,%3};"
        : "+f"(d[0]), "+f"(d[1]), "+f"(d[2]), "+f"(d[3])
        : "r"(a[0]), "r"(a[1]), "r"(a[2]), "r"(a[3]), "r"(b[0]), "r"(b[1]));
}

__device__ __forceinline__ void ldsm_x4(u32* r, u32 addr)
{
    asm volatile("ldmatrix.sync.aligned.m8n8.x4.shared.b16 {%0,%1,%2,%3}, [%4];"
        : "=r"(r[0]), "=r"(r[1]), "=r"(r[2]), "=r"(r[3]) : "r"(addr));
}

__device__ __forceinline__ void ldsm_x4_t(u32* r, u32 addr)
{
    asm volatile("ldmatrix.sync.aligned.m8n8.x4.trans.shared.b16 {%0,%1,%2,%3}, [%4];"
        : "=r"(r[0]), "=r"(r[1]), "=r"(r[2]), "=r"(r[3]) : "r"(addr));
}

__device__ __forceinline__ void split2(float x, float y, u32& hh, u32& ll)
{
    __nv_bfloat16 hx = __float2bfloat16(x), hy = __float2bfloat16(y);
    __nv_bfloat162 hv(hx, hy);
    __nv_bfloat162 lv(__float2bfloat16(x - __bfloat162float(hx)),
                      __float2bfloat16(y - __bfloat162float(hy)));
    hh = *(u32*)&hv; ll = *(u32*)&lv;
}

// ---------------------------------------------------------------------------
// Prep kernels
// ---------------------------------------------------------------------------
__global__ void split_kernel(const float* __restrict__ in,
                             __nv_bfloat16* __restrict__ hi,
                             __nv_bfloat16* __restrict__ lo, int n4)
{
    int i = blockIdx.x * 256 + threadIdx.x;
    if (i >= n4) return;
    float4 v = ((const float4*)in)[i];
    __nv_bfloat16 h0 = __float2bfloat16(v.x), h1 = __float2bfloat16(v.y);
    __nv_bfloat16 h2 = __float2bfloat16(v.z), h3 = __float2bfloat16(v.w);
    __nv_bfloat162* H = (__nv_bfloat162*)hi;
    __nv_bfloat162* L = (__nv_bfloat162*)lo;
    H[i * 2]     = __nv_bfloat162(h0, h1);
    H[i * 2 + 1] = __nv_bfloat162(h2, h3);
    L[i * 2]     = __nv_bfloat162(__float2bfloat16(v.x - __bfloat162float(h0)),
                                  __float2bfloat16(v.y - __bfloat162float(h1)));
    L[i * 2 + 1] = __nv_bfloat162(__float2bfloat16(v.z - __bfloat162float(h2)),
                                  __float2bfloat16(v.w - __bfloat162float(h3)));
}

__global__ void transpose_split(const float* __restrict__ W,
                                __nv_bfloat16* __restrict__ Th,
                                __nv_bfloat16* __restrict__ Tl, int K, int N)
{
    __shared__ float t[32][33];
    int n0 = blockIdx.x * 32, k0 = blockIdx.y * 32;
    for (int i = threadIdx.y; i < 32; i += 8)
        t[i][threadIdx.x] = W[(size_t)(k0 + i) * N + n0 + threadIdx.x];
    __syncthreads();
    for (int i = threadIdx.y; i < 32; i += 8) {
        float v = t[threadIdx.x][i];
        size_t o = (size_t)(n0 + i) * K + k0 + threadIdx.x;
        __nv_bfloat16 h = __float2bfloat16(v);
        Th[o] = h;
        Tl[o] = __float2bfloat16(v - __bfloat162float(h));
    }
}

__global__ void rope_table_kernel(float2* tab)
{
    int idx = blockIdx.x * 256 + threadIdx.x;
    if (idx >= S_ * 64) return;
    int pos = idx >> 6, i = idx & 63;
    float inv = (float)exp(-(double)i * (9.210340371976184 / 64.0));
    float ang = (float)pos * inv;
    tab[idx] = make_float2(cosf(ang), sinf(ang));
}

// ---------------------------------------------------------------------------
// mma.sync bf16 GEMM, ldmatrix fragment loads.
// Block 128x128x32, 8 warps (2m x 4n), cp.async 2-stage, 2 CTAs/SM.
// ---------------------------------------------------------------------------
#define BKP       40
#define TILE_ELEM (128 * BKP)
#define STAGE_ELEM (4 * TILE_ELEM)
#define GT_SMEM   (2 * STAGE_ELEM * 2)

#define CP_ASYNC16(dst, src) \
    asm volatile("cp.async.cg.shared.global [%0], [%1], 16;" :: "r"(dst), "l"(src))
#define CP_COMMIT() asm volatile("cp.async.commit_group;")
#define CP_WAIT1()  asm volatile("cp.async.wait_group 1;")
#define CP_WAIT0()  asm volatile("cp.async.wait_group 0;")

__global__ __launch_bounds__(256, 2) void mma_gemm_kernel(
    const __nv_bfloat16* __restrict__ Ahi, const __nv_bfloat16* __restrict__ Alo,
    const __nv_bfloat16* __restrict__ Bhi, const __nv_bfloat16* __restrict__ Blo,
    const float* __restrict__ bias, float* __restrict__ Cf,
    __nv_bfloat16* __restrict__ Ch, __nv_bfloat16* __restrict__ Cl,
    const float2* __restrict__ tab, int M, int N, int K,
    int rope_mode, int bf16_out)
{
    extern __shared__ __nv_bfloat16 sm[];
    const u32 sbase = smem_u32(sm);
    const int tid = threadIdx.x;
    const int wid = tid >> 5, lane = tid & 31;
    const int wm = wid & 1, wn = wid >> 1;
    const int m0 = blockIdx.y * 128;
    const int n0 = blockIdx.x * 128;
    const int g  = lane >> 2;
    const int c0 = (lane & 3) * 2;
    const int lrow = lane & 7, grp = lane >> 3;

    auto load_stage = [&](int c, int stage) {
        const int k0 = c * 32;
        const u32 sb = sbase + stage * STAGE_ELEM * 2;
#pragma unroll
        for (int i = 0; i < 2; i++) {
            int idx = tid + i * 256;
            int row = idx >> 2, quad = idx & 3;
            u32 soff = (u32)(row * BKP + quad * 8) * 2;
            size_t ga = (size_t)(m0 + row) * K + k0 + quad * 8;
            size_t gb = (size_t)(n0 + row) * K + k0 + quad * 8;
            CP_ASYNC16(sb + soff,                 (const char*)(Ahi + ga));
            CP_ASYNC16(sb + TILE_ELEM * 2 + soff, (const char*)(Alo + ga));
            CP_ASYNC16(sb + TILE_ELEM * 4 + soff, (const char*)(Bhi + gb));
            CP_ASYNC16(sb + TILE_ELEM * 6 + soff, (const char*)(Blo + gb));
        }
    };

    float acc[4][4][4];
#pragma unroll
    for (int i = 0; i < 4; i++)
#pragma unroll
        for (int j = 0; j < 4; j++)
#pragma unroll
            for (int e = 0; e < 4; e++) acc[i][j][e] = 0.f;

    const int nc = K >> 5;
    load_stage(0, 0);
    CP_COMMIT();

    for (int c = 0; c < nc; c++) {
        if (c + 1 < nc) {
            load_stage(c + 1, (c + 1) & 1);
            CP_COMMIT();
            CP_WAIT1();
        } else {
            CP_WAIT0();
        }
        __syncthreads();

        const u32 st  = sbase + (c & 1) * STAGE_ELEM * 2;
        const u32 sAh = st;
        const u32 sAl = st + TILE_ELEM * 2;
        const u32 sBh = st + TILE_ELEM * 4;
        const u32 sBl = st + TILE_ELEM * 6;

#pragma unroll
        for (int kh = 0; kh < 2; kh++) {
            const int kk = kh * 16;
            u32 bh[4][2], bl[4][2];
#pragma unroll
            for (int nfp = 0; nfp < 2; nfp++) {
                u32 off = (u32)((wn * 32 + nfp * 16 + (grp >> 1) * 8 + lrow) * BKP
                                + kk + (grp & 1) * 8) * 2;
                ldsm_x4(&bh[nfp * 2][0], sBh + off);
                ldsm_x4(&bl[nfp * 2][0], sBl + off);
            }
#pragma unroll
            for (int mf = 0; mf < 4; mf++) {
                u32 offa = (u32)((wm * 64 + mf * 16 + (grp & 1) * 8 + lrow) * BKP
                                 + kk + (grp >> 1) * 8) * 2;
                u32 ah[4], al[4];
                ldsm_x4(ah, sAh + offa);
                ldsm_x4(al, sAl + offa);
#pragma unroll
                for (int nf = 0; nf < 4; nf++) {
                    mma16816(acc[mf][nf], ah, bh[nf]);
                    mma16816(acc[mf][nf], ah, bl[nf]);
                    mma16816(acc[mf][nf], al, bh[nf]);
                }
            }
        }
        __syncthreads();
    }

    // Epilogue
#pragma unroll
    for (int mf = 0; mf < 4; mf++) {
        int row0 = m0 + wm * 64 + mf * 16 + g;
        int pos0 = row0 & (S_ - 1);
        int pos1 = (row0 + 8) & (S_ - 1);
#pragma unroll
        for (int nf = 0; nf < 4; nf++) {
            int col = n0 + wn * 32 + nf * 8 + c0;
            float b0 = bias[col], b1 = bias[col + 1];
            float v0 = acc[mf][nf][0] + b0, v1 = acc[mf][nf][1] + b1;
            float v2 = acc[mf][nf][2] + b0, v3 = acc[mf][nf][3] + b1;
            bool do_rope = (rope_mode == 1) || (rope_mode == 2 && col < 512);
            if (do_rope) {
                int ti = (col & 127) >> 1;
                float2 cs0 = tab[pos0 * 64 + ti];
                float2 cs1 = tab[pos1 * 64 + ti];
                float t0 = v0, t1 = v1;
                v0 = t0 * cs0.x - t1 * cs0.y;
                v1 = t1 * cs0.x + t0 * cs0.y;
                float t2 = v2, t3 = v3;
                v2 = t2 * cs1.x - t3 * cs1.y;
                v3 = t3 * cs1.x + t2 * cs1.y;
            }
            if (!bf16_out) {
                *(float2*)(Cf + (size_t)row0 * N + col)       = make_float2(v0, v1);
                *(float2*)(Cf + (size_t)(row0 + 8) * N + col) = make_float2(v2, v3);
            } else {
                u32 hh, ll;
                split2(v0, v1, hh, ll);
                *(u32*)(Ch + (size_t)row0 * N + col) = hh;
                *(u32*)(Cl + (size_t)row0 * N + col) = ll;
                split2(v2, v3, hh, ll);
                *(u32*)(Ch + (size_t)(row0 + 8) * N + col) = hh;
                *(u32*)(Cl + (size_t)(row0 + 8) * N + col) = ll;
            }
        }
    }
}

// ---------------------------------------------------------------------------
// Attention: mma.sync bf16, hi/lo 3-pass. Q fragments register-resident.
// Key range starts at max(NMETA, q0-511): tiles fully below the window for
// ALL queries in the block are skipped (identical mask => identical output).
// ---------------------------------------------------------------------------
#define AT_BKP 136
#define KH_OFF 0
#define KL_OFF (64 * AT_BKP)
#define VH_OFF (2 * 64 * AT_BKP)
#define VL_OFF (3 * 64 * AT_BKP)
#define ATT_SMEM (4 * 64 * AT_BKP * 2)

__global__ __launch_bounds__(128, 2) void attn_mma_kernel(
    const __nv_bfloat16* __restrict__ qh, const __nv_bfloat16* __restrict__ ql,
    const __nv_bfloat16* __restrict__ kvh, const __nv_bfloat16* __restrict__ kvl,
    __nv_bfloat16* __restrict__ yh, __nv_bfloat16* __restrict__ yl)
{
    extern __shared__ __nv_bfloat16 sm[];
    const u32 smb = smem_u32(sm);
    const int tid = threadIdx.x;
    const int w = tid >> 5, lane = tid & 31;
    const int g = lane >> 2, c0 = (lane & 3) * 2;
    const int lrow = lane & 7, grp = lane >> 3;
    const int bhp = blockIdx.y;
    const int b = bhp >> 4, h = bhp & 15;
    const int kv_h = h >> 2;
    const int q0 = blockIdx.x << 6;
    // Earliest key any query in this block can see (non-meta): q0 - 511
    int ls = q0 - WINDOW_ + 1; if (ls < NMETA_) ls = NMETA_;
    const int kend = q0 + 64;
    const float scale = 0.088388347648318447f;

    // Stage Q (hi/lo) into KH/KL regions, extract fragments to registers
#pragma unroll
    for (int it = 0; it < 8; it++) {
        int fi = tid + it * 128;
        int r = fi >> 4, q8 = fi & 15;
        size_t ga = ((size_t)(b * S_ + q0 + r) * NH_ + h) * HD_ + q8 * 8;
        *(uint4*)&sm[KH_OFF + r * AT_BKP + q8 * 8] = *(const uint4*)(qh + ga);
        *(uint4*)&sm[KL_OFF + r * AT_BKP + q8 * 8] = *(const uint4*)(ql + ga);
    }
    __syncthreads();

    u32 qfh[8][4], qfl[8][4];
#pragma unroll
    for (int ks = 0; ks < 8; ks++) {
        u32 off = (u32)((w * 16 + (grp & 1) * 8 + lrow) * AT_BKP
                        + ks * 16 + (grp >> 1) * 8) * 2;
        ldsm_x4(qfh[ks], smb + KH_OFF * 2 + off);
        ldsm_x4(qfl[ks], smb + KL_OFF * 2 + off);
    }

    float m0 = -1e30f, m1 = -1e30f, l0 = 0.f, l1 = 0.f;
    float o[16][4];
#pragma unroll
    for (int i = 0; i < 16; i++)
#pragma unroll
        for (int e = 0; e < 4; e++) o[i][e] = 0.f;

    const int qp0 = q0 + w * 16 + g;
    const int qp1 = qp0 + 8;
    const int nB = (kend - ls + 63) >> 6;

    for (int t = -1; t < nB; t++) {
        const int kbase = (t < 0) ? 0 : (ls + (t << 6));
        int kcnt = (t < 0) ? NMETA_ : (kend - kbase);
        if (kcnt > 64) kcnt = 64;

        __syncthreads();
#pragma unroll
        for (int it = 0; it < 8; it++) {
            int fi = tid + it * 128;
            int r = fi >> 4, q8 = fi & 15;
            uint4 kh4 = make_uint4(0, 0, 0, 0), kl4 = kh4, vh4 = kh4, vl4 = kh4;
            if (r < kcnt) {
                size_t base = (size_t)(b * S_ + kbase + r) * 1024 + kv_h * 128 + q8 * 8;
                kh4 = *(const uint4*)(kvh + base);
                kl4 = *(const uint4*)(kvl + base);
                vh4 = *(const uint4*)(kvh + base + 512);
                vl4 = *(const uint4*)(kvl + base + 512);
            }
            int so = r * AT_BKP + q8 * 8;
            *(uint4*)&sm[KH_OFF + so] = kh4;
            *(uint4*)&sm[KL_OFF + so] = kl4;
            *(uint4*)&sm[VH_OFF + so] = vh4;
            *(uint4*)&sm[VL_OFF + so] = vl4;
        }
        __syncthreads();

        // --- QK^T: 3-pass hi/lo ---
        float s[8][4];
#pragma unroll
        for (int nf = 0; nf < 8; nf++)
#pragma unroll
            for (int e = 0; e < 4; e++) s[nf][e] = 0.f;

#pragma unroll
        for (int ks = 0; ks < 8; ks++) {
            const int kk = ks * 16;
#pragma unroll
            for (int nfp = 0; nfp < 4; nfp++) {
                u32 off = (u32)((nfp * 16 + (grp >> 1) * 8 + lrow) * AT_BKP
                                + kk + (grp & 1) * 8) * 2;
                u32 kh2[4], kl2[4];
                ldsm_x4(kh2, smb + KH_OFF * 2 + off);
                ldsm_x4(kl2, smb + KL_OFF * 2 + off);
                mma16816(s[2 * nfp],     qfh[ks], &kh2[0]);
                mma16816(s[2 * nfp],     qfh[ks], &kl2[0]);
                mma16816(s[2 * nfp],     qfl[ks], &kh2[0]);
                mma16816(s[2 * nfp + 1], qfh[ks], &kh2[2]);
                mma16816(s[2 * nfp + 1], qfh[ks], &kl2[2]);
                mma16816(s[2 * nfp + 1], qfl[ks], &kh2[2]);
            }
        }

        // --- Mask + scale + online softmax ---
        float mx0 = -1e30f, mx1 = -1e30f;
#pragma unroll
        for (int nf = 0; nf < 8; nf++) {
#pragma unroll
            for (int e = 0; e < 4; e++) {
                int col = nf * 8 + c0 + (e & 1);
                int kpos = kbase + col;
                int qp = (e < 2) ? qp0 : qp1;
                bool ok = (col < kcnt) && (kpos <= qp) &&
                          ((kpos >= qp - (WINDOW_ - 1)) || (kpos < NMETA_));
                float v = ok ? s[nf][e] * scale : -1e30f;
                s[nf][e] = v;
                if (e < 2) mx0 = fmaxf(mx0, v); else mx1 = fmaxf(mx1, v);
            }
        }
        mx0 = fmaxf(mx0, __shfl_xor_sync(0xffffffffu, mx0, 1));
        mx0 = fmaxf(mx0, __shfl_xor_sync(0xffffffffu, mx0, 2));
        mx1 = fmaxf(mx1, __shfl_xor_sync(0xffffffffu, mx1, 1));
        mx1 = fmaxf(mx1, __shfl_xor_sync(0xffffffffu, mx1, 2));

        float mn0 = fmaxf(m0, mx0), mn1 = fmaxf(m1, mx1);
        float f0 = __expf(m0 - mn0), f1 = __expf(m1 - mn1);
        float rs0 = 0.f, rs1 = 0.f;
#pragma unroll
        for (int nf = 0; nf < 8; nf++) {
            float p0 = __expf(s[nf][0] - mn0);
            float p1 = __expf(s[nf][1] - mn0);
            float p2 = __expf(s[nf][2] - mn1);
            float p3 = __expf(s[nf][3] - mn1);
            s[nf][0] = p0; s[nf][1] = p1; s[nf][2] = p2; s[nf][3] = p3;
            rs0 += p0 + p1; rs1 += p2 + p3;
        }
        rs0 += __shfl_xor_sync(0xffffffffu, rs0, 1);
        rs0 += __shfl_xor_sync(0xffffffffu, rs0, 2);
        rs1 += __shfl_xor_sync(0xffffffffu, rs1, 1);
        rs1 += __shfl_xor_sync(0xffffffffu, rs1, 2);
        l0 = l0 * f0 + rs0; m0 = mn0;
        l1 = l1 * f1 + rs1; m1 = mn1;
#pragma unroll
        for (int nf = 0; nf < 16; nf++) {
            o[nf][0] *= f0; o[nf][1] *= f0;
            o[nf][2] *= f1; o[nf][3] *= f1;
        }

        // --- P @ V: A = P (registers hi/lo), B = V via ldmatrix.trans ---
#pragma unroll
        for (int ks = 0; ks < 4; ks++) {
            u32 ph[4], pl[4];
            split2(s[2 * ks][0],     s[2 * ks][1],     ph[0], pl[0]);
            split2(s[2 * ks][2],     s[2 * ks][3],     ph[1], pl[1]);
            split2(s[2 * ks + 1][0], s[2 * ks + 1][1], ph[2], pl[2]);
            split2(s[2 * ks + 1][2], s[2 * ks + 1][3], ph[3], pl[3]);
            const int kk = ks * 16;
#pragma unroll
            for (int nfp = 0; nfp < 8; nfp++) {
                u32 off = (u32)((kk + (grp & 1) * 8 + lrow) * AT_BKP
                                + nfp * 16 + (grp >> 1) * 8) * 2;
                u32 vh2[4], vl2[4];
                ldsm_x4_t(vh2, smb + VH_OFF * 2 + off);
                ldsm_x4_t(vl2, smb + VL_OFF * 2 + off);
                mma16816(o[2 * nfp],     ph, &vh2[0]);
                mma16816(o[2 * nfp],     ph, &vl2[0]);
                mma16816(o[2 * nfp],     pl, &vh2[0]);
                mma16816(o[2 * nfp + 1], ph, &vh2[2]);
                mma16816(o[2 * nfp + 1], ph, &vl2[2]);
                mma16816(o[2 * nfp + 1], pl, &vh2[2]);
            }
        }
    }

    // Epilogue: normalize, split to bf16 hi/lo, store y[b, q, h, :]
    float i0 = 1.0f / l0, i1 = 1.0f / l1;
    const int row0 = q0 + w * 16 + g;
#pragma unroll
    for (int nf = 0; nf < 16; nf++) {
        int col = nf * 8 + c0;
        size_t a0 = ((size_t)(b * S_ + row0) * NH_ + h) * HD_ + col;
        size_t a1 = ((size_t)(b * S_ + row0 + 8) * NH_ + h) * HD_ + col;
        u32 hh, ll;
        split2(o[nf][0] * i0, o[nf][1] * i0, hh, ll);
        *(u32*)(yh + a0) = hh;
        *(u32*)(yl + a0) = ll;
        split2(o[nf][2] * i1, o[nf][3] * i1, hh, ll);
        *(u32*)(yh + a1) = hh;
        *(u32*)(yl + a1) = ll;
    }
}

// ---------------------------------------------------------------------------
// Launch
// ---------------------------------------------------------------------------
extern "C" void kernel_launch(void* const* d_in, const int* in_sizes, int n_in,
                              void* d_out, int out_size)
{
    const float* x   = (const float*)d_in[0];
    const float* Wq  = (const float*)d_in[1];
    const float* bq  = (const float*)d_in[2];
    const float* Wkv = (const float*)d_in[3];
    const float* bkv = (const float*)d_in[4];
    const float* Wo  = (const float*)d_in[5];
    const float* bo  = (const float*)d_in[6];
    float* out = (float*)d_out;

    __nv_bfloat16 *xh, *xl, *qh, *ql, *kvh, *kvl, *yh, *yl;
    __nv_bfloat16 *wqh, *wql, *wkh, *wkl, *woh, *wol;
    float2* tab;
    cudaGetSymbolAddress((void**)&xh,  g_xh);
    cudaGetSymbolAddress((void**)&xl,  g_xl);
    cudaGetSymbolAddress((void**)&qh,  g_qh);
    cudaGetSymbolAddress((void**)&ql,  g_ql);
    cudaGetSymbolAddress((void**)&kvh, g_kvh);
    cudaGetSymbolAddress((void**)&kvl, g_kvl);
    cudaGetSymbolAddress((void**)&yh,  g_yh);
    cudaGetSymbolAddress((void**)&yl,  g_yl);
    cudaGetSymbolAddress((void**)&wqh, g_wqt_h);
    cudaGetSymbolAddress((void**)&wql, g_wqt_l);
    cudaGetSymbolAddress((void**)&wkh, g_wkvt_h);
    cudaGetSymbolAddress((void**)&wkl, g_wkvt_l);
    cudaGetSymbolAddress((void**)&woh, g_wot_h);
    cudaGetSymbolAddress((void**)&wol, g_wot_l);
    cudaGetSymbolAddress((void**)&tab, g_ropetab);

    const int M = B_ * S_;
    const int n4 = (B_ * S_ * E_) / 4;

    split_kernel<<<n4 / 256, 256>>>(x, xh, xl, n4);
    transpose_split<<<dim3(E_ / 32, E_ / 32), dim3(32, 8)>>>(Wq, wqh, wql, E_, E_);
    transpose_split<<<dim3(KVOUT_ / 32, E_ / 32), dim3(32, 8)>>>(Wkv, wkh, wkl, E_, KVOUT_);
    transpose_split<<<dim3(E_ / 32, E_ / 32), dim3(32, 8)>>>(Wo, woh, wol, E_, E_);
    rope_table_kernel<<<(S_ * 64) / 256, 256>>>(tab);

    cudaFuncSetAttribute(mma_gemm_kernel, cudaFuncAttributeMaxDynamicSharedMemorySize,
                         GT_SMEM);
    cudaFuncSetAttribute(attn_mma_kernel, cudaFuncAttributeMaxDynamicSharedMemorySize,
                         ATT_SMEM);

    // q = x @ Wq + bq  (+RoPE, bf16 hi/lo out)
    mma_gemm_kernel<<<dim3(E_ / 128, M / 128), 256, GT_SMEM>>>(
        xh, xl, wqh, wql, bq, nullptr, qh, ql, tab, M, E_, E_, 1, 1);
    // kv = x @ Wkv + bkv  (+RoPE on K half, bf16 hi/lo out)
    mma_gemm_kernel<<<dim3(KVOUT_ / 128, M / 128), 256, GT_SMEM>>>(
        xh, xl, wkh, wkl, bkv, nullptr, kvh, kvl, tab, M, KVOUT_, E_, 2, 1);

    // attention (tensor-core, bf16 hi/lo in & out)
    attn_mma_kernel<<<dim3(S_ / 64, B_ * NH_), 128, ATT_SMEM>>>(
        qh, ql, kvh, kvl, yh, yl);

    // out = y @ Wo + bo  (fp32 out)
    mma_gemm_kernel<<<dim3(E_ / 128, M / 128), 256, GT_SMEM>>>(
        yh, yl, woh, wol, bo, out, nullptr, nullptr, tab, M, E_, E_, 0, 0);
}

// round 7
// speedup vs baseline: 3.2938x; 1.0113x over previous
#include <cuda_runtime.h>
#include <cuda_bf16.h>
#include <math.h>

typedef unsigned int u32;

// Problem constants
#define B_      2
#define S_      4096
#define E_      2048
#define NH_     16
#define HD_     128
#define NKV_    4
#define KVOUT_  1024
#define WINDOW_ 512
#define NMETA_  16

// ---------------------------------------------------------------------------
// Scratch (device globals)
// ---------------------------------------------------------------------------
__device__ __nv_bfloat16 g_xh[B_ * S_ * E_];
__device__ __nv_bfloat16 g_xl[B_ * S_ * E_];
__device__ __nv_bfloat16 g_qh[B_ * S_ * E_];
__device__ __nv_bfloat16 g_ql[B_ * S_ * E_];
__device__ __nv_bfloat16 g_kvh[B_ * S_ * KVOUT_];
__device__ __nv_bfloat16 g_kvl[B_ * S_ * KVOUT_];
__device__ __nv_bfloat16 g_yh[B_ * S_ * E_];
__device__ __nv_bfloat16 g_yl[B_ * S_ * E_];
__device__ __nv_bfloat16 g_wqt_h[E_ * E_];
__device__ __nv_bfloat16 g_wqt_l[E_ * E_];
__device__ __nv_bfloat16 g_wkvt_h[KVOUT_ * E_];
__device__ __nv_bfloat16 g_wkvt_l[KVOUT_ * E_];
__device__ __nv_bfloat16 g_wot_h[E_ * E_];
__device__ __nv_bfloat16 g_wot_l[E_ * E_];
__device__ float2 g_ropetab[S_ * 64];

// ---------------------------------------------------------------------------
// Helpers
// ---------------------------------------------------------------------------
__device__ __forceinline__ u32 smem_u32(const void* p) {
    u32 a;
    asm("{ .reg .u64 t; cvta.to.shared.u64 t, %1; cvt.u32.u64 %0, t; }"
        : "=r"(a) : "l"(p));
    return a;
}

__device__ __forceinline__ void mma16816(float* d, const u32* a, const u32* b)
{
    asm volatile(
        "mma.sync.aligned.m16n8k16.row.col.f32.bf16.bf16.f32 "
        "{%0,%1,%2,%3}, {%4,%5,%6,%7}, {%8,%9}, {%0,%1,%2,%3};"
        : "+f"(d[0]), "+f"(d[1]), "+f"(d[2]), "+f"(d[3])
        : "r"(a[0]), "r"(a[1]), "r"(a[2]), "r"(a[3]), "r"(b[0]), "r"(b[1]));
}

__device__ __forceinline__ void ldsm_x4(u32* r, u32 addr)
{
    asm volatile("ldmatrix.sync.aligned.m8n8.x4.shared.b16 {%0,%1,%2,%3}, [%4];"
        : "=r"(r[0]), "=r"(r[1]), "=r"(r[2]), "=r"(r[3]) : "r"(addr));
}

__device__ __forceinline__ void ldsm_x4_t(u32* r, u32 addr)
{
    asm volatile("ldmatrix.sync.aligned.m8n8.x4.trans.shared.b16 {%0,%1,%2,%3}, [%4];"
        : "=r"(r[0]), "=r"(r[1]), "=r"(r[2]), "=r"(r[3]) : "r"(addr));
}

__device__ __forceinline__ void split2(float x, float y, u32& hh, u32& ll)
{
    __nv_bfloat16 hx = __float2bfloat16(x), hy = __float2bfloat16(y);
    __nv_bfloat162 hv(hx, hy);
    __nv_bfloat162 lv(__float2bfloat16(x - __bfloat162float(hx)),
                      __float2bfloat16(y - __bfloat162float(hy)));
    hh = *(u32*)&hv; ll = *(u32*)&lv;
}

// ---------------------------------------------------------------------------
// Prep kernels
// ---------------------------------------------------------------------------
__global__ void split_kernel(const float* __restrict__ in,
                             __nv_bfloat16* __restrict__ hi,
                             __nv_bfloat16* __restrict__ lo, int n4)
{
    int i = blockIdx.x * 256 + threadIdx.x;
    if (i >= n4) return;
    float4 v = ((const float4*)in)[i];
    __nv_bfloat16 h0 = __float2bfloat16(v.x), h1 = __float2bfloat16(v.y);
    __nv_bfloat16 h2 = __float2bfloat16(v.z), h3 = __float2bfloat16(v.w);
    __nv_bfloat162* H = (__nv_bfloat162*)hi;
    __nv_bfloat162* L = (__nv_bfloat162*)lo;
    H[i * 2]     = __nv_bfloat162(h0, h1);
    H[i * 2 + 1] = __nv_bfloat162(h2, h3);
    L[i * 2]     = __nv_bfloat162(__float2bfloat16(v.x - __bfloat162float(h0)),
                                  __float2bfloat16(v.y - __bfloat162float(h1)));
    L[i * 2 + 1] = __nv_bfloat162(__float2bfloat16(v.z - __bfloat162float(h2)),
                                  __float2bfloat16(v.w - __bfloat162float(h3)));
}

__global__ void transpose_split(const float* __restrict__ W,
                                __nv_bfloat16* __restrict__ Th,
                                __nv_bfloat16* __restrict__ Tl, int K, int N)
{
    __shared__ float t[32][33];
    int n0 = blockIdx.x * 32, k0 = blockIdx.y * 32;
    for (int i = threadIdx.y; i < 32; i += 8)
        t[i][threadIdx.x] = W[(size_t)(k0 + i) * N + n0 + threadIdx.x];
    __syncthreads();
    for (int i = threadIdx.y; i < 32; i += 8) {
        float v = t[threadIdx.x][i];
        size_t o = (size_t)(n0 + i) * K + k0 + threadIdx.x;
        __nv_bfloat16 h = __float2bfloat16(v);
        Th[o] = h;
        Tl[o] = __float2bfloat16(v - __bfloat162float(h));
    }
}

__global__ void rope_table_kernel(float2* tab)
{
    int idx = blockIdx.x * 256 + threadIdx.x;
    if (idx >= S_ * 64) return;
    int pos = idx >> 6, i = idx & 63;
    float inv = (float)exp(-(double)i * (9.210340371976184 / 64.0));
    float ang = (float)pos * inv;
    tab[idx] = make_float2(cosf(ang), sinf(ang));
}

// ---------------------------------------------------------------------------
// mma.sync bf16 GEMM, ldmatrix fragment loads.
// Block 128x128x32, 4 warps (2m x 2n) of 64x64 tiles, cp.async 2-stage,
// 2 CTAs/SM. Warp tile fattened to cut smem crossbar traffic per MAC.
// ---------------------------------------------------------------------------
#define BKP       40
#define TILE_ELEM (128 * BKP)
#define STAGE_ELEM (4 * TILE_ELEM)
#define GT_SMEM   (2 * STAGE_ELEM * 2)

#define CP_ASYNC16(dst, src) \
    asm volatile("cp.async.cg.shared.global [%0], [%1], 16;" :: "r"(dst), "l"(src))
#define CP_COMMIT() asm volatile("cp.async.commit_group;")
#define CP_WAIT1()  asm volatile("cp.async.wait_group 1;")
#define CP_WAIT0()  asm volatile("cp.async.wait_group 0;")

__global__ __launch_bounds__(128, 2) void mma_gemm_kernel(
    const __nv_bfloat16* __restrict__ Ahi, const __nv_bfloat16* __restrict__ Alo,
    const __nv_bfloat16* __restrict__ Bhi, const __nv_bfloat16* __restrict__ Blo,
    const float* __restrict__ bias, float* __restrict__ Cf,
    __nv_bfloat16* __restrict__ Ch, __nv_bfloat16* __restrict__ Cl,
    const float2* __restrict__ tab, int M, int N, int K,
    int rope_mode, int bf16_out)
{
    extern __shared__ __nv_bfloat16 sm[];
    const u32 sbase = smem_u32(sm);
    const int tid = threadIdx.x;
    const int wid = tid >> 5, lane = tid & 31;
    const int wm = wid & 1, wn = wid >> 1;      // 2 x 2 warp grid
    const int m0 = blockIdx.y * 128;
    const int n0 = blockIdx.x * 128;
    const int g  = lane >> 2;
    const int c0 = (lane & 3) * 2;
    const int lrow = lane & 7, grp = lane >> 3;

    auto load_stage = [&](int c, int stage) {
        const int k0 = c * 32;
        const u32 sb = sbase + stage * STAGE_ELEM * 2;
#pragma unroll
        for (int i = 0; i < 4; i++) {
            int idx = tid + i * 128;            // 0..511
            int row = idx >> 2, quad = idx & 3;
            u32 soff = (u32)(row * BKP + quad * 8) * 2;
            size_t ga = (size_t)(m0 + row) * K + k0 + quad * 8;
            size_t gb = (size_t)(n0 + row) * K + k0 + quad * 8;
            CP_ASYNC16(sb + soff,                 (const char*)(Ahi + ga));
            CP_ASYNC16(sb + TILE_ELEM * 2 + soff, (const char*)(Alo + ga));
            CP_ASYNC16(sb + TILE_ELEM * 4 + soff, (const char*)(Bhi + gb));
            CP_ASYNC16(sb + TILE_ELEM * 6 + soff, (const char*)(Blo + gb));
        }
    };

    float acc[4][8][4];
#pragma unroll
    for (int i = 0; i < 4; i++)
#pragma unroll
        for (int j = 0; j < 8; j++)
#pragma unroll
            for (int e = 0; e < 4; e++) acc[i][j][e] = 0.f;

    const int nc = K >> 5;
    load_stage(0, 0);
    CP_COMMIT();

    for (int c = 0; c < nc; c++) {
        if (c + 1 < nc) {
            load_stage(c + 1, (c + 1) & 1);
            CP_COMMIT();
            CP_WAIT1();
        } else {
            CP_WAIT0();
        }
        __syncthreads();

        const u32 st  = sbase + (c & 1) * STAGE_ELEM * 2;
        const u32 sAh = st;
        const u32 sAl = st + TILE_ELEM * 2;
        const u32 sBh = st + TILE_ELEM * 4;
        const u32 sBl = st + TILE_ELEM * 6;

#pragma unroll
        for (int kh = 0; kh < 2; kh++) {
            const int kk = kh * 16;
            u32 bh[8][2], bl[8][2];
#pragma unroll
            for (int nfp = 0; nfp < 4; nfp++) {
                u32 off = (u32)((wn * 64 + nfp * 16 + (grp >> 1) * 8 + lrow) * BKP
                                + kk + (grp & 1) * 8) * 2;
                ldsm_x4(&bh[nfp * 2][0], sBh + off);
                ldsm_x4(&bl[nfp * 2][0], sBl + off);
            }
#pragma unroll
            for (int mf = 0; mf < 4; mf++) {
                u32 offa = (u32)((wm * 64 + mf * 16 + (grp & 1) * 8 + lrow) * BKP
                                 + kk + (grp >> 1) * 8) * 2;
                u32 ah[4], al[4];
                ldsm_x4(ah, sAh + offa);
                ldsm_x4(al, sAl + offa);
#pragma unroll
                for (int nf = 0; nf < 8; nf++) {
                    mma16816(acc[mf][nf], ah, bh[nf]);
                    mma16816(acc[mf][nf], ah, bl[nf]);
                    mma16816(acc[mf][nf], al, bh[nf]);
                }
            }
        }
        __syncthreads();
    }

    // Epilogue
#pragma unroll
    for (int mf = 0; mf < 4; mf++) {
        int row0 = m0 + wm * 64 + mf * 16 + g;
        int pos0 = row0 & (S_ - 1);
        int pos1 = (row0 + 8) & (S_ - 1);
#pragma unroll
        for (int nf = 0; nf < 8; nf++) {
            int col = n0 + wn * 64 + nf * 8 + c0;
            float b0 = bias[col], b1 = bias[col + 1];
            float v0 = acc[mf][nf][0] + b0, v1 = acc[mf][nf][1] + b1;
            float v2 = acc[mf][nf][2] + b0, v3 = acc[mf][nf][3] + b1;
            bool do_rope = (rope_mode == 1) || (rope_mode == 2 && col < 512);
            if (do_rope) {
                int ti = (col & 127) >> 1;
                float2 cs0 = tab[pos0 * 64 + ti];
                float2 cs1 = tab[pos1 * 64 + ti];
                float t0 = v0, t1 = v1;
                v0 = t0 * cs0.x - t1 * cs0.y;
                v1 = t1 * cs0.x + t0 * cs0.y;
                float t2 = v2, t3 = v3;
                v2 = t2 * cs1.x - t3 * cs1.y;
                v3 = t3 * cs1.x + t2 * cs1.y;
            }
            if (!bf16_out) {
                *(float2*)(Cf + (size_t)row0 * N + col)       = make_float2(v0, v1);
                *(float2*)(Cf + (size_t)(row0 + 8) * N + col) = make_float2(v2, v3);
            } else {
                u32 hh, ll;
                split2(v0, v1, hh, ll);
                *(u32*)(Ch + (size_t)row0 * N + col) = hh;
                *(u32*)(Cl + (size_t)row0 * N + col) = ll;
                split2(v2, v3, hh, ll);
                *(u32*)(Ch + (size_t)(row0 + 8) * N + col) = hh;
                *(u32*)(Cl + (size_t)(row0 + 8) * N + col) = ll;
            }
        }
    }
}

// ---------------------------------------------------------------------------
// Attention: mma.sync bf16, hi/lo 3-pass. Q fragments register-resident.
// (unchanged from R6 — passing at ~0.35 ms)
// ---------------------------------------------------------------------------
#define AT_BKP 136
#define KH_OFF 0
#define KL_OFF (64 * AT_BKP)
#define VH_OFF (2 * 64 * AT_BKP)
#define VL_OFF (3 * 64 * AT_BKP)
#define ATT_SMEM (4 * 64 * AT_BKP * 2)

__global__ __launch_bounds__(128, 2) void attn_mma_kernel(
    const __nv_bfloat16* __restrict__ qh, const __nv_bfloat16* __restrict__ ql,
    const __nv_bfloat16* __restrict__ kvh, const __nv_bfloat16* __restrict__ kvl,
    __nv_bfloat16* __restrict__ yh, __nv_bfloat16* __restrict__ yl)
{
    extern __shared__ __nv_bfloat16 sm[];
    const u32 smb = smem_u32(sm);
    const int tid = threadIdx.x;
    const int w = tid >> 5, lane = tid & 31;
    const int g = lane >> 2, c0 = (lane & 3) * 2;
    const int lrow = lane & 7, grp = lane >> 3;
    const int bhp = blockIdx.y;
    const int b = bhp >> 4, h = bhp & 15;
    const int kv_h = h >> 2;
    const int q0 = blockIdx.x << 6;
    int ls = q0 - WINDOW_ + 1; if (ls < NMETA_) ls = NMETA_;
    const int kend = q0 + 64;
    const float scale = 0.088388347648318447f;

    // Stage Q (hi/lo) into KH/KL regions, extract fragments to registers
#pragma unroll
    for (int it = 0; it < 8; it++) {
        int fi = tid + it * 128;
        int r = fi >> 4, q8 = fi & 15;
        size_t ga = ((size_t)(b * S_ + q0 + r) * NH_ + h) * HD_ + q8 * 8;
        *(uint4*)&sm[KH_OFF + r * AT_BKP + q8 * 8] = *(const uint4*)(qh + ga);
        *(uint4*)&sm[KL_OFF + r * AT_BKP + q8 * 8] = *(const uint4*)(ql + ga);
    }
    __syncthreads();

    u32 qfh[8][4], qfl[8][4];
#pragma unroll
    for (int ks = 0; ks < 8; ks++) {
        u32 off = (u32)((w * 16 + (grp & 1) * 8 + lrow) * AT_BKP
                        + ks * 16 + (grp >> 1) * 8) * 2;
        ldsm_x4(qfh[ks], smb + KH_OFF * 2 + off);
        ldsm_x4(qfl[ks], smb + KL_OFF * 2 + off);
    }

    float m0 = -1e30f, m1 = -1e30f, l0 = 0.f, l1 = 0.f;
    float o[16][4];
#pragma unroll
    for (int i = 0; i < 16; i++)
#pragma unroll
        for (int e = 0; e < 4; e++) o[i][e] = 0.f;

    const int qp0 = q0 + w * 16 + g;
    const int qp1 = qp0 + 8;
    const int nB = (kend - ls + 63) >> 6;

    for (int t = -1; t < nB; t++) {
        const int kbase = (t < 0) ? 0 : (ls + (t << 6));
        int kcnt = (t < 0) ? NMETA_ : (kend - kbase);
        if (kcnt > 64) kcnt = 64;

        __syncthreads();
#pragma unroll
        for (int it = 0; it < 8; it++) {
            int fi = tid + it * 128;
            int r = fi >> 4, q8 = fi & 15;
            uint4 kh4 = make_uint4(0, 0, 0, 0), kl4 = kh4, vh4 = kh4, vl4 = kh4;
            if (r < kcnt) {
                size_t base = (size_t)(b * S_ + kbase + r) * 1024 + kv_h * 128 + q8 * 8;
                kh4 = *(const uint4*)(kvh + base);
                kl4 = *(const uint4*)(kvl + base);
                vh4 = *(const uint4*)(kvh + base + 512);
                vl4 = *(const uint4*)(kvl + base + 512);
            }
            int so = r * AT_BKP + q8 * 8;
            *(uint4*)&sm[KH_OFF + so] = kh4;
            *(uint4*)&sm[KL_OFF + so] = kl4;
            *(uint4*)&sm[VH_OFF + so] = vh4;
            *(uint4*)&sm[VL_OFF + so] = vl4;
        }
        __syncthreads();

        // --- QK^T: 3-pass hi/lo ---
        float s[8][4];
#pragma unroll
        for (int nf = 0; nf < 8; nf++)
#pragma unroll
            for (int e = 0; e < 4; e++) s[nf][e] = 0.f;

#pragma unroll
        for (int ks = 0; ks < 8; ks++) {
            const int kk = ks * 16;
#pragma unroll
            for (int nfp = 0; nfp < 4; nfp++) {
                u32 off = (u32)((nfp * 16 + (grp >> 1) * 8 + lrow) * AT_BKP
                                + kk + (grp & 1) * 8) * 2;
                u32 kh2[4], kl2[4];
                ldsm_x4(kh2, smb + KH_OFF * 2 + off);
                ldsm_x4(kl2, smb + KL_OFF * 2 + off);
                mma16816(s[2 * nfp],     qfh[ks], &kh2[0]);
                mma16816(s[2 * nfp],     qfh[ks], &kl2[0]);
                mma16816(s[2 * nfp],     qfl[ks], &kh2[0]);
                mma16816(s[2 * nfp + 1], qfh[ks], &kh2[2]);
                mma16816(s[2 * nfp + 1], qfh[ks], &kl2[2]);
                mma16816(s[2 * nfp + 1], qfl[ks], &kh2[2]);
            }
        }

        // --- Mask + scale + online softmax ---
        float mx0 = -1e30f, mx1 = -1e30f;
#pragma unroll
        for (int nf = 0; nf < 8; nf++) {
#pragma unroll
            for (int e = 0; e < 4; e++) {
                int col = nf * 8 + c0 + (e & 1);
                int kpos = kbase + col;
                int qp = (e < 2) ? qp0 : qp1;
                bool ok = (col < kcnt) && (kpos <= qp) &&
                          ((kpos >= qp - (WINDOW_ - 1)) || (kpos < NMETA_));
                float v = ok ? s[nf][e] * scale : -1e30f;
                s[nf][e] = v;
                if (e < 2) mx0 = fmaxf(mx0, v); else mx1 = fmaxf(mx1, v);
            }
        }
        mx0 = fmaxf(mx0, __shfl_xor_sync(0xffffffffu, mx0, 1));
        mx0 = fmaxf(mx0, __shfl_xor_sync(0xffffffffu, mx0, 2));
        mx1 = fmaxf(mx1, __shfl_xor_sync(0xffffffffu, mx1, 1));
        mx1 = fmaxf(mx1, __shfl_xor_sync(0xffffffffu, mx1, 2));

        float mn0 = fmaxf(m0, mx0), mn1 = fmaxf(m1, mx1);
        float f0 = __expf(m0 - mn0), f1 = __expf(m1 - mn1);
        float rs0 = 0.f, rs1 = 0.f;
#pragma unroll
        for (int nf = 0; nf < 8; nf++) {
            float p0 = __expf(s[nf][0] - mn0);
            float p1 = __expf(s[nf][1] - mn0);
            float p2 = __expf(s[nf][2] - mn1);
            float p3 = __expf(s[nf][3] - mn1);
            s[nf][0] = p0; s[nf][1] = p1; s[nf][2] = p2; s[nf][3] = p3;
            rs0 += p0 + p1; rs1 += p2 + p3;
        }
        rs0 += __shfl_xor_sync(0xffffffffu, rs0, 1);
        rs0 += __shfl_xor_sync(0xffffffffu, rs0, 2);
        rs1 += __shfl_xor_sync(0xffffffffu, rs1, 1);
        rs1 += __shfl_xor_sync(0xffffffffu, rs1, 2);
        l0 = l0 * f0 + rs0; m0 = mn0;
        l1 = l1 * f1 + rs1; m1 = mn1;
#pragma unroll
        for (int nf = 0; nf < 16; nf++) {
            o[nf][0] *= f0; o[nf][1] *= f0;
            o[nf][2] *= f1; o[nf][3] *= f1;
        }

        // --- P @ V: A = P (registers hi/lo), B = V via ldmatrix.trans ---
#pragma unroll
        for (int ks = 0; ks < 4; ks++) {
            u32 ph[4], pl[4];
            split2(s[2 * ks][0],     s[2 * ks][1],     ph[0], pl[0]);
            split2(s[2 * ks][2],     s[2 * ks][3],     ph[1], pl[1]);
            split2(s[2 * ks + 1][0], s[2 * ks + 1][1], ph[2], pl[2]);
            split2(s[2 * ks + 1][2], s[2 * ks + 1][3], ph[3], pl[3]);
            const int kk = ks * 16;
#pragma unroll
            for (int nfp = 0; nfp < 8; nfp++) {
                u32 off = (u32)((kk + (grp & 1) * 8 + lrow) * AT_BKP
                                + nfp * 16 + (grp >> 1) * 8) * 2;
                u32 vh2[4], vl2[4];
                ldsm_x4_t(vh2, smb + VH_OFF * 2 + off);
                ldsm_x4_t(vl2, smb + VL_OFF * 2 + off);
                mma16816(o[2 * nfp],     ph, &vh2[0]);
                mma16816(o[2 * nfp],     ph, &vl2[0]);
                mma16816(o[2 * nfp],     pl, &vh2[0]);
                mma16816(o[2 * nfp + 1], ph, &vh2[2]);
                mma16816(o[2 * nfp + 1], ph, &vl2[2]);
                mma16816(o[2 * nfp + 1], pl, &vh2[2]);
            }
        }
    }

    // Epilogue: normalize, split to bf16 hi/lo, store y[b, q, h, :]
    float i0 = 1.0f / l0, i1 = 1.0f / l1;
    const int row0 = q0 + w * 16 + g;
#pragma unroll
    for (int nf = 0; nf < 16; nf++) {
        int col = nf * 8 + c0;
        size_t a0 = ((size_t)(b * S_ + row0) * NH_ + h) * HD_ + col;
        size_t a1 = ((size_t)(b * S_ + row0 + 8) * NH_ + h) * HD_ + col;
        u32 hh, ll;
        split2(o[nf][0] * i0, o[nf][1] * i0, hh, ll);
        *(u32*)(yh + a0) = hh;
        *(u32*)(yl + a0) = ll;
        split2(o[nf][2] * i1, o[nf][3] * i1, hh, ll);
        *(u32*)(yh + a1) = hh;
        *(u32*)(yl + a1) = ll;
    }
}

// ---------------------------------------------------------------------------
// Launch
// ---------------------------------------------------------------------------
extern "C" void kernel_launch(void* const* d_in, const int* in_sizes, int n_in,
                              void* d_out, int out_size)
{
    const float* x   = (const float*)d_in[0];
    const float* Wq  = (const float*)d_in[1];
    const float* bq  = (const float*)d_in[2];
    const float* Wkv = (const float*)d_in[3];
    const float* bkv = (const float*)d_in[4];
    const float* Wo  = (const float*)d_in[5];
    const float* bo  = (const float*)d_in[6];
    float* out = (float*)d_out;

    __nv_bfloat16 *xh, *xl, *qh, *ql, *kvh, *kvl, *yh, *yl;
    __nv_bfloat16 *wqh, *wql, *wkh, *wkl, *woh, *wol;
    float2* tab;
    cudaGetSymbolAddress((void**)&xh,  g_xh);
    cudaGetSymbolAddress((void**)&xl,  g_xl);
    cudaGetSymbolAddress((void**)&qh,  g_qh);
    cudaGetSymbolAddress((void**)&ql,  g_ql);
    cudaGetSymbolAddress((void**)&kvh, g_kvh);
    cudaGetSymbolAddress((void**)&kvl, g_kvl);
    cudaGetSymbolAddress((void**)&yh,  g_yh);
    cudaGetSymbolAddress((void**)&yl,  g_yl);
    cudaGetSymbolAddress((void**)&wqh, g_wqt_h);
    cudaGetSymbolAddress((void**)&wql, g_wqt_l);
    cudaGetSymbolAddress((void**)&wkh, g_wkvt_h);
    cudaGetSymbolAddress((void**)&wkl, g_wkvt_l);
    cudaGetSymbolAddress((void**)&woh, g_wot_h);
    cudaGetSymbolAddress((void**)&wol, g_wot_l);
    cudaGetSymbolAddress((void**)&tab, g_ropetab);

    const int M = B_ * S_;
    const int n4 = (B_ * S_ * E_) / 4;

    split_kernel<<<n4 / 256, 256>>>(x, xh, xl, n4);
    transpose_split<<<dim3(E_ / 32, E_ / 32), dim3(32, 8)>>>(Wq, wqh, wql, E_, E_);
    transpose_split<<<dim3(KVOUT_ / 32, E_ / 32), dim3(32, 8)>>>(Wkv, wkh, wkl, E_, KVOUT_);
    transpose_split<<<dim3(E_ / 32, E_ / 32), dim3(32, 8)>>>(Wo, woh, wol, E_, E_);
    rope_table_kernel<<<(S_ * 64) / 256, 256>>>(tab);

    cudaFuncSetAttribute(mma_gemm_kernel, cudaFuncAttributeMaxDynamicSharedMemorySize,
                         GT_SMEM);
    cudaFuncSetAttribute(attn_mma_kernel, cudaFuncAttributeMaxDynamicSharedMemorySize,
                         ATT_SMEM);

    // q = x @ Wq + bq  (+RoPE, bf16 hi/lo out)
    mma_gemm_kernel<<<dim3(E_ / 128, M / 128), 128, GT_SMEM>>>(
        xh, xl, wqh, wql, bq, nullptr, qh, ql, tab, M, E_, E_, 1, 1);
    // kv = x @ Wkv + bkv  (+RoPE on K half, bf16 hi/lo out)
    mma_gemm_kernel<<<dim3(KVOUT_ / 128, M / 128), 128, GT_SMEM>>>(
        xh, xl, wkh, wkl, bkv, nullptr, kvh, kvl, tab, M, KVOUT_, E_, 2, 1);

    // attention (tensor-core, bf16 hi/lo in & out)
    attn_mma_kernel<<<dim3(S_ / 64, B_ * NH_), 128, ATT_SMEM>>>(
        qh, ql, kvh, kvl, yh, yl);

    // out = y @ Wo + bo  (fp32 out)
    mma_gemm_kernel<<<dim3(E_ / 128, M / 128), 128, GT_SMEM>>>(
        yh, yl, woh, wol, bo, out, nullptr, nullptr, tab, M, E_, E_, 0, 0);
}

// round 8
// speedup vs baseline: 6.4891x; 1.9701x over previous
#include <cuda_runtime.h>
#include <cuda_fp16.h>
#include <math.h>

typedef unsigned int u32;

// Problem constants
#define B_      2
#define S_      4096
#define E_      2048
#define NH_     16
#define HD_     128
#define NKV_    4
#define KVOUT_  1024
#define WINDOW_ 512
#define NMETA_  16

// ---------------------------------------------------------------------------
// Scratch (device globals) — single fp16 copies
// ---------------------------------------------------------------------------
__device__ __half g_x16 [B_ * S_ * E_];
__device__ __half g_q16 [B_ * S_ * E_];
__device__ __half g_kv16[B_ * S_ * KVOUT_];
__device__ __half g_y16 [B_ * S_ * E_];
__device__ __half g_wqt [E_ * E_];
__device__ __half g_wkvt[KVOUT_ * E_];
__device__ __half g_wot [E_ * E_];
__device__ float2 g_ropetab[S_ * 64];

// ---------------------------------------------------------------------------
// Helpers
// ---------------------------------------------------------------------------
__device__ __forceinline__ u32 smem_u32(const void* p) {
    u32 a;
    asm("{ .reg .u64 t; cvta.to.shared.u64 t, %1; cvt.u32.u64 %0, t; }"
        : "=r"(a) : "l"(p));
    return a;
}

__device__ __forceinline__ void mma16816(float* d, const u32* a, const u32* b)
{
    asm volatile(
        "mma.sync.aligned.m16n8k16.row.col.f32.f16.f16.f32 "
        "{%0,%1,%2,%3}, {%4,%5,%6,%7}, {%8,%9}, {%0,%1,%2,%3};"
        : "+f"(d[0]), "+f"(d[1]), "+f"(d[2]), "+f"(d[3])
        : "r"(a[0]), "r"(a[1]), "r"(a[2]), "r"(a[3]), "r"(b[0]), "r"(b[1]));
}

__device__ __forceinline__ void ldsm_x4(u32* r, u32 addr)
{
    asm volatile("ldmatrix.sync.aligned.m8n8.x4.shared.b16 {%0,%1,%2,%3}, [%4];"
        : "=r"(r[0]), "=r"(r[1]), "=r"(r[2]), "=r"(r[3]) : "r"(addr));
}

__device__ __forceinline__ void ldsm_x4_t(u32* r, u32 addr)
{
    asm volatile("ldmatrix.sync.aligned.m8n8.x4.trans.shared.b16 {%0,%1,%2,%3}, [%4];"
        : "=r"(r[0]), "=r"(r[1]), "=r"(r[2]), "=r"(r[3]) : "r"(addr));
}

__device__ __forceinline__ u32 packh2(float x, float y)
{
    __half2 h = __floats2half2_rn(x, y);
    return *(u32*)&h;
}

// ---------------------------------------------------------------------------
// Prep kernels
// ---------------------------------------------------------------------------
__global__ void convert_kernel(const float* __restrict__ in,
                               __half* __restrict__ out, int n4)
{
    int i = blockIdx.x * 256 + threadIdx.x;
    if (i >= n4) return;
    float4 v = ((const float4*)in)[i];
    u32* O = (u32*)out;
    O[i * 2]     = packh2(v.x, v.y);
    O[i * 2 + 1] = packh2(v.z, v.w);
}

__global__ void transpose_convert(const float* __restrict__ W,
                                  __half* __restrict__ T, int K, int N)
{
    __shared__ float t[32][33];
    int n0 = blockIdx.x * 32, k0 = blockIdx.y * 32;
    for (int i = threadIdx.y; i < 32; i += 8)
        t[i][threadIdx.x] = W[(size_t)(k0 + i) * N + n0 + threadIdx.x];
    __syncthreads();
    for (int i = threadIdx.y; i < 32; i += 8)
        T[(size_t)(n0 + i) * K + k0 + threadIdx.x] =
            __float2half_rn(t[threadIdx.x][i]);
}

__global__ void rope_table_kernel(float2* tab)
{
    int idx = blockIdx.x * 256 + threadIdx.x;
    if (idx >= S_ * 64) return;
    int pos = idx >> 6, i = idx & 63;
    float inv = (float)exp(-(double)i * (9.210340371976184 / 64.0));
    float ang = (float)pos * inv;
    tab[idx] = make_float2(cosf(ang), sinf(ang));
}

// ---------------------------------------------------------------------------
// mma.sync fp16 GEMM (single-pass), ldmatrix fragment loads.
// Block 128x128x32, 4 warps (2m x 2n) of 64x64 tiles, cp.async 2-stage,
// 2 CTAs/SM.
// ---------------------------------------------------------------------------
#define BKP       40
#define TILE_ELEM (128 * BKP)
#define STAGE_ELEM (2 * TILE_ELEM)          // A, B tiles
#define GT_SMEM   (2 * STAGE_ELEM * 2)      // 2 stages, bytes

#define CP_ASYNC16(dst, src) \
    asm volatile("cp.async.cg.shared.global [%0], [%1], 16;" :: "r"(dst), "l"(src))
#define CP_COMMIT() asm volatile("cp.async.commit_group;")
#define CP_WAIT1()  asm volatile("cp.async.wait_group 1;")
#define CP_WAIT0()  asm volatile("cp.async.wait_group 0;")

__global__ __launch_bounds__(128, 2) void mma_gemm_kernel(
    const __half* __restrict__ A, const __half* __restrict__ Bm,
    const float* __restrict__ bias, float* __restrict__ Cf,
    __half* __restrict__ C16,
    const float2* __restrict__ tab, int M, int N, int K,
    int rope_mode, int f16_out)
{
    extern __shared__ __half sm[];
    const u32 sbase = smem_u32(sm);
    const int tid = threadIdx.x;
    const int wid = tid >> 5, lane = tid & 31;
    const int wm = wid & 1, wn = wid >> 1;      // 2 x 2 warp grid
    const int m0 = blockIdx.y * 128;
    const int n0 = blockIdx.x * 128;
    const int g  = lane >> 2;
    const int c0 = (lane & 3) * 2;
    const int lrow = lane & 7, grp = lane >> 3;

    auto load_stage = [&](int c, int stage) {
        const int k0 = c * 32;
        const u32 sb = sbase + stage * STAGE_ELEM * 2;
#pragma unroll
        for (int i = 0; i < 4; i++) {
            int idx = tid + i * 128;            // 0..511
            int row = idx >> 2, quad = idx & 3;
            u32 soff = (u32)(row * BKP + quad * 8) * 2;
            size_t ga = (size_t)(m0 + row) * K + k0 + quad * 8;
            size_t gb = (size_t)(n0 + row) * K + k0 + quad * 8;
            CP_ASYNC16(sb + soff,                 (const char*)(A + ga));
            CP_ASYNC16(sb + TILE_ELEM * 2 + soff, (const char*)(Bm + gb));
        }
    };

    float acc[4][8][4];
#pragma unroll
    for (int i = 0; i < 4; i++)
#pragma unroll
        for (int j = 0; j < 8; j++)
#pragma unroll
            for (int e = 0; e < 4; e++) acc[i][j][e] = 0.f;

    const int nc = K >> 5;
    load_stage(0, 0);
    CP_COMMIT();

    for (int c = 0; c < nc; c++) {
        if (c + 1 < nc) {
            load_stage(c + 1, (c + 1) & 1);
            CP_COMMIT();
            CP_WAIT1();
        } else {
            CP_WAIT0();
        }
        __syncthreads();

        const u32 st = sbase + (c & 1) * STAGE_ELEM * 2;
        const u32 sA = st;
        const u32 sB = st + TILE_ELEM * 2;

#pragma unroll
        for (int kh = 0; kh < 2; kh++) {
            const int kk = kh * 16;
            u32 bfr[8][2];
#pragma unroll
            for (int nfp = 0; nfp < 4; nfp++) {
                u32 off = (u32)((wn * 64 + nfp * 16 + (grp >> 1) * 8 + lrow) * BKP
                                + kk + (grp & 1) * 8) * 2;
                ldsm_x4(&bfr[nfp * 2][0], sB + off);
            }
#pragma unroll
            for (int mf = 0; mf < 4; mf++) {
                u32 offa = (u32)((wm * 64 + mf * 16 + (grp & 1) * 8 + lrow) * BKP
                                 + kk + (grp >> 1) * 8) * 2;
                u32 a[4];
                ldsm_x4(a, sA + offa);
#pragma unroll
                for (int nf = 0; nf < 8; nf++)
                    mma16816(acc[mf][nf], a, bfr[nf]);
            }
        }
        __syncthreads();
    }

    // Epilogue: bias + RoPE, fp32 or fp16 store
#pragma unroll
    for (int mf = 0; mf < 4; mf++) {
        int row0 = m0 + wm * 64 + mf * 16 + g;
        int pos0 = row0 & (S_ - 1);
        int pos1 = (row0 + 8) & (S_ - 1);
#pragma unroll
        for (int nf = 0; nf < 8; nf++) {
            int col = n0 + wn * 64 + nf * 8 + c0;
            float b0 = bias[col], b1 = bias[col + 1];
            float v0 = acc[mf][nf][0] + b0, v1 = acc[mf][nf][1] + b1;
            float v2 = acc[mf][nf][2] + b0, v3 = acc[mf][nf][3] + b1;
            bool do_rope = (rope_mode == 1) || (rope_mode == 2 && col < 512);
            if (do_rope) {
                int ti = (col & 127) >> 1;
                float2 cs0 = tab[pos0 * 64 + ti];
                float2 cs1 = tab[pos1 * 64 + ti];
                float t0 = v0, t1 = v1;
                v0 = t0 * cs0.x - t1 * cs0.y;
                v1 = t1 * cs0.x + t0 * cs0.y;
                float t2 = v2, t3 = v3;
                v2 = t2 * cs1.x - t3 * cs1.y;
                v3 = t3 * cs1.x + t2 * cs1.y;
            }
            if (!f16_out) {
                *(float2*)(Cf + (size_t)row0 * N + col)       = make_float2(v0, v1);
                *(float2*)(Cf + (size_t)(row0 + 8) * N + col) = make_float2(v2, v3);
            } else {
                *(u32*)(C16 + (size_t)row0 * N + col)       = packh2(v0, v1);
                *(u32*)(C16 + (size_t)(row0 + 8) * N + col) = packh2(v2, v3);
            }
        }
    }
}

// ---------------------------------------------------------------------------
// Attention: mma.sync fp16 single-pass. Q fragments register-resident,
// K row-major (ldmatrix), V row-major (ldmatrix.trans).
// Block = 64 queries x one (b,h), 4 warps, 2 CTAs/SM.
// ---------------------------------------------------------------------------
#define AT_BKP 136
#define K_OFF  0
#define V_OFF  (64 * AT_BKP)
#define ATT_SMEM (2 * 64 * AT_BKP * 2)

__global__ __launch_bounds__(128, 2) void attn_mma_kernel(
    const __half* __restrict__ q16, const __half* __restrict__ kv16,
    __half* __restrict__ y16)
{
    extern __shared__ __half sm[];
    const u32 smb = smem_u32(sm);
    const int tid = threadIdx.x;
    const int w = tid >> 5, lane = tid & 31;
    const int g = lane >> 2, c0 = (lane & 3) * 2;
    const int lrow = lane & 7, grp = lane >> 3;
    const int bhp = blockIdx.y;
    const int b = bhp >> 4, h = bhp & 15;
    const int kv_h = h >> 2;
    const int q0 = blockIdx.x << 6;
    int ls = q0 - WINDOW_ + 1; if (ls < NMETA_) ls = NMETA_;
    const int kend = q0 + 64;
    const float scale = 0.088388347648318447f;

    // Stage Q into K region, extract fragments to registers
#pragma unroll
    for (int it = 0; it < 8; it++) {
        int fi = tid + it * 128;
        int r = fi >> 4, q8 = fi & 15;
        size_t ga = ((size_t)(b * S_ + q0 + r) * NH_ + h) * HD_ + q8 * 8;
        *(uint4*)&sm[K_OFF + r * AT_BKP + q8 * 8] = *(const uint4*)(q16 + ga);
    }
    __syncthreads();

    u32 qf[8][4];
#pragma unroll
    for (int ks = 0; ks < 8; ks++) {
        u32 off = (u32)((w * 16 + (grp & 1) * 8 + lrow) * AT_BKP
                        + ks * 16 + (grp >> 1) * 8) * 2;
        ldsm_x4(qf[ks], smb + K_OFF * 2 + off);
    }

    float m0 = -1e30f, m1 = -1e30f, l0 = 0.f, l1 = 0.f;
    float o[16][4];
#pragma unroll
    for (int i = 0; i < 16; i++)
#pragma unroll
        for (int e = 0; e < 4; e++) o[i][e] = 0.f;

    const int qp0 = q0 + w * 16 + g;
    const int qp1 = qp0 + 8;
    const int nB = (kend - ls + 63) >> 6;

    for (int t = -1; t < nB; t++) {
        const int kbase = (t < 0) ? 0 : (ls + (t << 6));
        int kcnt = (t < 0) ? NMETA_ : (kend - kbase);
        if (kcnt > 64) kcnt = 64;

        __syncthreads();
#pragma unroll
        for (int it = 0; it < 8; it++) {
            int fi = tid + it * 128;
            int r = fi >> 4, q8 = fi & 15;
            uint4 k4 = make_uint4(0, 0, 0, 0), v4 = k4;
            if (r < kcnt) {
                size_t base = (size_t)(b * S_ + kbase + r) * 1024 + kv_h * 128 + q8 * 8;
                k4 = *(const uint4*)(kv16 + base);
                v4 = *(const uint4*)(kv16 + base + 512);
            }
            int so = r * AT_BKP + q8 * 8;
            *(uint4*)&sm[K_OFF + so] = k4;
            *(uint4*)&sm[V_OFF + so] = v4;
        }
        __syncthreads();

        // --- QK^T single pass ---
        float s[8][4];
#pragma unroll
        for (int nf = 0; nf < 8; nf++)
#pragma unroll
            for (int e = 0; e < 4; e++) s[nf][e] = 0.f;

#pragma unroll
        for (int ks = 0; ks < 8; ks++) {
            const int kk = ks * 16;
#pragma unroll
            for (int nfp = 0; nfp < 4; nfp++) {
                u32 off = (u32)((nfp * 16 + (grp >> 1) * 8 + lrow) * AT_BKP
                                + kk + (grp & 1) * 8) * 2;
                u32 k2[4];
                ldsm_x4(k2, smb + K_OFF * 2 + off);
                mma16816(s[2 * nfp],     qf[ks], &k2[0]);
                mma16816(s[2 * nfp + 1], qf[ks], &k2[2]);
            }
        }

        // --- Mask + scale + online softmax ---
        float mx0 = -1e30f, mx1 = -1e30f;
#pragma unroll
        for (int nf = 0; nf < 8; nf++) {
#pragma unroll
            for (int e = 0; e < 4; e++) {
                int col = nf * 8 + c0 + (e & 1);
                int kpos = kbase + col;
                int qp = (e < 2) ? qp0 : qp1;
                bool ok = (col < kcnt) && (kpos <= qp) &&
                          ((kpos >= qp - (WINDOW_ - 1)) || (kpos < NMETA_));
                float v = ok ? s[nf][e] * scale : -1e30f;
                s[nf][e] = v;
                if (e < 2) mx0 = fmaxf(mx0, v); else mx1 = fmaxf(mx1, v);
            }
        }
        mx0 = fmaxf(mx0, __shfl_xor_sync(0xffffffffu, mx0, 1));
        mx0 = fmaxf(mx0, __shfl_xor_sync(0xffffffffu, mx0, 2));
        mx1 = fmaxf(mx1, __shfl_xor_sync(0xffffffffu, mx1, 1));
        mx1 = fmaxf(mx1, __shfl_xor_sync(0xffffffffu, mx1, 2));

        float mn0 = fmaxf(m0, mx0), mn1 = fmaxf(m1, mx1);
        float f0 = __expf(m0 - mn0), f1 = __expf(m1 - mn1);
        float rs0 = 0.f, rs1 = 0.f;
#pragma unroll
        for (int nf = 0; nf < 8; nf++) {
            float p0 = __expf(s[nf][0] - mn0);
            float p1 = __expf(s[nf][1] - mn0);
            float p2 = __expf(s[nf][2] - mn1);
            float p3 = __expf(s[nf][3] - mn1);
            s[nf][0] = p0; s[nf][1] = p1; s[nf][2] = p2; s[nf][3] = p3;
            rs0 += p0 + p1; rs1 += p2 + p3;
        }
        rs0 += __shfl_xor_sync(0xffffffffu, rs0, 1);
        rs0 += __shfl_xor_sync(0xffffffffu, rs0, 2);
        rs1 += __shfl_xor_sync(0xffffffffu, rs1, 1);
        rs1 += __shfl_xor_sync(0xffffffffu, rs1, 2);
        l0 = l0 * f0 + rs0; m0 = mn0;
        l1 = l1 * f1 + rs1; m1 = mn1;
#pragma unroll
        for (int nf = 0; nf < 16; nf++) {
            o[nf][0] *= f0; o[nf][1] *= f0;
            o[nf][2] *= f1; o[nf][3] *= f1;
        }

        // --- P @ V single pass: A = P (registers, fp16), B = V (ldmatrix.trans) ---
#pragma unroll
        for (int ks = 0; ks < 4; ks++) {
            u32 ph[4];
            ph[0] = packh2(s[2 * ks][0],     s[2 * ks][1]);
            ph[1] = packh2(s[2 * ks][2],     s[2 * ks][3]);
            ph[2] = packh2(s[2 * ks + 1][0], s[2 * ks + 1][1]);
            ph[3] = packh2(s[2 * ks + 1][2], s[2 * ks + 1][3]);
            const int kk = ks * 16;
#pragma unroll
            for (int nfp = 0; nfp < 8; nfp++) {
                u32 off = (u32)((kk + (grp & 1) * 8 + lrow) * AT_BKP
                                + nfp * 16 + (grp >> 1) * 8) * 2;
                u32 v2[4];
                ldsm_x4_t(v2, smb + V_OFF * 2 + off);
                mma16816(o[2 * nfp],     ph, &v2[0]);
                mma16816(o[2 * nfp + 1], ph, &v2[2]);
            }
        }
    }

    // Epilogue: normalize, fp16 store y[b, q, h, :]
    float i0 = 1.0f / l0, i1 = 1.0f / l1;
    const int row0 = q0 + w * 16 + g;
#pragma unroll
    for (int nf = 0; nf < 16; nf++) {
        int col = nf * 8 + c0;
        size_t a0 = ((size_t)(b * S_ + row0) * NH_ + h) * HD_ + col;
        size_t a1 = ((size_t)(b * S_ + row0 + 8) * NH_ + h) * HD_ + col;
        *(u32*)(y16 + a0) = packh2(o[nf][0] * i0, o[nf][1] * i0);
        *(u32*)(y16 + a1) = packh2(o[nf][2] * i1, o[nf][3] * i1);
    }
}

// ---------------------------------------------------------------------------
// Launch
// ---------------------------------------------------------------------------
extern "C" void kernel_launch(void* const* d_in, const int* in_sizes, int n_in,
                              void* d_out, int out_size)
{
    const float* x   = (const float*)d_in[0];
    const float* Wq  = (const float*)d_in[1];
    const float* bq  = (const float*)d_in[2];
    const float* Wkv = (const float*)d_in[3];
    const float* bkv = (const float*)d_in[4];
    const float* Wo  = (const float*)d_in[5];
    const float* bo  = (const float*)d_in[6];
    float* out = (float*)d_out;

    __half *x16, *q16, *kv16, *y16, *wqt, *wkvt, *wot;
    float2* tab;
    cudaGetSymbolAddress((void**)&x16,  g_x16);
    cudaGetSymbolAddress((void**)&q16,  g_q16);
    cudaGetSymbolAddress((void**)&kv16, g_kv16);
    cudaGetSymbolAddress((void**)&y16,  g_y16);
    cudaGetSymbolAddress((void**)&wqt,  g_wqt);
    cudaGetSymbolAddress((void**)&wkvt, g_wkvt);
    cudaGetSymbolAddress((void**)&wot,  g_wot);
    cudaGetSymbolAddress((void**)&tab,  g_ropetab);

    const int M = B_ * S_;
    const int n4 = (B_ * S_ * E_) / 4;

    convert_kernel<<<n4 / 256, 256>>>(x, x16, n4);
    transpose_convert<<<dim3(E_ / 32, E_ / 32), dim3(32, 8)>>>(Wq, wqt, E_, E_);
    transpose_convert<<<dim3(KVOUT_ / 32, E_ / 32), dim3(32, 8)>>>(Wkv, wkvt, E_, KVOUT_);
    transpose_convert<<<dim3(E_ / 32, E_ / 32), dim3(32, 8)>>>(Wo, wot, E_, E_);
    rope_table_kernel<<<(S_ * 64) / 256, 256>>>(tab);

    cudaFuncSetAttribute(mma_gemm_kernel, cudaFuncAttributeMaxDynamicSharedMemorySize,
                         GT_SMEM);
    cudaFuncSetAttribute(attn_mma_kernel, cudaFuncAttributeMaxDynamicSharedMemorySize,
                         ATT_SMEM);

    // q = x @ Wq + bq  (+RoPE, fp16 out)
    mma_gemm_kernel<<<dim3(E_ / 128, M / 128), 128, GT_SMEM>>>(
        x16, wqt, bq, nullptr, q16, tab, M, E_, E_, 1, 1);
    // kv = x @ Wkv + bkv  (+RoPE on K half, fp16 out)
    mma_gemm_kernel<<<dim3(KVOUT_ / 128, M / 128), 128, GT_SMEM>>>(
        x16, wkvt, bkv, nullptr, kv16, tab, M, KVOUT_, E_, 2, 1);

    // attention (tensor-core fp16 single-pass)
    attn_mma_kernel<<<dim3(S_ / 64, B_ * NH_), 128, ATT_SMEM>>>(q16, kv16, y16);

    // out = y @ Wo + bo  (fp32 out)
    mma_gemm_kernel<<<dim3(E_ / 128, M / 128), 128, GT_SMEM>>>(
        y16, wot, bo, out, nullptr, tab, M, E_, E_, 0, 0);
}

// round 9
// speedup vs baseline: 7.8857x; 1.2152x over previous
#include <cuda_runtime.h>
#include <cuda_fp16.h>
#include <math.h>

typedef unsigned int u32;

// Problem constants
#define B_      2
#define S_      4096
#define E_      2048
#define NH_     16
#define HD_     128
#define NKV_    4
#define KVOUT_  1024
#define QKVN_   3072
#define WINDOW_ 512
#define NMETA_  16

// ---------------------------------------------------------------------------
// Scratch (device globals)
// ---------------------------------------------------------------------------
__device__ __half g_x16 [B_ * S_ * E_];
__device__ __half g_q16 [B_ * S_ * E_];
__device__ __half g_kv16[B_ * S_ * KVOUT_];
__device__ __half g_y16 [B_ * S_ * E_];
__device__ __half g_wqkvt[QKVN_ * E_];     // [Wq^T ; Wkv^T] rows 0..3071
__device__ __half g_wot [E_ * E_];
__device__ float  g_bqkv[QKVN_];
__device__ float2 g_ropetab[S_ * 64];

// ---------------------------------------------------------------------------
// Helpers
// ---------------------------------------------------------------------------
__device__ __forceinline__ u32 smem_u32(const void* p) {
    u32 a;
    asm("{ .reg .u64 t; cvta.to.shared.u64 t, %1; cvt.u32.u64 %0, t; }"
        : "=r"(a) : "l"(p));
    return a;
}

__device__ __forceinline__ void mma16816(float* d, const u32* a, const u32* b)
{
    asm volatile(
        "mma.sync.aligned.m16n8k16.row.col.f32.f16.f16.f32 "
        "{%0,%1,%2,%3}, {%4,%5,%6,%7}, {%8,%9}, {%0,%1,%2,%3};"
        : "+f"(d[0]), "+f"(d[1]), "+f"(d[2]), "+f"(d[3])
        : "r"(a[0]), "r"(a[1]), "r"(a[2]), "r"(a[3]), "r"(b[0]), "r"(b[1]));
}

__device__ __forceinline__ void ldsm_x4(u32* r, u32 addr)
{
    asm volatile("ldmatrix.sync.aligned.m8n8.x4.shared.b16 {%0,%1,%2,%3}, [%4];"
        : "=r"(r[0]), "=r"(r[1]), "=r"(r[2]), "=r"(r[3]) : "r"(addr));
}

__device__ __forceinline__ void ldsm_x4_t(u32* r, u32 addr)
{
    asm volatile("ldmatrix.sync.aligned.m8n8.x4.trans.shared.b16 {%0,%1,%2,%3}, [%4];"
        : "=r"(r[0]), "=r"(r[1]), "=r"(r[2]), "=r"(r[3]) : "r"(addr));
}

__device__ __forceinline__ u32 packh2(float x, float y)
{
    __half2 h = __floats2half2_rn(x, y);
    return *(u32*)&h;
}

#define CP_ASYNC16(dst, src) \
    asm volatile("cp.async.cg.shared.global [%0], [%1], 16;" :: "r"(dst), "l"(src))
#define CP_ASYNC16Z(dst, src, sz) \
    asm volatile("cp.async.cg.shared.global [%0], [%1], 16, %2;" \
                 :: "r"(dst), "l"(src), "r"(sz))
#define CP_COMMIT() asm volatile("cp.async.commit_group;")
#define CP_WAIT1()  asm volatile("cp.async.wait_group 1;")
#define CP_WAIT0()  asm volatile("cp.async.wait_group 0;")

// ---------------------------------------------------------------------------
// Prep kernels
// ---------------------------------------------------------------------------
__global__ void convert_kernel(const float* __restrict__ in,
                               __half* __restrict__ out, int n4)
{
    int i = blockIdx.x * 256 + threadIdx.x;
    if (i >= n4) return;
    float4 v = ((const float4*)in)[i];
    u32* O = (u32*)out;
    O[i * 2]     = packh2(v.x, v.y);
    O[i * 2 + 1] = packh2(v.z, v.w);
}

__global__ void transpose_convert(const float* __restrict__ W,
                                  __half* __restrict__ T, int K, int N)
{
    __shared__ float t[32][33];
    int n0 = blockIdx.x * 32, k0 = blockIdx.y * 32;
    for (int i = threadIdx.y; i < 32; i += 8)
        t[i][threadIdx.x] = W[(size_t)(k0 + i) * N + n0 + threadIdx.x];
    __syncthreads();
    for (int i = threadIdx.y; i < 32; i += 8)
        T[(size_t)(n0 + i) * K + k0 + threadIdx.x] =
            __float2half_rn(t[threadIdx.x][i]);
}

__global__ void concat_bias_kernel(const float* __restrict__ bq,
                                   const float* __restrict__ bkv,
                                   float* __restrict__ out)
{
    int i = blockIdx.x * 256 + threadIdx.x;
    if (i < E_) out[i] = bq[i];
    else if (i < QKVN_) out[i] = bkv[i - E_];
}

__global__ void rope_table_kernel(float2* tab)
{
    int idx = blockIdx.x * 256 + threadIdx.x;
    if (idx >= S_ * 64) return;
    int pos = idx >> 6, i = idx & 63;
    float inv = (float)exp(-(double)i * (9.210340371976184 / 64.0));
    float ang = (float)pos * inv;
    tab[idx] = make_float2(cosf(ang), sinf(ang));
}

// ---------------------------------------------------------------------------
// mma.sync fp16 GEMM. Block 128x128x64, 4 warps (2m x 2n) of 64x64 tiles,
// cp.async 2-stage, 2 CTAs/SM.
// mode 0: fp32 out (out-proj). mode 1: fused qkv -> q16 (rope all) +
//         kv16 (rope on K half).
// ---------------------------------------------------------------------------
#define BKP       72
#define TILE_ELEM (128 * BKP)
#define STAGE_ELEM (2 * TILE_ELEM)
#define GT_SMEM   (2 * STAGE_ELEM * 2)

__global__ __launch_bounds__(128, 2) void mma_gemm_kernel(
    const __half* __restrict__ A, const __half* __restrict__ Bm,
    const float* __restrict__ bias, float* __restrict__ Cf,
    __half* __restrict__ Cq, __half* __restrict__ Ckv,
    const float2* __restrict__ tab, int M, int N, int K, int mode)
{
    extern __shared__ __half sm[];
    const u32 sbase = smem_u32(sm);
    const int tid = threadIdx.x;
    const int wid = tid >> 5, lane = tid & 31;
    const int wm = wid & 1, wn = wid >> 1;
    const int m0 = blockIdx.y * 128;
    const int n0 = blockIdx.x * 128;
    const int g  = lane >> 2;
    const int c0 = (lane & 3) * 2;
    const int lrow = lane & 7, grp = lane >> 3;

    auto load_stage = [&](int c, int stage) {
        const int k0 = c * 64;
        const u32 sb = sbase + stage * STAGE_ELEM * 2;
#pragma unroll
        for (int i = 0; i < 8; i++) {
            int idx = tid + i * 128;            // 0..1023
            int row = idx >> 3, q8 = idx & 7;
            u32 soff = (u32)(row * BKP + q8 * 8) * 2;
            size_t ga = (size_t)(m0 + row) * K + k0 + q8 * 8;
            size_t gb = (size_t)(n0 + row) * K + k0 + q8 * 8;
            CP_ASYNC16(sb + soff,                 (const char*)(A + ga));
            CP_ASYNC16(sb + TILE_ELEM * 2 + soff, (const char*)(Bm + gb));
        }
    };

    float acc[4][8][4];
#pragma unroll
    for (int i = 0; i < 4; i++)
#pragma unroll
        for (int j = 0; j < 8; j++)
#pragma unroll
            for (int e = 0; e < 4; e++) acc[i][j][e] = 0.f;

    const int nc = K >> 6;
    load_stage(0, 0);
    CP_COMMIT();

    for (int c = 0; c < nc; c++) {
        if (c + 1 < nc) {
            load_stage(c + 1, (c + 1) & 1);
            CP_COMMIT();
            CP_WAIT1();
        } else {
            CP_WAIT0();
        }
        __syncthreads();

        const u32 st = sbase + (c & 1) * STAGE_ELEM * 2;
        const u32 sA = st;
        const u32 sB = st + TILE_ELEM * 2;

#pragma unroll
        for (int kh = 0; kh < 4; kh++) {
            const int kk = kh * 16;
            u32 bfr[8][2];
#pragma unroll
            for (int nfp = 0; nfp < 4; nfp++) {
                u32 off = (u32)((wn * 64 + nfp * 16 + (grp >> 1) * 8 + lrow) * BKP
                                + kk + (grp & 1) * 8) * 2;
                ldsm_x4(&bfr[nfp * 2][0], sB + off);
            }
#pragma unroll
            for (int mf = 0; mf < 4; mf++) {
                u32 offa = (u32)((wm * 64 + mf * 16 + (grp & 1) * 8 + lrow) * BKP
                                 + kk + (grp >> 1) * 8) * 2;
                u32 a[4];
                ldsm_x4(a, sA + offa);
#pragma unroll
                for (int nf = 0; nf < 8; nf++)
                    mma16816(acc[mf][nf], a, bfr[nf]);
            }
        }
        __syncthreads();
    }

    // Epilogue
#pragma unroll
    for (int mf = 0; mf < 4; mf++) {
        int row0 = m0 + wm * 64 + mf * 16 + g;
        int pos0 = row0 & (S_ - 1);
        int pos1 = (row0 + 8) & (S_ - 1);
#pragma unroll
        for (int nf = 0; nf < 8; nf++) {
            int col = n0 + wn * 64 + nf * 8 + c0;
            float b0 = bias[col], b1 = bias[col + 1];
            float v0 = acc[mf][nf][0] + b0, v1 = acc[mf][nf][1] + b1;
            float v2 = acc[mf][nf][2] + b0, v3 = acc[mf][nf][3] + b1;
            if (mode == 0) {
                *(float2*)(Cf + (size_t)row0 * N + col)       = make_float2(v0, v1);
                *(float2*)(Cf + (size_t)(row0 + 8) * N + col) = make_float2(v2, v3);
            } else {
                // fused qkv: rope on q (col<2048) and K half (col<2560)
                bool do_rope = (col < 2560);
                if (do_rope) {
                    int ti = (col & 127) >> 1;
                    float2 cs0 = tab[pos0 * 64 + ti];
                    float2 cs1 = tab[pos1 * 64 + ti];
                    float t0 = v0, t1 = v1;
                    v0 = t0 * cs0.x - t1 * cs0.y;
                    v1 = t1 * cs0.x + t0 * cs0.y;
                    float t2 = v2, t3 = v3;
                    v2 = t2 * cs1.x - t3 * cs1.y;
                    v3 = t3 * cs1.x + t2 * cs1.y;
                }
                if (col < E_) {
                    *(u32*)(Cq + (size_t)row0 * E_ + col)       = packh2(v0, v1);
                    *(u32*)(Cq + (size_t)(row0 + 8) * E_ + col) = packh2(v2, v3);
                } else {
                    int c2 = col - E_;
                    *(u32*)(Ckv + (size_t)row0 * KVOUT_ + c2)       = packh2(v0, v1);
                    *(u32*)(Ckv + (size_t)(row0 + 8) * KVOUT_ + c2) = packh2(v2, v3);
                }
            }
        }
    }
}

// ---------------------------------------------------------------------------
// Attention: mma.sync fp16 single-pass, cp.async double-buffered K/V tiles.
// Block = 64 queries x one (b,h), 4 warps, 2 CTAs/SM.
// ---------------------------------------------------------------------------
#define AT_BKP   136
#define AT_TILE  (64 * AT_BKP)          // halves per K (or V) tile
#define AT_STAGE (2 * AT_TILE)          // K + V
#define ATT_SMEM (2 * AT_STAGE * 2)     // 2 stages, bytes

__global__ __launch_bounds__(128, 2) void attn_mma_kernel(
    const __half* __restrict__ q16, const __half* __restrict__ kv16,
    __half* __restrict__ y16)
{
    extern __shared__ __half sm[];
    const u32 smb = smem_u32(sm);
    const int tid = threadIdx.x;
    const int w = tid >> 5, lane = tid & 31;
    const int g = lane >> 2, c0 = (lane & 3) * 2;
    const int lrow = lane & 7, grp = lane >> 3;
    const int bhp = blockIdx.y;
    const int b = bhp >> 4, h = bhp & 15;
    const int kv_h = h >> 2;
    const int q0 = blockIdx.x << 6;
    int ls = q0 - WINDOW_ + 1; if (ls < NMETA_) ls = NMETA_;
    const int kend = q0 + 64;
    const float scale = 0.088388347648318447f;

    // ---- Stage Q into stage0 K region via cp.async, extract fragments ----
#pragma unroll
    for (int it = 0; it < 8; it++) {
        int fi = tid + it * 128;
        int r = fi >> 4, q8 = fi & 15;
        size_t ga = ((size_t)(b * S_ + q0 + r) * NH_ + h) * HD_ + q8 * 8;
        CP_ASYNC16(smb + (u32)(r * AT_BKP + q8 * 8) * 2, (const char*)(q16 + ga));
    }
    CP_COMMIT(); CP_WAIT0();
    __syncthreads();

    u32 qf[8][4];
#pragma unroll
    for (int ks = 0; ks < 8; ks++) {
        u32 off = (u32)((w * 16 + (grp & 1) * 8 + lrow) * AT_BKP
                        + ks * 16 + (grp >> 1) * 8) * 2;
        ldsm_x4(qf[ks], smb + off);
    }
    __syncthreads();   // all warps done reading Q before tile 0 overwrites

    // ---- Tile loader (t=0 is meta, t>=1 window tiles) ----
    auto load_tile = [&](int t, int stage) {
        int kb = (t == 0) ? 0 : (ls + ((t - 1) << 6));
        int kc = (t == 0) ? NMETA_ : (kend - kb);
        if (kc > 64) kc = 64;
        u32 sK = smb + (u32)(stage * AT_STAGE) * 2;
        u32 sV = sK + AT_TILE * 2;
#pragma unroll
        for (int it = 0; it < 8; it++) {
            int fi = tid + it * 128;
            int r = fi >> 4, q8 = fi & 15;
            int sz = (r < kc) ? 16 : 0;
            int rr = (r < kc) ? r : 0;
            size_t base = (size_t)(b * S_ + kb + rr) * 1024 + kv_h * 128 + q8 * 8;
            u32 off = (u32)(r * AT_BKP + q8 * 8) * 2;
            CP_ASYNC16Z(sK + off, (const char*)(kv16 + base), sz);
            CP_ASYNC16Z(sV + off, (const char*)(kv16 + base + 512), sz);
        }
    };

    float m0 = -1e30f, m1 = -1e30f, l0 = 0.f, l1 = 0.f;
    float o[16][4];
#pragma unroll
    for (int i = 0; i < 16; i++)
#pragma unroll
        for (int e = 0; e < 4; e++) o[i][e] = 0.f;

    const int qp0 = q0 + w * 16 + g;
    const int qp1 = qp0 + 8;
    const int nT = 1 + ((kend - ls + 63) >> 6);

    load_tile(0, 0);
    CP_COMMIT();

    for (int t = 0; t < nT; t++) {
        if (t + 1 < nT) {
            load_tile(t + 1, (t + 1) & 1);
            CP_COMMIT();
            CP_WAIT1();
        } else {
            CP_WAIT0();
        }
        __syncthreads();

        const int stage = t & 1;
        const u32 sK = smb + (u32)(stage * AT_STAGE) * 2;
        const u32 sV = sK + AT_TILE * 2;
        const int kbase = (t == 0) ? 0 : (ls + ((t - 1) << 6));
        int kcnt = (t == 0) ? NMETA_ : (kend - kbase);
        if (kcnt > 64) kcnt = 64;

        // --- QK^T single pass ---
        float s[8][4];
#pragma unroll
        for (int nf = 0; nf < 8; nf++)
#pragma unroll
            for (int e = 0; e < 4; e++) s[nf][e] = 0.f;

#pragma unroll
        for (int ks = 0; ks < 8; ks++) {
            const int kk = ks * 16;
#pragma unroll
            for (int nfp = 0; nfp < 4; nfp++) {
                u32 off = (u32)((nfp * 16 + (grp >> 1) * 8 + lrow) * AT_BKP
                                + kk + (grp & 1) * 8) * 2;
                u32 k2[4];
                ldsm_x4(k2, sK + off);
                mma16816(s[2 * nfp],     qf[ks], &k2[0]);
                mma16816(s[2 * nfp + 1], qf[ks], &k2[2]);
            }
        }

        // --- Mask + scale + online softmax ---
        float mx0 = -1e30f, mx1 = -1e30f;
#pragma unroll
        for (int nf = 0; nf < 8; nf++) {
#pragma unroll
            for (int e = 0; e < 4; e++) {
                int col = nf * 8 + c0 + (e & 1);
                int kpos = kbase + col;
                int qp = (e < 2) ? qp0 : qp1;
                bool ok = (col < kcnt) && (kpos <= qp) &&
                          ((kpos >= qp - (WINDOW_ - 1)) || (kpos < NMETA_));
                float v = ok ? s[nf][e] * scale : -1e30f;
                s[nf][e] = v;
                if (e < 2) mx0 = fmaxf(mx0, v); else mx1 = fmaxf(mx1, v);
            }
        }
        mx0 = fmaxf(mx0, __shfl_xor_sync(0xffffffffu, mx0, 1));
        mx0 = fmaxf(mx0, __shfl_xor_sync(0xffffffffu, mx0, 2));
        mx1 = fmaxf(mx1, __shfl_xor_sync(0xffffffffu, mx1, 1));
        mx1 = fmaxf(mx1, __shfl_xor_sync(0xffffffffu, mx1, 2));

        float mn0 = fmaxf(m0, mx0), mn1 = fmaxf(m1, mx1);
        float f0 = __expf(m0 - mn0), f1 = __expf(m1 - mn1);
        float rs0 = 0.f, rs1 = 0.f;
#pragma unroll
        for (int nf = 0; nf < 8; nf++) {
            float p0 = __expf(s[nf][0] - mn0);
            float p1 = __expf(s[nf][1] - mn0);
            float p2 = __expf(s[nf][2] - mn1);
            float p3 = __expf(s[nf][3] - mn1);
            s[nf][0] = p0; s[nf][1] = p1; s[nf][2] = p2; s[nf][3] = p3;
            rs0 += p0 + p1; rs1 += p2 + p3;
        }
        rs0 += __shfl_xor_sync(0xffffffffu, rs0, 1);
        rs0 += __shfl_xor_sync(0xffffffffu, rs0, 2);
        rs1 += __shfl_xor_sync(0xffffffffu, rs1, 1);
        rs1 += __shfl_xor_sync(0xffffffffu, rs1, 2);
        l0 = l0 * f0 + rs0; m0 = mn0;
        l1 = l1 * f1 + rs1; m1 = mn1;
#pragma unroll
        for (int nf = 0; nf < 16; nf++) {
            o[nf][0] *= f0; o[nf][1] *= f0;
            o[nf][2] *= f1; o[nf][3] *= f1;
        }

        // --- P @ V single pass ---
#pragma unroll
        for (int ks = 0; ks < 4; ks++) {
            u32 ph[4];
            ph[0] = packh2(s[2 * ks][0],     s[2 * ks][1]);
            ph[1] = packh2(s[2 * ks][2],     s[2 * ks][3]);
            ph[2] = packh2(s[2 * ks + 1][0], s[2 * ks + 1][1]);
            ph[3] = packh2(s[2 * ks + 1][2], s[2 * ks + 1][3]);
            const int kk = ks * 16;
#pragma unroll
            for (int nfp = 0; nfp < 8; nfp++) {
                u32 off = (u32)((kk + (grp & 1) * 8 + lrow) * AT_BKP
                                + nfp * 16 + (grp >> 1) * 8) * 2;
                u32 v2[4];
                ldsm_x4_t(v2, sV + off);
                mma16816(o[2 * nfp],     ph, &v2[0]);
                mma16816(o[2 * nfp + 1], ph, &v2[2]);
            }
        }
        __syncthreads();
    }

    // Epilogue: normalize, fp16 store y[b, q, h, :]
    float i0 = 1.0f / l0, i1 = 1.0f / l1;
    const int row0 = q0 + w * 16 + g;
#pragma unroll
    for (int nf = 0; nf < 16; nf++) {
        int col = nf * 8 + c0;
        size_t a0 = ((size_t)(b * S_ + row0) * NH_ + h) * HD_ + col;
        size_t a1 = ((size_t)(b * S_ + row0 + 8) * NH_ + h) * HD_ + col;
        *(u32*)(y16 + a0) = packh2(o[nf][0] * i0, o[nf][1] * i0);
        *(u32*)(y16 + a1) = packh2(o[nf][2] * i1, o[nf][3] * i1);
    }
}

// ---------------------------------------------------------------------------
// Launch
// ---------------------------------------------------------------------------
extern "C" void kernel_launch(void* const* d_in, const int* in_sizes, int n_in,
                              void* d_out, int out_size)
{
    const float* x   = (const float*)d_in[0];
    const float* Wq  = (const float*)d_in[1];
    const float* bq  = (const float*)d_in[2];
    const float* Wkv = (const float*)d_in[3];
    const float* bkv = (const float*)d_in[4];
    const float* Wo  = (const float*)d_in[5];
    const float* bo  = (const float*)d_in[6];
    float* out = (float*)d_out;

    __half *x16, *q16, *kv16, *y16, *wqkvt, *wot;
    float *bqkv;
    float2* tab;
    cudaGetSymbolAddress((void**)&x16,   g_x16);
    cudaGetSymbolAddress((void**)&q16,   g_q16);
    cudaGetSymbolAddress((void**)&kv16,  g_kv16);
    cudaGetSymbolAddress((void**)&y16,   g_y16);
    cudaGetSymbolAddress((void**)&wqkvt, g_wqkvt);
    cudaGetSymbolAddress((void**)&wot,   g_wot);
    cudaGetSymbolAddress((void**)&bqkv,  g_bqkv);
    cudaGetSymbolAddress((void**)&tab,   g_ropetab);

    const int M = B_ * S_;
    const int n4 = (B_ * S_ * E_) / 4;

    convert_kernel<<<n4 / 256, 256>>>(x, x16, n4);
    transpose_convert<<<dim3(E_ / 32, E_ / 32), dim3(32, 8)>>>(Wq, wqkvt, E_, E_);
    transpose_convert<<<dim3(KVOUT_ / 32, E_ / 32), dim3(32, 8)>>>(
        Wkv, wqkvt + (size_t)E_ * E_, E_, KVOUT_);
    transpose_convert<<<dim3(E_ / 32, E_ / 32), dim3(32, 8)>>>(Wo, wot, E_, E_);
    concat_bias_kernel<<<QKVN_ / 256, 256>>>(bq, bkv, bqkv);
    rope_table_kernel<<<(S_ * 64) / 256, 256>>>(tab);

    cudaFuncSetAttribute(mma_gemm_kernel, cudaFuncAttributeMaxDynamicSharedMemorySize,
                         GT_SMEM);
    cudaFuncSetAttribute(attn_mma_kernel, cudaFuncAttributeMaxDynamicSharedMemorySize,
                         ATT_SMEM);

    // fused [q | kv] = x @ [Wq | Wkv] + [bq | bkv]  (+RoPE, fp16 out)
    mma_gemm_kernel<<<dim3(QKVN_ / 128, M / 128), 128, GT_SMEM>>>(
        x16, wqkvt, bqkv, nullptr, q16, kv16, tab, M, QKVN_, E_, 1);

    // attention (tensor-core fp16, cp.async pipelined K/V)
    attn_mma_kernel<<<dim3(S_ / 64, B_ * NH_), 128, ATT_SMEM>>>(q16, kv16, y16);

    // out = y @ Wo + bo  (fp32 out)
    mma_gemm_kernel<<<dim3(E_ / 128, M / 128), 128, GT_SMEM>>>(
        y16, wot, bo, out, nullptr, nullptr, tab, M, E_, E_, 0);
}

// round 10
// speedup vs baseline: 8.0012x; 1.0146x over previous
#include <cuda_runtime.h>
#include <cuda_fp16.h>
#include <math.h>

typedef unsigned int u32;

// Problem constants
#define B_      2
#define S_      4096
#define E_      2048
#define NH_     16
#define HD_     128
#define NKV_    4
#define KVOUT_  1024
#define QKVN_   3072
#define WINDOW_ 512
#define NMETA_  16

// ---------------------------------------------------------------------------
// Scratch (device globals)
// ---------------------------------------------------------------------------
__device__ __half g_x16 [B_ * S_ * E_];
__device__ __half g_q16 [B_ * S_ * E_];
__device__ __half g_kv16[B_ * S_ * KVOUT_];
__device__ __half g_y16 [B_ * S_ * E_];
__device__ __half g_wqkvt[QKVN_ * E_];     // [Wq^T ; Wkv^T]
__device__ __half g_wot [E_ * E_];
__device__ float  g_bqkv[QKVN_];
__device__ float2 g_ropetab[S_ * 64];

// ---------------------------------------------------------------------------
// Helpers
// ---------------------------------------------------------------------------
__device__ __forceinline__ u32 smem_u32(const void* p) {
    u32 a;
    asm("{ .reg .u64 t; cvta.to.shared.u64 t, %1; cvt.u32.u64 %0, t; }"
        : "=r"(a) : "l"(p));
    return a;
}

__device__ __forceinline__ void mma16816(float* d, const u32* a, const u32* b)
{
    asm volatile(
        "mma.sync.aligned.m16n8k16.row.col.f32.f16.f16.f32 "
        "{%0,%1,%2,%3}, {%4,%5,%6,%7}, {%8,%9}, {%0,%1,%2,%3};"
        : "+f"(d[0]), "+f"(d[1]), "+f"(d[2]), "+f"(d[3])
        : "r"(a[0]), "r"(a[1]), "r"(a[2]), "r"(a[3]), "r"(b[0]), "r"(b[1]));
}

__device__ __forceinline__ void ldsm_x4(u32* r, u32 addr)
{
    asm volatile("ldmatrix.sync.aligned.m8n8.x4.shared.b16 {%0,%1,%2,%3}, [%4];"
        : "=r"(r[0]), "=r"(r[1]), "=r"(r[2]), "=r"(r[3]) : "r"(addr));
}

__device__ __forceinline__ void ldsm_x4_t(u32* r, u32 addr)
{
    asm volatile("ldmatrix.sync.aligned.m8n8.x4.trans.shared.b16 {%0,%1,%2,%3}, [%4];"
        : "=r"(r[0]), "=r"(r[1]), "=r"(r[2]), "=r"(r[3]) : "r"(addr));
}

__device__ __forceinline__ u32 packh2(float x, float y)
{
    __half2 h = __floats2half2_rn(x, y);
    return *(u32*)&h;
}

#define CP_ASYNC16(dst, src) \
    asm volatile("cp.async.cg.shared.global [%0], [%1], 16;" :: "r"(dst), "l"(src))
#define CP_ASYNC16Z(dst, src, sz) \
    asm volatile("cp.async.cg.shared.global [%0], [%1], 16, %2;" \
                 :: "r"(dst), "l"(src), "r"(sz))
#define CP_COMMIT() asm volatile("cp.async.commit_group;")
#define CP_WAIT1()  asm volatile("cp.async.wait_group 1;")
#define CP_WAIT0()  asm volatile("cp.async.wait_group 0;")

// ---------------------------------------------------------------------------
// Prep kernels
// ---------------------------------------------------------------------------
__global__ void convert_kernel(const float* __restrict__ in,
                               __half* __restrict__ out, int n4)
{
    int i = blockIdx.x * 256 + threadIdx.x;
    if (i >= n4) return;
    float4 v = ((const float4*)in)[i];
    u32* O = (u32*)out;
    O[i * 2]     = packh2(v.x, v.y);
    O[i * 2 + 1] = packh2(v.z, v.w);
}

// All three weight transposes in one launch (z selects the matrix)
__global__ void transpose_convert_all(const float* __restrict__ Wq,
                                      const float* __restrict__ Wkv,
                                      const float* __restrict__ Wo,
                                      __half* __restrict__ wqkvt,
                                      __half* __restrict__ wot)
{
    const float* W;
    __half* T;
    int N;
    int z = blockIdx.z;
    if (z == 0)      { W = Wq;  T = wqkvt;                    N = E_; }
    else if (z == 1) { W = Wkv; T = wqkvt + (size_t)E_ * E_;  N = KVOUT_; }
    else             { W = Wo;  T = wot;                      N = E_; }
    const int K = E_;

    __shared__ float t[32][33];
    int n0 = blockIdx.x * 32, k0 = blockIdx.y * 32;
    if (n0 >= N) return;
    for (int i = threadIdx.y; i < 32; i += 8)
        t[i][threadIdx.x] = W[(size_t)(k0 + i) * N + n0 + threadIdx.x];
    __syncthreads();
    for (int i = threadIdx.y; i < 32; i += 8)
        T[(size_t)(n0 + i) * K + k0 + threadIdx.x] =
            __float2half_rn(t[threadIdx.x][i]);
}

__global__ void concat_bias_kernel(const float* __restrict__ bq,
                                   const float* __restrict__ bkv,
                                   float* __restrict__ out)
{
    int i = blockIdx.x * 256 + threadIdx.x;
    if (i < E_) out[i] = bq[i];
    else if (i < QKVN_) out[i] = bkv[i - E_];
}

__global__ void rope_table_kernel(float2* tab)
{
    int idx = blockIdx.x * 256 + threadIdx.x;
    if (idx >= S_ * 64) return;
    int pos = idx >> 6, i = idx & 63;
    float inv = (float)exp(-(double)i * (9.210340371976184 / 64.0));
    float ang = (float)pos * inv;
    tab[idx] = make_float2(cosf(ang), sinf(ang));
}

// ---------------------------------------------------------------------------
// mma.sync fp16 GEMM. Block 128x128x64, 4 warps (2m x 2n) of 64x64 tiles,
// cp.async 3-stage pipeline, ONE __syncthreads per chunk, 2 CTAs/SM.
// mode 0: fp32 out. mode 1: fused qkv out (rope cols < 2560).
// ---------------------------------------------------------------------------
#define BKP       72
#define TILE_ELEM (128 * BKP)
#define STAGE_ELEM (2 * TILE_ELEM)
#define GT_SMEM   (3 * STAGE_ELEM * 2)

__global__ __launch_bounds__(128, 2) void mma_gemm_kernel(
    const __half* __restrict__ A, const __half* __restrict__ Bm,
    const float* __restrict__ bias, float* __restrict__ Cf,
    __half* __restrict__ Cq, __half* __restrict__ Ckv,
    const float2* __restrict__ tab, int M, int N, int K, int mode)
{
    extern __shared__ __half sm[];
    const u32 sbase = smem_u32(sm);
    const int tid = threadIdx.x;
    const int wid = tid >> 5, lane = tid & 31;
    const int wm = wid & 1, wn = wid >> 1;
    const int m0 = blockIdx.y * 128;
    const int n0 = blockIdx.x * 128;
    const int g  = lane >> 2;
    const int c0 = (lane & 3) * 2;
    const int lrow = lane & 7, grp = lane >> 3;

    auto load_stage = [&](int c, int stage) {
        const int k0 = c * 64;
        const u32 sb = sbase + stage * STAGE_ELEM * 2;
#pragma unroll
        for (int i = 0; i < 8; i++) {
            int idx = tid + i * 128;
            int row = idx >> 3, q8 = idx & 7;
            u32 soff = (u32)(row * BKP + q8 * 8) * 2;
            size_t ga = (size_t)(m0 + row) * K + k0 + q8 * 8;
            size_t gb = (size_t)(n0 + row) * K + k0 + q8 * 8;
            CP_ASYNC16(sb + soff,                 (const char*)(A + ga));
            CP_ASYNC16(sb + TILE_ELEM * 2 + soff, (const char*)(Bm + gb));
        }
    };

    float acc[4][8][4];
#pragma unroll
    for (int i = 0; i < 4; i++)
#pragma unroll
        for (int j = 0; j < 8; j++)
#pragma unroll
            for (int e = 0; e < 4; e++) acc[i][j][e] = 0.f;

    const int nc = K >> 6;           // >= 2 always (K = 2048)
    load_stage(0, 0); CP_COMMIT();
    load_stage(1, 1); CP_COMMIT();

    for (int c = 0; c < nc; c++) {
        if (c + 1 < nc) CP_WAIT1(); else CP_WAIT0();
        __syncthreads();             // all warps done with chunk c-1's stage
        if (c + 2 < nc) {            // prefetch into stage of chunk c-1 (free now)
            load_stage(c + 2, (c + 2) % 3);
            CP_COMMIT();
        }

        const u32 st = sbase + (u32)((c % 3) * STAGE_ELEM) * 2;
        const u32 sA = st;
        const u32 sB = st + TILE_ELEM * 2;

#pragma unroll
        for (int kh = 0; kh < 4; kh++) {
            const int kk = kh * 16;
            u32 bfr[8][2];
#pragma unroll
            for (int nfp = 0; nfp < 4; nfp++) {
                u32 off = (u32)((wn * 64 + nfp * 16 + (grp >> 1) * 8 + lrow) * BKP
                                + kk + (grp & 1) * 8) * 2;
                ldsm_x4(&bfr[nfp * 2][0], sB + off);
            }
#pragma unroll
            for (int mf = 0; mf < 4; mf++) {
                u32 offa = (u32)((wm * 64 + mf * 16 + (grp & 1) * 8 + lrow) * BKP
                                 + kk + (grp >> 1) * 8) * 2;
                u32 a[4];
                ldsm_x4(a, sA + offa);
#pragma unroll
                for (int nf = 0; nf < 8; nf++)
                    mma16816(acc[mf][nf], a, bfr[nf]);
            }
        }
    }

    // Epilogue (register-only inputs; no extra barrier needed)
#pragma unroll
    for (int mf = 0; mf < 4; mf++) {
        int row0 = m0 + wm * 64 + mf * 16 + g;
        int pos0 = row0 & (S_ - 1);
        int pos1 = (row0 + 8) & (S_ - 1);
#pragma unroll
        for (int nf = 0; nf < 8; nf++) {
            int col = n0 + wn * 64 + nf * 8 + c0;
            float b0 = bias[col], b1 = bias[col + 1];
            float v0 = acc[mf][nf][0] + b0, v1 = acc[mf][nf][1] + b1;
            float v2 = acc[mf][nf][2] + b0, v3 = acc[mf][nf][3] + b1;
            if (mode == 0) {
                *(float2*)(Cf + (size_t)row0 * N + col)       = make_float2(v0, v1);
                *(float2*)(Cf + (size_t)(row0 + 8) * N + col) = make_float2(v2, v3);
            } else {
                bool do_rope = (col < 2560);
                if (do_rope) {
                    int ti = (col & 127) >> 1;
                    float2 cs0 = tab[pos0 * 64 + ti];
                    float2 cs1 = tab[pos1 * 64 + ti];
                    float t0 = v0, t1 = v1;
                    v0 = t0 * cs0.x - t1 * cs0.y;
                    v1 = t1 * cs0.x + t0 * cs0.y;
                    float t2 = v2, t3 = v3;
                    v2 = t2 * cs1.x - t3 * cs1.y;
                    v3 = t3 * cs1.x + t2 * cs1.y;
                }
                if (col < E_) {
                    *(u32*)(Cq + (size_t)row0 * E_ + col)       = packh2(v0, v1);
                    *(u32*)(Cq + (size_t)(row0 + 8) * E_ + col) = packh2(v2, v3);
                } else {
                    int c2 = col - E_;
                    *(u32*)(Ckv + (size_t)row0 * KVOUT_ + c2)       = packh2(v0, v1);
                    *(u32*)(Ckv + (size_t)(row0 + 8) * KVOUT_ + c2) = packh2(v2, v3);
                }
            }
        }
    }
}

// ---------------------------------------------------------------------------
// Attention: mma.sync fp16, cp.async 3-stage K/V pipeline, one barrier/tile.
// Block = 64 queries x one (b,h), 4 warps, 2 CTAs/SM.
// ---------------------------------------------------------------------------
#define AT_BKP   136
#define AT_TILE  (64 * AT_BKP)
#define AT_STAGE (2 * AT_TILE)
#define ATT_SMEM (3 * AT_STAGE * 2)

__global__ __launch_bounds__(128, 2) void attn_mma_kernel(
    const __half* __restrict__ q16, const __half* __restrict__ kv16,
    __half* __restrict__ y16)
{
    extern __shared__ __half sm[];
    const u32 smb = smem_u32(sm);
    const int tid = threadIdx.x;
    const int w = tid >> 5, lane = tid & 31;
    const int g = lane >> 2, c0 = (lane & 3) * 2;
    const int lrow = lane & 7, grp = lane >> 3;
    const int bhp = blockIdx.y;
    const int b = bhp >> 4, h = bhp & 15;
    const int kv_h = h >> 2;
    const int q0 = blockIdx.x << 6;
    int ls = q0 - WINDOW_ + 1; if (ls < NMETA_) ls = NMETA_;
    const int kend = q0 + 64;
    const float scale = 0.088388347648318447f;

    // ---- Stage Q via cp.async into stage0, extract fragments ----
#pragma unroll
    for (int it = 0; it < 8; it++) {
        int fi = tid + it * 128;
        int r = fi >> 4, q8 = fi & 15;
        size_t ga = ((size_t)(b * S_ + q0 + r) * NH_ + h) * HD_ + q8 * 8;
        CP_ASYNC16(smb + (u32)(r * AT_BKP + q8 * 8) * 2, (const char*)(q16 + ga));
    }
    CP_COMMIT(); CP_WAIT0();
    __syncthreads();

    u32 qf[8][4];
#pragma unroll
    for (int ks = 0; ks < 8; ks++) {
        u32 off = (u32)((w * 16 + (grp & 1) * 8 + lrow) * AT_BKP
                        + ks * 16 + (grp >> 1) * 8) * 2;
        ldsm_x4(qf[ks], smb + off);
    }
    __syncthreads();   // Q fully read before tile 0 overwrites stage 0

    auto load_tile = [&](int t, int stage) {
        int kb = (t == 0) ? 0 : (ls + ((t - 1) << 6));
        int kc = (t == 0) ? NMETA_ : (kend - kb);
        if (kc > 64) kc = 64;
        u32 sK = smb + (u32)(stage * AT_STAGE) * 2;
        u32 sV = sK + AT_TILE * 2;
#pragma unroll
        for (int it = 0; it < 8; it++) {
            int fi = tid + it * 128;
            int r = fi >> 4, q8 = fi & 15;
            int sz = (r < kc) ? 16 : 0;
            int rr = (r < kc) ? r : 0;
            size_t base = (size_t)(b * S_ + kb + rr) * 1024 + kv_h * 128 + q8 * 8;
            u32 off = (u32)(r * AT_BKP + q8 * 8) * 2;
            CP_ASYNC16Z(sK + off, (const char*)(kv16 + base), sz);
            CP_ASYNC16Z(sV + off, (const char*)(kv16 + base + 512), sz);
        }
    };

    float m0 = -1e30f, m1 = -1e30f, l0 = 0.f, l1 = 0.f;
    float o[16][4];
#pragma unroll
    for (int i = 0; i < 16; i++)
#pragma unroll
        for (int e = 0; e < 4; e++) o[i][e] = 0.f;

    const int qp0 = q0 + w * 16 + g;
    const int qp1 = qp0 + 8;
    const int nT = 1 + ((kend - ls + 63) >> 6);   // >= 2 always

    load_tile(0, 0); CP_COMMIT();
    load_tile(1, 1); CP_COMMIT();

    for (int t = 0; t < nT; t++) {
        if (t + 1 < nT) CP_WAIT1(); else CP_WAIT0();
        __syncthreads();
        if (t + 2 < nT) {
            load_tile(t + 2, (t + 2) % 3);
            CP_COMMIT();
        }

        const u32 sK = smb + (u32)((t % 3) * AT_STAGE) * 2;
        const u32 sV = sK + AT_TILE * 2;
        const int kbase = (t == 0) ? 0 : (ls + ((t - 1) << 6));
        int kcnt = (t == 0) ? NMETA_ : (kend - kbase);
        if (kcnt > 64) kcnt = 64;

        // --- QK^T single pass ---
        float s[8][4];
#pragma unroll
        for (int nf = 0; nf < 8; nf++)
#pragma unroll
            for (int e = 0; e < 4; e++) s[nf][e] = 0.f;

#pragma unroll
        for (int ks = 0; ks < 8; ks++) {
            const int kk = ks * 16;
#pragma unroll
            for (int nfp = 0; nfp < 4; nfp++) {
                u32 off = (u32)((nfp * 16 + (grp >> 1) * 8 + lrow) * AT_BKP
                                + kk + (grp & 1) * 8) * 2;
                u32 k2[4];
                ldsm_x4(k2, sK + off);
                mma16816(s[2 * nfp],     qf[ks], &k2[0]);
                mma16816(s[2 * nfp + 1], qf[ks], &k2[2]);
            }
        }

        // --- Mask + scale + online softmax ---
        float mx0 = -1e30f, mx1 = -1e30f;
#pragma unroll
        for (int nf = 0; nf < 8; nf++) {
#pragma unroll
            for (int e = 0; e < 4; e++) {
                int col = nf * 8 + c0 + (e & 1);
                int kpos = kbase + col;
                int qp = (e < 2) ? qp0 : qp1;
                bool ok = (col < kcnt) && (kpos <= qp) &&
                          ((kpos >= qp - (WINDOW_ - 1)) || (kpos < NMETA_));
                float v = ok ? s[nf][e] * scale : -1e30f;
                s[nf][e] = v;
                if (e < 2) mx0 = fmaxf(mx0, v); else mx1 = fmaxf(mx1, v);
            }
        }
        mx0 = fmaxf(mx0, __shfl_xor_sync(0xffffffffu, mx0, 1));
        mx0 = fmaxf(mx0, __shfl_xor_sync(0xffffffffu, mx0, 2));
        mx1 = fmaxf(mx1, __shfl_xor_sync(0xffffffffu, mx1, 1));
        mx1 = fmaxf(mx1, __shfl_xor_sync(0xffffffffu, mx1, 2));

        float mn0 = fmaxf(m0, mx0), mn1 = fmaxf(m1, mx1);
        float f0 = __expf(m0 - mn0), f1 = __expf(m1 - mn1);
        float rs0 = 0.f, rs1 = 0.f;
#pragma unroll
        for (int nf = 0; nf < 8; nf++) {
            float p0 = __expf(s[nf][0] - mn0);
            float p1 = __expf(s[nf][1] - mn0);
            float p2 = __expf(s[nf][2] - mn1);
            float p3 = __expf(s[nf][3] - mn1);
            s[nf][0] = p0; s[nf][1] = p1; s[nf][2] = p2; s[nf][3] = p3;
            rs0 += p0 + p1; rs1 += p2 + p3;
        }
        rs0 += __shfl_xor_sync(0xffffffffu, rs0, 1);
        rs0 += __shfl_xor_sync(0xffffffffu, rs0, 2);
        rs1 += __shfl_xor_sync(0xffffffffu, rs1, 1);
        rs1 += __shfl_xor_sync(0xffffffffu, rs1, 2);
        l0 = l0 * f0 + rs0; m0 = mn0;
        l1 = l1 * f1 + rs1; m1 = mn1;
#pragma unroll
        for (int nf = 0; nf < 16; nf++) {
            o[nf][0] *= f0; o[nf][1] *= f0;
            o[nf][2] *= f1; o[nf][3] *= f1;
        }

        // --- P @ V single pass ---
#pragma unroll
        for (int ks = 0; ks < 4; ks++) {
            u32 ph[4];
            ph[0] = packh2(s[2 * ks][0],     s[2 * ks][1]);
            ph[1] = packh2(s[2 * ks][2],     s[2 * ks][3]);
            ph[2] = packh2(s[2 * ks + 1][0], s[2 * ks + 1][1]);
            ph[3] = packh2(s[2 * ks + 1][2], s[2 * ks + 1][3]);
            const int kk = ks * 16;
#pragma unroll
            for (int nfp = 0; nfp < 8; nfp++) {
                u32 off = (u32)((kk + (grp & 1) * 8 + lrow) * AT_BKP
                                + nfp * 16 + (grp >> 1) * 8) * 2;
                u32 v2[4];
                ldsm_x4_t(v2, sV + off);
                mma16816(o[2 * nfp],     ph, &v2[0]);
                mma16816(o[2 * nfp + 1], ph, &v2[2]);
            }
        }
    }

    // Epilogue: normalize, fp16 store
    float i0 = 1.0f / l0, i1 = 1.0f / l1;
    const int row0 = q0 + w * 16 + g;
#pragma unroll
    for (int nf = 0; nf < 16; nf++) {
        int col = nf * 8 + c0;
        size_t a0 = ((size_t)(b * S_ + row0) * NH_ + h) * HD_ + col;
        size_t a1 = ((size_t)(b * S_ + row0 + 8) * NH_ + h) * HD_ + col;
        *(u32*)(y16 + a0) = packh2(o[nf][0] * i0, o[nf][1] * i0);
        *(u32*)(y16 + a1) = packh2(o[nf][2] * i1, o[nf][3] * i1);
    }
}

// ---------------------------------------------------------------------------
// Launch
// ---------------------------------------------------------------------------
extern "C" void kernel_launch(void* const* d_in, const int* in_sizes, int n_in,
                              void* d_out, int out_size)
{
    const float* x   = (const float*)d_in[0];
    const float* Wq  = (const float*)d_in[1];
    const float* bq  = (const float*)d_in[2];
    const float* Wkv = (const float*)d_in[3];
    const float* bkv = (const float*)d_in[4];
    const float* Wo  = (const float*)d_in[5];
    const float* bo  = (const float*)d_in[6];
    float* out = (float*)d_out;

    __half *x16, *q16, *kv16, *y16, *wqkvt, *wot;
    float *bqkv;
    float2* tab;
    cudaGetSymbolAddress((void**)&x16,   g_x16);
    cudaGetSymbolAddress((void**)&q16,   g_q16);
    cudaGetSymbolAddress((void**)&kv16,  g_kv16);
    cudaGetSymbolAddress((void**)&y16,   g_y16);
    cudaGetSymbolAddress((void**)&wqkvt, g_wqkvt);
    cudaGetSymbolAddress((void**)&wot,   g_wot);
    cudaGetSymbolAddress((void**)&bqkv,  g_bqkv);
    cudaGetSymbolAddress((void**)&tab,   g_ropetab);

    const int M = B_ * S_;
    const int n4 = (B_ * S_ * E_) / 4;

    convert_kernel<<<n4 / 256, 256>>>(x, x16, n4);
    transpose_convert_all<<<dim3(E_ / 32, E_ / 32, 3), dim3(32, 8)>>>(
        Wq, Wkv, Wo, wqkvt, wot);
    concat_bias_kernel<<<QKVN_ / 256, 256>>>(bq, bkv, bqkv);
    rope_table_kernel<<<(S_ * 64) / 256, 256>>>(tab);

    cudaFuncSetAttribute(mma_gemm_kernel, cudaFuncAttributeMaxDynamicSharedMemorySize,
                         GT_SMEM);
    cudaFuncSetAttribute(attn_mma_kernel, cudaFuncAttributeMaxDynamicSharedMemorySize,
                         ATT_SMEM);

    // fused [q | kv] = x @ [Wq | Wkv] + [bq | bkv]  (+RoPE, fp16 out)
    mma_gemm_kernel<<<dim3(QKVN_ / 128, M / 128), 128, GT_SMEM>>>(
        x16, wqkvt, bqkv, nullptr, q16, kv16, tab, M, QKVN_, E_, 1);

    // attention (tensor-core fp16, 3-stage cp.async K/V)
    attn_mma_kernel<<<dim3(S_ / 64, B_ * NH_), 128, ATT_SMEM>>>(q16, kv16, y16);

    // out = y @ Wo + bo  (fp32 out)
    mma_gemm_kernel<<<dim3(E_ / 128, M / 128), 128, GT_SMEM>>>(
        y16, wot, bo, out, nullptr, nullptr, tab, M, E_, E_, 0);
}